// round 1
// baseline (speedup 1.0000x reference)
#include <cuda_runtime.h>
#include <math.h>

#define D_MODEL 1024
#define N_HEADS 16
#define D_HEAD 64
#define D_FF 4096
#define SEQ 2048
#define BATCH 2
#define TOKENS (BATCH * SEQ)
#define QKV_N (3 * D_MODEL)

// ---------------- scratch (no allocations allowed) ----------------
__device__ float g_Wqkv[D_MODEL * QKV_N];            // [1024][3072]
__device__ float g_xn[TOKENS * D_MODEL];
__device__ float g_qkv[TOKENS * QKV_N];              // [t][q|k|v, h*64+e]
__device__ float g_attn[TOKENS * D_MODEL];
__device__ float g_hidden[TOKENS * D_MODEL];
__device__ float g_hn[TOKENS * D_MODEL];
__device__ float g_ffh[(size_t)TOKENS * D_FF];

// ---------------- weight packing: Wq/Wk/Wv -> [d][3*1024] ----------------
__global__ void pack_qkv_k(const float* __restrict__ Wq,
                           const float* __restrict__ Wk,
                           const float* __restrict__ Wv) {
    int idx = blockIdx.x * blockDim.x + threadIdx.x;
    if (idx >= D_MODEL * QKV_N) return;
    int d = idx / QKV_N;
    int n = idx % QKV_N;
    int which = n >> 10;         // 0=q,1=k,2=v
    int c = n & 1023;            // h*64+e
    int h = c >> 6, e = c & 63;
    const float* W = (which == 0) ? Wq : (which == 1) ? Wk : Wv;
    g_Wqkv[idx] = W[(h * D_MODEL + d) * D_HEAD + e];
}

// ---------------- fused LayerNorm (one block per row of 1024) ----------------
__global__ __launch_bounds__(256) void layernorm_k(const float* __restrict__ x,
                                                   const float* __restrict__ g,
                                                   const float* __restrict__ b,
                                                   float* __restrict__ out) {
    __shared__ float red[2][8];
    int row = blockIdx.x;
    int tid = threadIdx.x;
    const float4* xr = (const float4*)(x + (size_t)row * D_MODEL);
    float4 v = xr[tid];
    float s  = v.x + v.y + v.z + v.w;
    float ss = v.x * v.x + v.y * v.y + v.z * v.z + v.w * v.w;
#pragma unroll
    for (int o = 16; o > 0; o >>= 1) {
        s  += __shfl_xor_sync(0xffffffffu, s,  o);
        ss += __shfl_xor_sync(0xffffffffu, ss, o);
    }
    int w = tid >> 5, l = tid & 31;
    if (l == 0) { red[0][w] = s; red[1][w] = ss; }
    __syncthreads();
    if (tid < 32) {
        s  = (l < 8) ? red[0][l] : 0.f;
        ss = (l < 8) ? red[1][l] : 0.f;
#pragma unroll
        for (int o = 4; o > 0; o >>= 1) {
            s  += __shfl_xor_sync(0xffffffffu, s,  o);
            ss += __shfl_xor_sync(0xffffffffu, ss, o);
        }
        if (l == 0) { red[0][0] = s; red[1][0] = ss; }
    }
    __syncthreads();
    float mu  = red[0][0] * (1.0f / D_MODEL);
    float var = red[1][0] * (1.0f / D_MODEL) - mu * mu;
    float r = rsqrtf(var + 1e-5f);
    float4 gv = ((const float4*)g)[tid];
    float4 bv = ((const float4*)b)[tid];
    float4 o4;
    o4.x = (v.x - mu) * r * gv.x + bv.x;
    o4.y = (v.y - mu) * r * gv.y + bv.y;
    o4.z = (v.z - mu) * r * gv.z + bv.z;
    o4.w = (v.w - mu) * r * gv.w + bv.w;
    ((float4*)(out + (size_t)row * D_MODEL))[tid] = o4;
}

__device__ __forceinline__ float gelu_exact(float v) {
    return 0.5f * v * (1.0f + erff(v * 0.70710678118654752440f));
}

// ---------------- SGEMM: C[M,N] = A[M,K] @ B[K,N] (+epilogue) ----------------
// EPI: 0 = none, 1 = bias + residual, 2 = bias + exact GELU
// 128x128 block, BK=8, 256 threads, 8x8 micro, double-buffered smem.
template <int EPI>
__global__ __launch_bounds__(256) void sgemm_k(const float* __restrict__ A,
                                               const float* __restrict__ B,
                                               float* __restrict__ C,
                                               int M, int N, int K,
                                               const float* __restrict__ bias,
                                               const float* __restrict__ res) {
    __shared__ float As[2][8][128];
    __shared__ float Bs[2][8][128];
    const int tid = threadIdx.x;
    const int bm = blockIdx.y * 128;
    const int bn = blockIdx.x * 128;
    const int arow = tid >> 1;
    const int acol = (tid & 1) << 2;
    const int brow = tid >> 5;
    const int bcol = (tid & 31) << 2;
    const int tx = tid & 15;
    const int ty = tid >> 4;

    const float* Ap = A + (size_t)(bm + arow) * K + acol;
    const float* Bp = B + (size_t)brow * N + bn + bcol;

    float acc[8][8];
#pragma unroll
    for (int i = 0; i < 8; i++)
#pragma unroll
        for (int j = 0; j < 8; j++) acc[i][j] = 0.f;

    float4 av = *(const float4*)Ap;
    float4 bv = *(const float4*)Bp;
    As[0][acol + 0][arow] = av.x;
    As[0][acol + 1][arow] = av.y;
    As[0][acol + 2][arow] = av.z;
    As[0][acol + 3][arow] = av.w;
    *(float4*)&Bs[0][brow][bcol] = bv;
    __syncthreads();

    const int nk = K >> 3;
    for (int kt = 0; kt < nk; kt++) {
        const int cur = kt & 1;
        if (kt + 1 < nk) {
            av = *(const float4*)(Ap + (kt + 1) * 8);
            bv = *(const float4*)(Bp + (size_t)(kt + 1) * 8 * N);
        }
#pragma unroll
        for (int kk = 0; kk < 8; kk++) {
            float4 t0 = *(const float4*)&As[cur][kk][ty * 8];
            float4 t1 = *(const float4*)&As[cur][kk][ty * 8 + 4];
            float4 u0 = *(const float4*)&Bs[cur][kk][tx * 8];
            float4 u1 = *(const float4*)&Bs[cur][kk][tx * 8 + 4];
            float ar[8] = {t0.x, t0.y, t0.z, t0.w, t1.x, t1.y, t1.z, t1.w};
            float br[8] = {u0.x, u0.y, u0.z, u0.w, u1.x, u1.y, u1.z, u1.w};
#pragma unroll
            for (int i = 0; i < 8; i++)
#pragma unroll
                for (int j = 0; j < 8; j++)
                    acc[i][j] = fmaf(ar[i], br[j], acc[i][j]);
        }
        if (kt + 1 < nk) {
            const int nxt = cur ^ 1;
            As[nxt][acol + 0][arow] = av.x;
            As[nxt][acol + 1][arow] = av.y;
            As[nxt][acol + 2][arow] = av.z;
            As[nxt][acol + 3][arow] = av.w;
            *(float4*)&Bs[nxt][brow][bcol] = bv;
            __syncthreads();
        }
    }

#pragma unroll
    for (int i = 0; i < 8; i++) {
        int gr = bm + ty * 8 + i;
#pragma unroll
        for (int jj = 0; jj < 8; jj += 4) {
            int gc = bn + tx * 8 + jj;
            float4 r;
            r.x = acc[i][jj + 0];
            r.y = acc[i][jj + 1];
            r.z = acc[i][jj + 2];
            r.w = acc[i][jj + 3];
            if (EPI != 0) {
                float4 bb = *(const float4*)(bias + gc);
                r.x += bb.x; r.y += bb.y; r.z += bb.z; r.w += bb.w;
            }
            if (EPI == 1) {
                float4 rr = *(const float4*)(res + (size_t)gr * N + gc);
                r.x += rr.x; r.y += rr.y; r.z += rr.z; r.w += rr.w;
            } else if (EPI == 2) {
                r.x = gelu_exact(r.x);
                r.y = gelu_exact(r.y);
                r.z = gelu_exact(r.z);
                r.w = gelu_exact(r.w);
            }
            *(float4*)(C + (size_t)gr * N + gc) = r;
        }
    }
}

// ---------------- flash attention, fp32, 64 q-rows per block ----------------
// grid: (SEQ/64, BATCH*N_HEADS), 256 threads (16x16), dyn smem 64KB
__global__ __launch_bounds__(256) void attn_k(const float* __restrict__ qkv,
                                              float* __restrict__ out) {
    extern __shared__ float smem[];
    float* Qs = smem;          // [e][r]  64x64
    float* Ks = smem + 4096;   // [e][c]  64x64
    float* Vs = smem + 8192;   // [kk][e] 64x64
    float* Ps = smem + 12288;  // [r][c]  64x64

    const int tid = threadIdx.x;
    const int tx = tid & 15, ty = tid >> 4;
    const int bh = blockIdx.y;
    const int b = bh >> 4, h = bh & 15;
    const int q0 = blockIdx.x * 64;

    const float* base = qkv + (size_t)b * SEQ * QKV_N + h * D_HEAD;
    const float* Qg = base;
    const float* Kg = base + D_MODEL;
    const float* Vg = base + 2 * D_MODEL;

#pragma unroll
    for (int it = 0; it < 4; it++) {
        int r = ty + it * 16;
        int e = tx * 4;
        float4 v = *(const float4*)(Qg + (size_t)(q0 + r) * QKV_N + e);
        Qs[(e + 0) * 64 + r] = v.x;
        Qs[(e + 1) * 64 + r] = v.y;
        Qs[(e + 2) * 64 + r] = v.z;
        Qs[(e + 3) * 64 + r] = v.w;
    }

    float m_i[4], l_i[4], acc[4][4];
#pragma unroll
    for (int i = 0; i < 4; i++) {
        m_i[i] = -1e30f;
        l_i[i] = 0.f;
#pragma unroll
        for (int j = 0; j < 4; j++) acc[i][j] = 0.f;
    }
    const int r0 = ty * 4, c0 = tx * 4;

    for (int kt = 0; kt < SEQ / 64; kt++) {
        const int k0 = kt * 64;
        __syncthreads();  // previous tile fully consumed (also covers Q load at kt=0)
#pragma unroll
        for (int it = 0; it < 4; it++) {
            int r = ty + it * 16;
            int e = tx * 4;
            float4 kv = *(const float4*)(Kg + (size_t)(k0 + r) * QKV_N + e);
            Ks[(e + 0) * 64 + r] = kv.x;
            Ks[(e + 1) * 64 + r] = kv.y;
            Ks[(e + 2) * 64 + r] = kv.z;
            Ks[(e + 3) * 64 + r] = kv.w;
            float4 vv = *(const float4*)(Vg + (size_t)(k0 + r) * QKV_N + e);
            *(float4*)&Vs[r * 64 + e] = vv;
        }
        __syncthreads();

        // S = Q @ K^T (4x4 per thread)
        float s[4][4];
#pragma unroll
        for (int i = 0; i < 4; i++)
#pragma unroll
            for (int j = 0; j < 4; j++) s[i][j] = 0.f;
#pragma unroll
        for (int e = 0; e < 64; e++) {
            float4 a  = *(const float4*)&Qs[e * 64 + r0];
            float4 k4 = *(const float4*)&Ks[e * 64 + c0];
            float aa[4] = {a.x, a.y, a.z, a.w};
            float kk4[4] = {k4.x, k4.y, k4.z, k4.w};
#pragma unroll
            for (int i = 0; i < 4; i++)
#pragma unroll
                for (int j = 0; j < 4; j++)
                    s[i][j] = fmaf(aa[i], kk4[j], s[i][j]);
        }

        // online softmax (rows shared by 16 lanes along tx; width-16 shfl)
#pragma unroll
        for (int i = 0; i < 4; i++) {
#pragma unroll
            for (int j = 0; j < 4; j++) s[i][j] *= 0.125f;  // 1/sqrt(64)
            float mx = fmaxf(fmaxf(s[i][0], s[i][1]), fmaxf(s[i][2], s[i][3]));
#pragma unroll
            for (int o = 8; o > 0; o >>= 1)
                mx = fmaxf(mx, __shfl_xor_sync(0xffffffffu, mx, o, 16));
            float mnew = fmaxf(m_i[i], mx);
            float corr = __expf(m_i[i] - mnew);
            float p0 = __expf(s[i][0] - mnew);
            float p1 = __expf(s[i][1] - mnew);
            float p2 = __expf(s[i][2] - mnew);
            float p3 = __expf(s[i][3] - mnew);
            *(float4*)&Ps[(r0 + i) * 64 + c0] = make_float4(p0, p1, p2, p3);
            float ls = p0 + p1 + p2 + p3;
#pragma unroll
            for (int o = 8; o > 0; o >>= 1)
                ls += __shfl_xor_sync(0xffffffffu, ls, o, 16);
            m_i[i] = mnew;
            l_i[i] = l_i[i] * corr + ls;
#pragma unroll
            for (int j = 0; j < 4; j++) acc[i][j] *= corr;
        }
        __syncthreads();

        // O += P @ V
#pragma unroll
        for (int kk = 0; kk < 64; kk++) {
            float p0 = Ps[(r0 + 0) * 64 + kk];
            float p1 = Ps[(r0 + 1) * 64 + kk];
            float p2 = Ps[(r0 + 2) * 64 + kk];
            float p3 = Ps[(r0 + 3) * 64 + kk];
            float4 v4 = *(const float4*)&Vs[kk * 64 + c0];
            acc[0][0] = fmaf(p0, v4.x, acc[0][0]);
            acc[0][1] = fmaf(p0, v4.y, acc[0][1]);
            acc[0][2] = fmaf(p0, v4.z, acc[0][2]);
            acc[0][3] = fmaf(p0, v4.w, acc[0][3]);
            acc[1][0] = fmaf(p1, v4.x, acc[1][0]);
            acc[1][1] = fmaf(p1, v4.y, acc[1][1]);
            acc[1][2] = fmaf(p1, v4.z, acc[1][2]);
            acc[1][3] = fmaf(p1, v4.w, acc[1][3]);
            acc[2][0] = fmaf(p2, v4.x, acc[2][0]);
            acc[2][1] = fmaf(p2, v4.y, acc[2][1]);
            acc[2][2] = fmaf(p2, v4.z, acc[2][2]);
            acc[2][3] = fmaf(p2, v4.w, acc[2][3]);
            acc[3][0] = fmaf(p3, v4.x, acc[3][0]);
            acc[3][1] = fmaf(p3, v4.y, acc[3][1]);
            acc[3][2] = fmaf(p3, v4.z, acc[3][2]);
            acc[3][3] = fmaf(p3, v4.w, acc[3][3]);
        }
    }

    float* O = out + (size_t)(b * SEQ + q0) * D_MODEL + h * D_HEAD;
#pragma unroll
    for (int i = 0; i < 4; i++) {
        float inv = 1.0f / l_i[i];
        float4 o4 = make_float4(acc[i][0] * inv, acc[i][1] * inv,
                                acc[i][2] * inv, acc[i][3] * inv);
        *(float4*)(O + (size_t)(r0 + i) * D_MODEL + c0) = o4;
    }
}

// ---------------- launch ----------------
extern "C" void kernel_launch(void* const* d_in, const int* in_sizes, int n_in,
                              void* d_out, int out_size) {
    const float* x    = (const float*)d_in[0];
    const float* Wq   = (const float*)d_in[1];
    const float* Wk   = (const float*)d_in[2];
    const float* Wv   = (const float*)d_in[3];
    const float* Wo   = (const float*)d_in[4];
    const float* bo   = (const float*)d_in[5];
    const float* ln1g = (const float*)d_in[6];
    const float* ln1b = (const float*)d_in[7];
    const float* ln2g = (const float*)d_in[8];
    const float* ln2b = (const float*)d_in[9];
    const float* W1   = (const float*)d_in[10];
    const float* b1   = (const float*)d_in[11];
    const float* W2   = (const float*)d_in[12];
    const float* b2   = (const float*)d_in[13];
    float* out = (float*)d_out;

    float *p_Wqkv, *p_xn, *p_qkv, *p_attn, *p_hidden, *p_hn, *p_ffh;
    cudaGetSymbolAddress((void**)&p_Wqkv,   g_Wqkv);
    cudaGetSymbolAddress((void**)&p_xn,     g_xn);
    cudaGetSymbolAddress((void**)&p_qkv,    g_qkv);
    cudaGetSymbolAddress((void**)&p_attn,   g_attn);
    cudaGetSymbolAddress((void**)&p_hidden, g_hidden);
    cudaGetSymbolAddress((void**)&p_hn,     g_hn);
    cudaGetSymbolAddress((void**)&p_ffh,    g_ffh);

    cudaFuncSetAttribute(attn_k, cudaFuncAttributeMaxDynamicSharedMemorySize, 65536);

    // 1) pack Wq/Wk/Wv into one [1024 x 3072] matrix
    pack_qkv_k<<<(D_MODEL * QKV_N + 255) / 256, 256>>>(Wq, Wk, Wv);
    // 2) LN1
    layernorm_k<<<TOKENS, 256>>>(x, ln1g, ln1b, p_xn);
    // 3) fused QKV projection: [4096,1024] @ [1024,3072]
    sgemm_k<0><<<dim3(QKV_N / 128, TOKENS / 128), 256>>>(
        p_xn, p_Wqkv, p_qkv, TOKENS, QKV_N, D_MODEL, nullptr, nullptr);
    // 4) attention (flash, online softmax)
    attn_k<<<dim3(SEQ / 64, BATCH * N_HEADS), 256, 65536>>>(p_qkv, p_attn);
    // 5) output projection + bias + residual: hidden = x + attn@Wo + bo
    sgemm_k<1><<<dim3(D_MODEL / 128, TOKENS / 128), 256>>>(
        p_attn, Wo, p_hidden, TOKENS, D_MODEL, D_MODEL, bo, x);
    // 6) LN2
    layernorm_k<<<TOKENS, 256>>>(p_hidden, ln2g, ln2b, p_hn);
    // 7) FFN up + bias + exact GELU
    sgemm_k<2><<<dim3(D_FF / 128, TOKENS / 128), 256>>>(
        p_hn, W1, p_ffh, TOKENS, D_FF, D_MODEL, b1, nullptr);
    // 8) FFN down + bias + residual -> out
    sgemm_k<1><<<dim3(D_MODEL / 128, TOKENS / 128), 256>>>(
        p_ffh, W2, out, TOKENS, D_MODEL, D_FF, b2, p_hidden);
}

// round 3
// speedup vs baseline: 1.5442x; 1.5442x over previous
#include <cuda_runtime.h>
#include <cuda_bf16.h>
#include <math.h>
#include <stdint.h>

#define D_MODEL 1024
#define N_HEADS 16
#define D_HEAD 64
#define D_FF 4096
#define SEQ 2048
#define BATCH 2
#define TOKENS (BATCH * SEQ)
#define QKV_N (3 * D_MODEL)

typedef __nv_bfloat16 bf16;

// ---------------- scratch ----------------
__device__ bf16 g_WqkvT_hi[QKV_N * D_MODEL];
__device__ bf16 g_WqkvT_lo[QKV_N * D_MODEL];
__device__ bf16 g_WoT_hi[D_MODEL * D_MODEL];
__device__ bf16 g_WoT_lo[D_MODEL * D_MODEL];
__device__ bf16 g_W1T_hi[D_FF * D_MODEL];
__device__ bf16 g_W1T_lo[D_FF * D_MODEL];
__device__ bf16 g_W2T_hi[D_MODEL * D_FF];
__device__ bf16 g_W2T_lo[D_MODEL * D_FF];
__device__ bf16 g_xn_hi[TOKENS * D_MODEL];
__device__ bf16 g_xn_lo[TOKENS * D_MODEL];
__device__ float g_qkv[(size_t)TOKENS * QKV_N];
__device__ bf16 g_at_hi[TOKENS * D_MODEL];
__device__ bf16 g_at_lo[TOKENS * D_MODEL];
__device__ float g_hidden[TOKENS * D_MODEL];
__device__ bf16 g_hn_hi[TOKENS * D_MODEL];
__device__ bf16 g_hn_lo[TOKENS * D_MODEL];
__device__ bf16 g_ff_hi[(size_t)TOKENS * D_FF];
__device__ bf16 g_ff_lo[(size_t)TOKENS * D_FF];

__device__ __forceinline__ uint32_t smem_to_u32(const void* p) {
    uint32_t a;
    asm("{ .reg .u64 t; cvta.to.shared.u64 t, %1; cvt.u32.u64 %0, t; }"
        : "=r"(a) : "l"(p));
    return a;
}
__device__ __forceinline__ void cp_async16(uint32_t smem, const void* gmem) {
    asm volatile("cp.async.cg.shared.global [%0], [%1], 16;" :: "r"(smem), "l"(gmem));
}
__device__ __forceinline__ void cp_commit() { asm volatile("cp.async.commit_group;"); }
template <int N>
__device__ __forceinline__ void cp_wait() { asm volatile("cp.async.wait_group %0;" :: "n"(N)); }

__device__ __forceinline__ void ldm_x4(uint32_t& r0, uint32_t& r1, uint32_t& r2, uint32_t& r3,
                                       uint32_t addr) {
    asm volatile("ldmatrix.sync.aligned.m8n8.x4.shared.b16 {%0,%1,%2,%3}, [%4];"
                 : "=r"(r0), "=r"(r1), "=r"(r2), "=r"(r3) : "r"(addr));
}
__device__ __forceinline__ void mma_bf16(float& c0, float& c1, float& c2, float& c3,
                                         uint32_t a0, uint32_t a1, uint32_t a2, uint32_t a3,
                                         uint32_t b0, uint32_t b1) {
    asm volatile(
        "mma.sync.aligned.m16n8k16.row.col.f32.bf16.bf16.f32 "
        "{%0,%1,%2,%3}, {%4,%5,%6,%7}, {%8,%9}, {%0,%1,%2,%3};"
        : "+f"(c0), "+f"(c1), "+f"(c2), "+f"(c3)
        : "r"(a0), "r"(a1), "r"(a2), "r"(a3), "r"(b0), "r"(b1));
}

__device__ __forceinline__ void split_bf16(float x, bf16& hi, bf16& lo) {
    hi = __float2bfloat16(x);
    lo = __float2bfloat16(x - __bfloat162float(hi));
}
__device__ __forceinline__ float gelu_exact(float v) {
    return 0.5f * v * (1.0f + erff(v * 0.70710678118654752440f));
}

// ---------------- weight transpose + bf16 split ----------------
__global__ void transconv_k(const float* __restrict__ src, bf16* __restrict__ dhi,
                            bf16* __restrict__ dlo, int K, int N) {
    __shared__ float t[32][33];
    int tx = threadIdx.x, ty = threadIdx.y;
    int k0 = blockIdx.x * 32, n0 = blockIdx.y * 32;
#pragma unroll
    for (int i = 0; i < 4; i++)
        t[ty + i * 8][tx] = src[(size_t)(k0 + ty + i * 8) * N + n0 + tx];
    __syncthreads();
#pragma unroll
    for (int i = 0; i < 4; i++) {
        float v = t[tx][ty + i * 8];
        bf16 h, l; split_bf16(v, h, l);
        size_t o = (size_t)(n0 + ty + i * 8) * K + k0 + tx;
        dhi[o] = h; dlo[o] = l;
    }
}

__global__ void transconv_qkv_k(const float* __restrict__ Wq, const float* __restrict__ Wk,
                                const float* __restrict__ Wv,
                                bf16* __restrict__ dhi, bf16* __restrict__ dlo) {
    __shared__ float t[32][33];
    int tx = threadIdx.x, ty = threadIdx.y;
    int k0 = blockIdx.x * 32, n0 = blockIdx.y * 32;
    int w = n0 >> 10, h = (n0 >> 6) & 15, e0 = n0 & 63;
    const float* W = (w == 0) ? Wq : (w == 1) ? Wk : Wv;
    const float* src = W + (size_t)h * D_MODEL * D_HEAD;
#pragma unroll
    for (int i = 0; i < 4; i++)
        t[ty + i * 8][tx] = src[(size_t)(k0 + ty + i * 8) * 64 + e0 + tx];
    __syncthreads();
#pragma unroll
    for (int i = 0; i < 4; i++) {
        float v = t[tx][ty + i * 8];
        bf16 h2, l2; split_bf16(v, h2, l2);
        size_t o = (size_t)(n0 + ty + i * 8) * D_MODEL + k0 + tx;
        dhi[o] = h2; dlo[o] = l2;
    }
}

// ---------------- LayerNorm -> bf16 hi/lo ----------------
__global__ __launch_bounds__(256) void layernorm_split_k(const float* __restrict__ x,
                                                         const float* __restrict__ g,
                                                         const float* __restrict__ b,
                                                         bf16* __restrict__ ohi,
                                                         bf16* __restrict__ olo) {
    __shared__ float red[2][8];
    int row = blockIdx.x;
    int tid = threadIdx.x;
    const float4* xr = (const float4*)(x + (size_t)row * D_MODEL);
    float4 v = xr[tid];
    float s = v.x + v.y + v.z + v.w;
    float ss = v.x * v.x + v.y * v.y + v.z * v.z + v.w * v.w;
#pragma unroll
    for (int o = 16; o > 0; o >>= 1) {
        s += __shfl_xor_sync(0xffffffffu, s, o);
        ss += __shfl_xor_sync(0xffffffffu, ss, o);
    }
    int w = tid >> 5, l = tid & 31;
    if (l == 0) { red[0][w] = s; red[1][w] = ss; }
    __syncthreads();
    if (tid < 32) {
        s = (l < 8) ? red[0][l] : 0.f;
        ss = (l < 8) ? red[1][l] : 0.f;
#pragma unroll
        for (int o = 4; o > 0; o >>= 1) {
            s += __shfl_xor_sync(0xffffffffu, s, o);
            ss += __shfl_xor_sync(0xffffffffu, ss, o);
        }
        if (l == 0) { red[0][0] = s; red[1][0] = ss; }
    }
    __syncthreads();
    float mu = red[0][0] * (1.0f / D_MODEL);
    float var = red[1][0] * (1.0f / D_MODEL) - mu * mu;
    float r = rsqrtf(var + 1e-5f);
    float4 gv = ((const float4*)g)[tid];
    float4 bv = ((const float4*)b)[tid];
    float o0 = (v.x - mu) * r * gv.x + bv.x;
    float o1 = (v.y - mu) * r * gv.y + bv.y;
    float o2 = (v.z - mu) * r * gv.z + bv.z;
    float o3 = (v.w - mu) * r * gv.w + bv.w;
    size_t base = (size_t)row * D_MODEL + tid * 4;
    bf16 h0, l0, h1, l1, h2, l2, h3, l3;
    split_bf16(o0, h0, l0); split_bf16(o1, h1, l1);
    split_bf16(o2, h2, l2); split_bf16(o3, h3, l3);
    ohi[base + 0] = h0; ohi[base + 1] = h1; ohi[base + 2] = h2; ohi[base + 3] = h3;
    olo[base + 0] = l0; olo[base + 1] = l1; olo[base + 2] = l2; olo[base + 3] = l3;
}

// ---------------- HMMA GEMM: C[M,N] = A[M,K] @ BT[N,K]^T, bf16 3-pass split ----
// 128x128x32 tiles, 256 thr, warp grid 4(M)x2(N), warp tile 32x64, cp.async 3 stages.
// Stage layout (32KB): Ahi(8K) Alo(8K) Bhi(8K) Blo(8K); row = 64B, seg swizzle ^((r>>1)&3)
#define GSTAGES 3
#define STAGE_BYTES 32768

template <int EPI>
__global__ __launch_bounds__(256, 1) void gemm_mma(
    const bf16* __restrict__ Ahi, const bf16* __restrict__ Alo,
    const bf16* __restrict__ Bhi, const bf16* __restrict__ Blo,
    int K, int N,
    float* __restrict__ C, bf16* __restrict__ Chi, bf16* __restrict__ Clo,
    const float* __restrict__ bias, const float* __restrict__ res) {
    extern __shared__ char smem[];
    const uint32_t sb = smem_to_u32(smem);
    const int tid = threadIdx.x;
    const int lane = tid & 31;
    const int warp = tid >> 5;
    const int warpM = warp & 3, warpN = warp >> 2;
    const int bn = blockIdx.x * 128, bm = blockIdx.y * 128;

    const size_t rstrideB = (size_t)K * 2;  // bytes per row (K bf16)
    const char* gA[2] = {(const char*)Ahi + (size_t)bm * K * 2,
                         (const char*)Alo + (size_t)bm * K * 2};
    const char* gB[2] = {(const char*)Bhi + (size_t)bn * K * 2,
                         (const char*)Blo + (size_t)bn * K * 2};

    // loader indices: row r = tid>>1, segs (tid&1)*2 + {0,1}
    const int ldRow = tid >> 1;
    const int ldSeg0 = (tid & 1) * 2;
    const uint32_t ldSw = (ldRow >> 1) & 3;
    const uint32_t ldSmemRow = (uint32_t)ldRow * 64;

    const int NK = K >> 5;  // chunks of 32 elems (64 bytes)

    auto issue_chunk = [&](int c) {
        const uint32_t stg = sb + (uint32_t)(c % GSTAGES) * STAGE_BYTES;
        const size_t goff = (size_t)c * 64;  // byte offset along K
#pragma unroll
        for (int t4 = 0; t4 < 4; t4++) {
            const char* src = ((t4 < 2) ? gA[t4] : gB[t4 - 2]) + goff + (size_t)ldRow * rstrideB;
            uint32_t dst = stg + (uint32_t)t4 * 8192 + ldSmemRow;
#pragma unroll
            for (int j = 0; j < 2; j++) {
                uint32_t seg = ldSeg0 + j;
                cp_async16(dst + ((seg ^ ldSw) << 4), src + seg * 16);
            }
        }
    };

    // ldmatrix per-lane geometry
    const int aRow = warpM * 32 + (lane & 7) + ((lane >> 3) & 1) * 8;
    const int aKh = lane >> 4;
    const uint32_t aSw = (aRow >> 1) & 3;
    const uint32_t aRowB = (uint32_t)aRow * 64;
    const int bRowBase = warpN * 64 + (lane & 7) + ((lane >> 3) & 1) * 8;
    const int bKh = lane >> 4;
    const uint32_t bSw = (bRowBase >> 1) & 3;
    const uint32_t bRowB = (uint32_t)bRowBase * 64;

    float acc[2][8][4];
#pragma unroll
    for (int i = 0; i < 2; i++)
#pragma unroll
        for (int j = 0; j < 8; j++)
#pragma unroll
            for (int q = 0; q < 4; q++) acc[i][j][q] = 0.f;

    // prologue: stages 0..GSTAGES-2
#pragma unroll
    for (int s = 0; s < GSTAGES - 1; s++) { issue_chunk(s); cp_commit(); }

    for (int c = 0; c < NK; c++) {
        cp_wait<GSTAGES - 2>();
        __syncthreads();
        const uint32_t stg = sb + (uint32_t)(c % GSTAGES) * STAGE_BYTES;
#pragma unroll
        for (int k16 = 0; k16 < 2; k16++) {
            const uint32_t aSeg = ((uint32_t)(k16 * 2 + aKh) ^ aSw) << 4;
            const uint32_t bSeg = ((uint32_t)(k16 * 2 + bKh) ^ bSw) << 4;
            uint32_t ah[2][4], al[2][4], bh[4][4], bl[4][4];
#pragma unroll
            for (int i = 0; i < 2; i++) {
                uint32_t base = stg + aRowB + (uint32_t)i * 16 * 64 + aSeg;
                ldm_x4(ah[i][0], ah[i][1], ah[i][2], ah[i][3], base);
                ldm_x4(al[i][0], al[i][1], al[i][2], al[i][3], base + 8192);
            }
#pragma unroll
            for (int t = 0; t < 4; t++) {
                uint32_t base = stg + 16384 + bRowB + (uint32_t)t * 16 * 64 + bSeg;
                ldm_x4(bh[t][0], bh[t][1], bh[t][2], bh[t][3], base);
                ldm_x4(bl[t][0], bl[t][1], bl[t][2], bl[t][3], base + 8192);
            }
#pragma unroll
            for (int i = 0; i < 2; i++)
#pragma unroll
                for (int t = 0; t < 4; t++) {
                    // n8 tile 2t  : {b[t][0], b[t][2]}; n8 tile 2t+1: {b[t][1], b[t][3]}
                    float* c0 = acc[i][2 * t];
                    float* c1 = acc[i][2 * t + 1];
                    mma_bf16(c0[0], c0[1], c0[2], c0[3],
                             ah[i][0], ah[i][1], ah[i][2], ah[i][3], bh[t][0], bh[t][2]);
                    mma_bf16(c1[0], c1[1], c1[2], c1[3],
                             ah[i][0], ah[i][1], ah[i][2], ah[i][3], bh[t][1], bh[t][3]);
                    mma_bf16(c0[0], c0[1], c0[2], c0[3],
                             al[i][0], al[i][1], al[i][2], al[i][3], bh[t][0], bh[t][2]);
                    mma_bf16(c1[0], c1[1], c1[2], c1[3],
                             al[i][0], al[i][1], al[i][2], al[i][3], bh[t][1], bh[t][3]);
                    mma_bf16(c0[0], c0[1], c0[2], c0[3],
                             ah[i][0], ah[i][1], ah[i][2], ah[i][3], bl[t][0], bl[t][2]);
                    mma_bf16(c1[0], c1[1], c1[2], c1[3],
                             ah[i][0], ah[i][1], ah[i][2], ah[i][3], bl[t][1], bl[t][3]);
                }
        }
        __syncthreads();
        if (c + GSTAGES - 1 < NK) issue_chunk(c + GSTAGES - 1);
        cp_commit();
    }

    // epilogue
    const int gRow = lane >> 2;
    const int gCol = (lane & 3) * 2;
#pragma unroll
    for (int i = 0; i < 2; i++) {
#pragma unroll
        for (int j = 0; j < 8; j++) {
            int row = bm + warpM * 32 + i * 16 + gRow;
            int col = bn + warpN * 64 + j * 8 + gCol;
#pragma unroll
            for (int half = 0; half < 2; half++) {
                int r = row + half * 8;
                float v0 = acc[i][j][half * 2 + 0];
                float v1 = acc[i][j][half * 2 + 1];
                if (EPI != 0) {
                    float2 bb = *(const float2*)(bias + col);
                    v0 += bb.x; v1 += bb.y;
                }
                if (EPI == 1) {
                    float2 rv = *(const float2*)(res + (size_t)r * N + col);
                    v0 += rv.x; v1 += rv.y;
                }
                if (EPI == 2) {
                    v0 = gelu_exact(v0); v1 = gelu_exact(v1);
                    size_t o = (size_t)r * N + col;
                    bf16 h0, l0, h1, l1;
                    split_bf16(v0, h0, l0); split_bf16(v1, h1, l1);
                    Chi[o] = h0; Chi[o + 1] = h1;
                    Clo[o] = l0; Clo[o + 1] = l1;
                } else {
                    *(float2*)(C + (size_t)r * N + col) = make_float2(v0, v1);
                }
            }
        }
    }
}

// ---------------- flash attention, fp32 ----------------
__global__ __launch_bounds__(256) void attn_k(const float* __restrict__ qkv,
                                              bf16* __restrict__ ohi,
                                              bf16* __restrict__ olo) {
    extern __shared__ float smemf[];
    float* Qs = smemf;
    float* Ks = smemf + 4096;
    float* Vs = smemf + 8192;
    float* Ps = smemf + 12288;

    const int tid = threadIdx.x;
    const int tx = tid & 15, ty = tid >> 4;
    const int bh = blockIdx.y;
    const int b = bh >> 4, h = bh & 15;
    const int q0 = blockIdx.x * 64;

    const float* base = qkv + (size_t)b * SEQ * QKV_N + h * D_HEAD;
    const float* Qg = base;
    const float* Kg = base + D_MODEL;
    const float* Vg = base + 2 * D_MODEL;

#pragma unroll
    for (int it = 0; it < 4; it++) {
        int r = ty + it * 16;
        int e = tx * 4;
        float4 v = *(const float4*)(Qg + (size_t)(q0 + r) * QKV_N + e);
        Qs[(e + 0) * 64 + r] = v.x;
        Qs[(e + 1) * 64 + r] = v.y;
        Qs[(e + 2) * 64 + r] = v.z;
        Qs[(e + 3) * 64 + r] = v.w;
    }

    float m_i[4], l_i[4], acc[4][4];
#pragma unroll
    for (int i = 0; i < 4; i++) {
        m_i[i] = -1e30f; l_i[i] = 0.f;
#pragma unroll
        for (int j = 0; j < 4; j++) acc[i][j] = 0.f;
    }
    const int r0 = ty * 4, c0 = tx * 4;

    for (int kt = 0; kt < SEQ / 64; kt++) {
        const int k0 = kt * 64;
        __syncthreads();
#pragma unroll
        for (int it = 0; it < 4; it++) {
            int r = ty + it * 16;
            int e = tx * 4;
            float4 kv = *(const float4*)(Kg + (size_t)(k0 + r) * QKV_N + e);
            Ks[(e + 0) * 64 + r] = kv.x;
            Ks[(e + 1) * 64 + r] = kv.y;
            Ks[(e + 2) * 64 + r] = kv.z;
            Ks[(e + 3) * 64 + r] = kv.w;
            float4 vv = *(const float4*)(Vg + (size_t)(k0 + r) * QKV_N + e);
            *(float4*)&Vs[r * 64 + e] = vv;
        }
        __syncthreads();

        float s[4][4];
#pragma unroll
        for (int i = 0; i < 4; i++)
#pragma unroll
            for (int j = 0; j < 4; j++) s[i][j] = 0.f;
#pragma unroll
        for (int e = 0; e < 64; e++) {
            float4 a = *(const float4*)&Qs[e * 64 + r0];
            float4 k4 = *(const float4*)&Ks[e * 64 + c0];
            float aa[4] = {a.x, a.y, a.z, a.w};
            float kk4[4] = {k4.x, k4.y, k4.z, k4.w};
#pragma unroll
            for (int i = 0; i < 4; i++)
#pragma unroll
                for (int j = 0; j < 4; j++)
                    s[i][j] = fmaf(aa[i], kk4[j], s[i][j]);
        }

#pragma unroll
        for (int i = 0; i < 4; i++) {
#pragma unroll
            for (int j = 0; j < 4; j++) s[i][j] *= 0.125f;
            float mx = fmaxf(fmaxf(s[i][0], s[i][1]), fmaxf(s[i][2], s[i][3]));
#pragma unroll
            for (int o = 8; o > 0; o >>= 1)
                mx = fmaxf(mx, __shfl_xor_sync(0xffffffffu, mx, o, 16));
            float mnew = fmaxf(m_i[i], mx);
            float corr = __expf(m_i[i] - mnew);
            float p0 = __expf(s[i][0] - mnew);
            float p1 = __expf(s[i][1] - mnew);
            float p2 = __expf(s[i][2] - mnew);
            float p3 = __expf(s[i][3] - mnew);
            *(float4*)&Ps[(r0 + i) * 64 + c0] = make_float4(p0, p1, p2, p3);
            float ls = p0 + p1 + p2 + p3;
#pragma unroll
            for (int o = 8; o > 0; o >>= 1)
                ls += __shfl_xor_sync(0xffffffffu, ls, o, 16);
            m_i[i] = mnew;
            l_i[i] = l_i[i] * corr + ls;
#pragma unroll
            for (int j = 0; j < 4; j++) acc[i][j] *= corr;
        }
        __syncthreads();

#pragma unroll
        for (int kk = 0; kk < 64; kk++) {
            float p0 = Ps[(r0 + 0) * 64 + kk];
            float p1 = Ps[(r0 + 1) * 64 + kk];
            float p2 = Ps[(r0 + 2) * 64 + kk];
            float p3 = Ps[(r0 + 3) * 64 + kk];
            float4 v4 = *(const float4*)&Vs[kk * 64 + c0];
            acc[0][0] = fmaf(p0, v4.x, acc[0][0]); acc[0][1] = fmaf(p0, v4.y, acc[0][1]);
            acc[0][2] = fmaf(p0, v4.z, acc[0][2]); acc[0][3] = fmaf(p0, v4.w, acc[0][3]);
            acc[1][0] = fmaf(p1, v4.x, acc[1][0]); acc[1][1] = fmaf(p1, v4.y, acc[1][1]);
            acc[1][2] = fmaf(p1, v4.z, acc[1][2]); acc[1][3] = fmaf(p1, v4.w, acc[1][3]);
            acc[2][0] = fmaf(p2, v4.x, acc[2][0]); acc[2][1] = fmaf(p2, v4.y, acc[2][1]);
            acc[2][2] = fmaf(p2, v4.z, acc[2][2]); acc[2][3] = fmaf(p2, v4.w, acc[2][3]);
            acc[3][0] = fmaf(p3, v4.x, acc[3][0]); acc[3][1] = fmaf(p3, v4.y, acc[3][1]);
            acc[3][2] = fmaf(p3, v4.z, acc[3][2]); acc[3][3] = fmaf(p3, v4.w, acc[3][3]);
        }
    }

    size_t obase = (size_t)(b * SEQ + q0) * D_MODEL + h * D_HEAD;
#pragma unroll
    for (int i = 0; i < 4; i++) {
        float inv = 1.0f / l_i[i];
        size_t o = obase + (size_t)(r0 + i) * D_MODEL + c0;
#pragma unroll
        for (int j = 0; j < 4; j++) {
            bf16 hh, ll;
            split_bf16(acc[i][j] * inv, hh, ll);
            ohi[o + j] = hh; olo[o + j] = ll;
        }
    }
}

// ---------------- launch ----------------
extern "C" void kernel_launch(void* const* d_in, const int* in_sizes, int n_in,
                              void* d_out, int out_size) {
    const float* x    = (const float*)d_in[0];
    const float* Wq   = (const float*)d_in[1];
    const float* Wk   = (const float*)d_in[2];
    const float* Wv   = (const float*)d_in[3];
    const float* Wo   = (const float*)d_in[4];
    const float* bo   = (const float*)d_in[5];
    const float* ln1g = (const float*)d_in[6];
    const float* ln1b = (const float*)d_in[7];
    const float* ln2g = (const float*)d_in[8];
    const float* ln2b = (const float*)d_in[9];
    const float* W1   = (const float*)d_in[10];
    const float* b1   = (const float*)d_in[11];
    const float* W2   = (const float*)d_in[12];
    const float* b2   = (const float*)d_in[13];
    float* out = (float*)d_out;

    bf16 *pWqkvH, *pWqkvL, *pWoH, *pWoL, *pW1H, *pW1L, *pW2H, *pW2L;
    bf16 *pXnH, *pXnL, *pAtH, *pAtL, *pHnH, *pHnL, *pFfH, *pFfL;
    float *pQkv, *pHid;
    cudaGetSymbolAddress((void**)&pWqkvH, g_WqkvT_hi);
    cudaGetSymbolAddress((void**)&pWqkvL, g_WqkvT_lo);
    cudaGetSymbolAddress((void**)&pWoH, g_WoT_hi);
    cudaGetSymbolAddress((void**)&pWoL, g_WoT_lo);
    cudaGetSymbolAddress((void**)&pW1H, g_W1T_hi);
    cudaGetSymbolAddress((void**)&pW1L, g_W1T_lo);
    cudaGetSymbolAddress((void**)&pW2H, g_W2T_hi);
    cudaGetSymbolAddress((void**)&pW2L, g_W2T_lo);
    cudaGetSymbolAddress((void**)&pXnH, g_xn_hi);
    cudaGetSymbolAddress((void**)&pXnL, g_xn_lo);
    cudaGetSymbolAddress((void**)&pAtH, g_at_hi);
    cudaGetSymbolAddress((void**)&pAtL, g_at_lo);
    cudaGetSymbolAddress((void**)&pHnH, g_hn_hi);
    cudaGetSymbolAddress((void**)&pHnL, g_hn_lo);
    cudaGetSymbolAddress((void**)&pFfH, g_ff_hi);
    cudaGetSymbolAddress((void**)&pFfL, g_ff_lo);
    cudaGetSymbolAddress((void**)&pQkv, g_qkv);
    cudaGetSymbolAddress((void**)&pHid, g_hidden);

    const int GEMM_SMEM = GSTAGES * STAGE_BYTES;  // 98304
    cudaFuncSetAttribute(gemm_mma<0>, cudaFuncAttributeMaxDynamicSharedMemorySize, GEMM_SMEM);
    cudaFuncSetAttribute(gemm_mma<1>, cudaFuncAttributeMaxDynamicSharedMemorySize, GEMM_SMEM);
    cudaFuncSetAttribute(gemm_mma<2>, cudaFuncAttributeMaxDynamicSharedMemorySize, GEMM_SMEM);
    cudaFuncSetAttribute(attn_k, cudaFuncAttributeMaxDynamicSharedMemorySize, 65536);

    dim3 t328(32, 8);
    transconv_qkv_k<<<dim3(D_MODEL / 32, QKV_N / 32), t328>>>(Wq, Wk, Wv, pWqkvH, pWqkvL);
    transconv_k<<<dim3(D_MODEL / 32, D_MODEL / 32), t328>>>(Wo, pWoH, pWoL, D_MODEL, D_MODEL);
    transconv_k<<<dim3(D_MODEL / 32, D_FF / 32), t328>>>(W1, pW1H, pW1L, D_MODEL, D_FF);
    transconv_k<<<dim3(D_FF / 32, D_MODEL / 32), t328>>>(W2, pW2H, pW2L, D_FF, D_MODEL);

    layernorm_split_k<<<TOKENS, 256>>>(x, ln1g, ln1b, pXnH, pXnL);
    gemm_mma<0><<<dim3(QKV_N / 128, TOKENS / 128), 256, GEMM_SMEM>>>(
        pXnH, pXnL, pWqkvH, pWqkvL, D_MODEL, QKV_N, pQkv, nullptr, nullptr, nullptr, nullptr);
    attn_k<<<dim3(SEQ / 64, BATCH * N_HEADS), 256, 65536>>>(pQkv, pAtH, pAtL);
    gemm_mma<1><<<dim3(D_MODEL / 128, TOKENS / 128), 256, GEMM_SMEM>>>(
        pAtH, pAtL, pWoH, pWoL, D_MODEL, D_MODEL, pHid, nullptr, nullptr, bo, x);
    layernorm_split_k<<<TOKENS, 256>>>(pHid, ln2g, ln2b, pHnH, pHnL);
    gemm_mma<2><<<dim3(D_FF / 128, TOKENS / 128), 256, GEMM_SMEM>>>(
        pHnH, pHnL, pW1H, pW1L, D_MODEL, D_FF, nullptr, pFfH, pFfL, b1, nullptr);
    gemm_mma<1><<<dim3(D_MODEL / 128, TOKENS / 128), 256, GEMM_SMEM>>>(
        pFfH, pFfL, pW2H, pW2L, D_FF, D_MODEL, out, nullptr, nullptr, b2, pHid);
}

// round 4
// speedup vs baseline: 2.2419x; 1.4518x over previous
#include <cuda_runtime.h>
#include <cuda_bf16.h>
#include <math.h>
#include <stdint.h>

#define D_MODEL 1024
#define N_HEADS 16
#define D_HEAD 64
#define D_FF 4096
#define SEQ 2048
#define BATCH 2
#define TOKENS (BATCH * SEQ)
#define QKV_N (3 * D_MODEL)
#define BH (BATCH * N_HEADS)

typedef __nv_bfloat16 bf16;

// ---------------- scratch ----------------
__device__ bf16 g_WqkvT_hi[QKV_N * D_MODEL];
__device__ bf16 g_WqkvT_lo[QKV_N * D_MODEL];
__device__ bf16 g_WoT_hi[D_MODEL * D_MODEL];
__device__ bf16 g_WoT_lo[D_MODEL * D_MODEL];
__device__ bf16 g_W1T_hi[D_FF * D_MODEL];
__device__ bf16 g_W1T_lo[D_FF * D_MODEL];
__device__ bf16 g_W2T_hi[D_MODEL * D_FF];
__device__ bf16 g_W2T_lo[D_MODEL * D_FF];
__device__ bf16 g_xn_hi[TOKENS * D_MODEL];
__device__ bf16 g_xn_lo[TOKENS * D_MODEL];
// head-major QKV splits: [bh][s][64]
__device__ bf16 g_q_hi[BH * SEQ * D_HEAD];
__device__ bf16 g_q_lo[BH * SEQ * D_HEAD];
__device__ bf16 g_k_hi[BH * SEQ * D_HEAD];
__device__ bf16 g_k_lo[BH * SEQ * D_HEAD];
__device__ bf16 g_v_hi[BH * SEQ * D_HEAD];
__device__ bf16 g_v_lo[BH * SEQ * D_HEAD];
__device__ bf16 g_at_hi[TOKENS * D_MODEL];
__device__ bf16 g_at_lo[TOKENS * D_MODEL];
__device__ float g_hidden[TOKENS * D_MODEL];
__device__ bf16 g_hn_hi[TOKENS * D_MODEL];
__device__ bf16 g_hn_lo[TOKENS * D_MODEL];
__device__ bf16 g_ff_hi[(size_t)TOKENS * D_FF];
__device__ bf16 g_ff_lo[(size_t)TOKENS * D_FF];

__device__ __forceinline__ uint32_t smem_to_u32(const void* p) {
    uint32_t a;
    asm("{ .reg .u64 t; cvta.to.shared.u64 t, %1; cvt.u32.u64 %0, t; }"
        : "=r"(a) : "l"(p));
    return a;
}
__device__ __forceinline__ void cp_async16(uint32_t smem, const void* gmem) {
    asm volatile("cp.async.cg.shared.global [%0], [%1], 16;" :: "r"(smem), "l"(gmem));
}
__device__ __forceinline__ void cp_commit() { asm volatile("cp.async.commit_group;"); }
template <int N>
__device__ __forceinline__ void cp_wait() { asm volatile("cp.async.wait_group %0;" :: "n"(N)); }

__device__ __forceinline__ void ldm_x4(uint32_t& r0, uint32_t& r1, uint32_t& r2, uint32_t& r3,
                                       uint32_t addr) {
    asm volatile("ldmatrix.sync.aligned.m8n8.x4.shared.b16 {%0,%1,%2,%3}, [%4];"
                 : "=r"(r0), "=r"(r1), "=r"(r2), "=r"(r3) : "r"(addr));
}
__device__ __forceinline__ void ldm_x4_t(uint32_t& r0, uint32_t& r1, uint32_t& r2, uint32_t& r3,
                                         uint32_t addr) {
    asm volatile("ldmatrix.sync.aligned.m8n8.x4.trans.shared.b16 {%0,%1,%2,%3}, [%4];"
                 : "=r"(r0), "=r"(r1), "=r"(r2), "=r"(r3) : "r"(addr));
}
__device__ __forceinline__ void mma_bf16(float& c0, float& c1, float& c2, float& c3,
                                         uint32_t a0, uint32_t a1, uint32_t a2, uint32_t a3,
                                         uint32_t b0, uint32_t b1) {
    asm volatile(
        "mma.sync.aligned.m16n8k16.row.col.f32.bf16.bf16.f32 "
        "{%0,%1,%2,%3}, {%4,%5,%6,%7}, {%8,%9}, {%0,%1,%2,%3};"
        : "+f"(c0), "+f"(c1), "+f"(c2), "+f"(c3)
        : "r"(a0), "r"(a1), "r"(a2), "r"(a3), "r"(b0), "r"(b1));
}

__device__ __forceinline__ void split_bf16(float x, bf16& hi, bf16& lo) {
    hi = __float2bfloat16(x);
    lo = __float2bfloat16(x - __bfloat162float(hi));
}
__device__ __forceinline__ float gelu_exact(float v) {
    return 0.5f * v * (1.0f + erff(v * 0.70710678118654752440f));
}
// FMA-pipe exp2 (no MUFU). y expected <= 0.
__device__ __forceinline__ float exp2_poly(float y) {
    float t = fmaxf(y, -126.0f);
    float fn = t + 12582912.0f;  // round-to-nearest-int magic
    int n = __float_as_int(fn) - 0x4B400000;
    float f = t - (fn - 12582912.0f);  // f in [-0.5, 0.5]
    float p = fmaf(0.0013333558f, f, 0.0096181291f);
    p = fmaf(p, f, 0.0555041087f);
    p = fmaf(p, f, 0.2402265070f);
    p = fmaf(p, f, 0.6931471806f);
    p = fmaf(p, f, 1.0f);
    return __int_as_float(__float_as_int(p) + (n << 23));
}
__device__ __forceinline__ uint32_t pack_bf16(float a, float b) {
    __nv_bfloat162 p = __floats2bfloat162_rn(a, b);
    return *(uint32_t*)&p;
}

#define QSCALE 0.18033688011f  // 0.125 * log2(e)

// ---------------- weight transpose + bf16 split ----------------
__global__ void transconv_k(const float* __restrict__ src, bf16* __restrict__ dhi,
                            bf16* __restrict__ dlo, int K, int N) {
    __shared__ float t[32][33];
    int tx = threadIdx.x, ty = threadIdx.y;
    int k0 = blockIdx.x * 32, n0 = blockIdx.y * 32;
#pragma unroll
    for (int i = 0; i < 4; i++)
        t[ty + i * 8][tx] = src[(size_t)(k0 + ty + i * 8) * N + n0 + tx];
    __syncthreads();
#pragma unroll
    for (int i = 0; i < 4; i++) {
        float v = t[tx][ty + i * 8];
        bf16 h, l; split_bf16(v, h, l);
        size_t o = (size_t)(n0 + ty + i * 8) * K + k0 + tx;
        dhi[o] = h; dlo[o] = l;
    }
}

__global__ void transconv_qkv_k(const float* __restrict__ Wq, const float* __restrict__ Wk,
                                const float* __restrict__ Wv,
                                bf16* __restrict__ dhi, bf16* __restrict__ dlo) {
    __shared__ float t[32][33];
    int tx = threadIdx.x, ty = threadIdx.y;
    int k0 = blockIdx.x * 32, n0 = blockIdx.y * 32;
    int w = n0 >> 10, h = (n0 >> 6) & 15, e0 = n0 & 63;
    const float* W = (w == 0) ? Wq : (w == 1) ? Wk : Wv;
    const float* src = W + (size_t)h * D_MODEL * D_HEAD;
#pragma unroll
    for (int i = 0; i < 4; i++)
        t[ty + i * 8][tx] = src[(size_t)(k0 + ty + i * 8) * 64 + e0 + tx];
    __syncthreads();
#pragma unroll
    for (int i = 0; i < 4; i++) {
        float v = t[tx][ty + i * 8];
        bf16 h2, l2; split_bf16(v, h2, l2);
        size_t o = (size_t)(n0 + ty + i * 8) * D_MODEL + k0 + tx;
        dhi[o] = h2; dlo[o] = l2;
    }
}

// ---------------- LayerNorm -> bf16 hi/lo ----------------
__global__ __launch_bounds__(256) void layernorm_split_k(const float* __restrict__ x,
                                                         const float* __restrict__ g,
                                                         const float* __restrict__ b,
                                                         bf16* __restrict__ ohi,
                                                         bf16* __restrict__ olo) {
    __shared__ float red[2][8];
    int row = blockIdx.x;
    int tid = threadIdx.x;
    const float4* xr = (const float4*)(x + (size_t)row * D_MODEL);
    float4 v = xr[tid];
    float s = v.x + v.y + v.z + v.w;
    float ss = v.x * v.x + v.y * v.y + v.z * v.z + v.w * v.w;
#pragma unroll
    for (int o = 16; o > 0; o >>= 1) {
        s += __shfl_xor_sync(0xffffffffu, s, o);
        ss += __shfl_xor_sync(0xffffffffu, ss, o);
    }
    int w = tid >> 5, l = tid & 31;
    if (l == 0) { red[0][w] = s; red[1][w] = ss; }
    __syncthreads();
    if (tid < 32) {
        s = (l < 8) ? red[0][l] : 0.f;
        ss = (l < 8) ? red[1][l] : 0.f;
#pragma unroll
        for (int o = 4; o > 0; o >>= 1) {
            s += __shfl_xor_sync(0xffffffffu, s, o);
            ss += __shfl_xor_sync(0xffffffffu, ss, o);
        }
        if (l == 0) { red[0][0] = s; red[1][0] = ss; }
    }
    __syncthreads();
    float mu = red[0][0] * (1.0f / D_MODEL);
    float var = red[1][0] * (1.0f / D_MODEL) - mu * mu;
    float r = rsqrtf(var + 1e-5f);
    float4 gv = ((const float4*)g)[tid];
    float4 bv = ((const float4*)b)[tid];
    float o0 = (v.x - mu) * r * gv.x + bv.x;
    float o1 = (v.y - mu) * r * gv.y + bv.y;
    float o2 = (v.z - mu) * r * gv.z + bv.z;
    float o3 = (v.w - mu) * r * gv.w + bv.w;
    size_t base = (size_t)row * D_MODEL + tid * 4;
    bf16 h0, l0, h1, l1, h2, l2, h3, l3;
    split_bf16(o0, h0, l0); split_bf16(o1, h1, l1);
    split_bf16(o2, h2, l2); split_bf16(o3, h3, l3);
    ohi[base + 0] = h0; ohi[base + 1] = h1; ohi[base + 2] = h2; ohi[base + 3] = h3;
    olo[base + 0] = l0; olo[base + 1] = l1; olo[base + 2] = l2; olo[base + 3] = l3;
}

// ---------------- HMMA GEMM ----------------
// EPI: 0 fp32 C; 1 bias+residual fp32 C; 2 bias+GELU split bf16; 3 QKV head-major split
#define GSTAGES 3
#define STAGE_BYTES 32768

template <int EPI>
__global__ __launch_bounds__(256, 1) void gemm_mma(
    const bf16* __restrict__ Ahi, const bf16* __restrict__ Alo,
    const bf16* __restrict__ Bhi, const bf16* __restrict__ Blo,
    int K, int N,
    float* __restrict__ C, bf16* __restrict__ Chi, bf16* __restrict__ Clo,
    const float* __restrict__ bias, const float* __restrict__ res,
    bf16* __restrict__ Qh, bf16* __restrict__ Ql,
    bf16* __restrict__ Kh2, bf16* __restrict__ Kl2,
    bf16* __restrict__ Vh, bf16* __restrict__ Vl) {
    extern __shared__ char smem[];
    const uint32_t sb = smem_to_u32(smem);
    const int tid = threadIdx.x;
    const int lane = tid & 31;
    const int warp = tid >> 5;
    const int warpM = warp & 3, warpN = warp >> 2;
    const int bn = blockIdx.x * 128, bm = blockIdx.y * 128;

    const size_t rstrideB = (size_t)K * 2;
    const char* gA[2] = {(const char*)Ahi + (size_t)bm * K * 2,
                         (const char*)Alo + (size_t)bm * K * 2};
    const char* gB[2] = {(const char*)Bhi + (size_t)bn * K * 2,
                         (const char*)Blo + (size_t)bn * K * 2};

    const int ldRow = tid >> 1;
    const int ldSeg0 = (tid & 1) * 2;
    const uint32_t ldSw = (ldRow >> 1) & 3;
    const uint32_t ldSmemRow = (uint32_t)ldRow * 64;

    const int NK = K >> 5;

    auto issue_chunk = [&](int c) {
        const uint32_t stg = sb + (uint32_t)(c % GSTAGES) * STAGE_BYTES;
        const size_t goff = (size_t)c * 64;
#pragma unroll
        for (int t4 = 0; t4 < 4; t4++) {
            const char* src = ((t4 < 2) ? gA[t4] : gB[t4 - 2]) + goff + (size_t)ldRow * rstrideB;
            uint32_t dst = stg + (uint32_t)t4 * 8192 + ldSmemRow;
#pragma unroll
            for (int j = 0; j < 2; j++) {
                uint32_t seg = ldSeg0 + j;
                cp_async16(dst + ((seg ^ ldSw) << 4), src + seg * 16);
            }
        }
    };

    const int aRow = warpM * 32 + (lane & 15);
    const int aKh = lane >> 4;
    const uint32_t aSw = (aRow >> 1) & 3;
    const uint32_t aRowB = (uint32_t)aRow * 64;
    const int bRowBase = warpN * 64 + (lane & 15);
    const int bKh = lane >> 4;
    const uint32_t bSw = (bRowBase >> 1) & 3;
    const uint32_t bRowB = (uint32_t)bRowBase * 64;

    float acc[2][8][4];
#pragma unroll
    for (int i = 0; i < 2; i++)
#pragma unroll
        for (int j = 0; j < 8; j++)
#pragma unroll
            for (int q = 0; q < 4; q++) acc[i][j][q] = 0.f;

#pragma unroll
    for (int s = 0; s < GSTAGES - 1; s++) { issue_chunk(s); cp_commit(); }

    for (int c = 0; c < NK; c++) {
        cp_wait<GSTAGES - 2>();
        __syncthreads();
        const uint32_t stg = sb + (uint32_t)(c % GSTAGES) * STAGE_BYTES;
#pragma unroll
        for (int k16 = 0; k16 < 2; k16++) {
            const uint32_t aSeg = ((uint32_t)(k16 * 2 + aKh) ^ aSw) << 4;
            const uint32_t bSeg = ((uint32_t)(k16 * 2 + bKh) ^ bSw) << 4;
            uint32_t ah[2][4], al[2][4], bh[4][4], bl[4][4];
#pragma unroll
            for (int i = 0; i < 2; i++) {
                uint32_t base = stg + aRowB + (uint32_t)i * 16 * 64 + aSeg;
                ldm_x4(ah[i][0], ah[i][1], ah[i][2], ah[i][3], base);
                ldm_x4(al[i][0], al[i][1], al[i][2], al[i][3], base + 8192);
            }
#pragma unroll
            for (int t = 0; t < 4; t++) {
                uint32_t base = stg + 16384 + bRowB + (uint32_t)t * 16 * 64 + bSeg;
                ldm_x4(bh[t][0], bh[t][1], bh[t][2], bh[t][3], base);
                ldm_x4(bl[t][0], bl[t][1], bl[t][2], bl[t][3], base + 8192);
            }
#pragma unroll
            for (int i = 0; i < 2; i++)
#pragma unroll
                for (int t = 0; t < 4; t++) {
                    float* c0 = acc[i][2 * t];
                    float* c1 = acc[i][2 * t + 1];
                    mma_bf16(c0[0], c0[1], c0[2], c0[3],
                             ah[i][0], ah[i][1], ah[i][2], ah[i][3], bh[t][0], bh[t][2]);
                    mma_bf16(c1[0], c1[1], c1[2], c1[3],
                             ah[i][0], ah[i][1], ah[i][2], ah[i][3], bh[t][1], bh[t][3]);
                    mma_bf16(c0[0], c0[1], c0[2], c0[3],
                             al[i][0], al[i][1], al[i][2], al[i][3], bh[t][0], bh[t][2]);
                    mma_bf16(c1[0], c1[1], c1[2], c1[3],
                             al[i][0], al[i][1], al[i][2], al[i][3], bh[t][1], bh[t][3]);
                    mma_bf16(c0[0], c0[1], c0[2], c0[3],
                             ah[i][0], ah[i][1], ah[i][2], ah[i][3], bl[t][0], bl[t][2]);
                    mma_bf16(c1[0], c1[1], c1[2], c1[3],
                             ah[i][0], ah[i][1], ah[i][2], ah[i][3], bl[t][1], bl[t][3]);
                }
        }
        __syncthreads();
        if (c + GSTAGES - 1 < NK) issue_chunk(c + GSTAGES - 1);
        cp_commit();
    }

    const int gRow = lane >> 2;
    const int gCol = (lane & 3) * 2;
#pragma unroll
    for (int i = 0; i < 2; i++) {
#pragma unroll
        for (int j = 0; j < 8; j++) {
            int row = bm + warpM * 32 + i * 16 + gRow;
            int col = bn + warpN * 64 + j * 8 + gCol;
#pragma unroll
            for (int half = 0; half < 2; half++) {
                int r = row + half * 8;
                float v0 = acc[i][j][half * 2 + 0];
                float v1 = acc[i][j][half * 2 + 1];
                if (EPI == 1 || EPI == 2) {
                    float2 bb = *(const float2*)(bias + col);
                    v0 += bb.x; v1 += bb.y;
                }
                if (EPI == 1) {
                    float2 rv = *(const float2*)(res + (size_t)r * N + col);
                    v0 += rv.x; v1 += rv.y;
                    *(float2*)(C + (size_t)r * N + col) = make_float2(v0, v1);
                } else if (EPI == 2) {
                    v0 = gelu_exact(v0); v1 = gelu_exact(v1);
                    size_t o = (size_t)r * N + col;
                    bf16 h0, l0, h1, l1;
                    split_bf16(v0, h0, l0); split_bf16(v1, h1, l1);
                    *(uint32_t*)(Chi + o) = ((uint32_t)*(uint16_t*)&h1 << 16) | *(uint16_t*)&h0;
                    *(uint32_t*)(Clo + o) = ((uint32_t)*(uint16_t*)&l1 << 16) | *(uint16_t*)&l0;
                } else if (EPI == 3) {
                    int which = col >> 10;
                    int h = (col >> 6) & 15;
                    int e = col & 63;
                    int bb = r >> 11, s = r & 2047;
                    size_t o = (((size_t)(bb * 16 + h)) * SEQ + s) * D_HEAD + e;
                    if (which == 0) { v0 *= QSCALE; v1 *= QSCALE; }
                    bf16 h0, l0, h1, l1;
                    split_bf16(v0, h0, l0); split_bf16(v1, h1, l1);
                    uint32_t ph = ((uint32_t)*(uint16_t*)&h1 << 16) | *(uint16_t*)&h0;
                    uint32_t pl = ((uint32_t)*(uint16_t*)&l1 << 16) | *(uint16_t*)&l0;
                    bf16* dh = (which == 0) ? Qh : (which == 1) ? Kh2 : Vh;
                    bf16* dl = (which == 0) ? Ql : (which == 1) ? Kl2 : Vl;
                    *(uint32_t*)(dh + o) = ph;
                    *(uint32_t*)(dl + o) = pl;
                } else {
                    *(float2*)(C + (size_t)r * N + col) = make_float2(v0, v1);
                }
            }
        }
    }
}

// ---------------- HMMA flash attention ----------------
// grid (SEQ/128, BH), 256 thr (8 warps x m16). K-tiles of 64, double buffered.
// smem: Qhi 0, Qlo 16384; stage s at 32768+s*32768: Khi 0, Klo 8192, Vhi 16384, Vlo 24576
#define ATT_SMEM (32768 + 2 * 32768)

__global__ __launch_bounds__(256, 1) void attn_mma(
    const bf16* __restrict__ qh_g, const bf16* __restrict__ ql_g,
    const bf16* __restrict__ kh_g, const bf16* __restrict__ kl_g,
    const bf16* __restrict__ vh_g, const bf16* __restrict__ vl_g,
    bf16* __restrict__ ohi, bf16* __restrict__ olo) {
    extern __shared__ char smem[];
    const uint32_t sb = smem_to_u32(smem);
    const int tid = threadIdx.x;
    const int lane = tid & 31;
    const int warp = tid >> 5;
    const int bh = blockIdx.y;
    const int q0 = blockIdx.x * 128;

    const char* qb[2] = {(const char*)(qh_g + ((size_t)bh * SEQ + q0) * D_HEAD),
                         (const char*)(ql_g + ((size_t)bh * SEQ + q0) * D_HEAD)};
    const char* kb[2] = {(const char*)(kh_g + (size_t)bh * SEQ * D_HEAD),
                         (const char*)(kl_g + (size_t)bh * SEQ * D_HEAD)};
    const char* vb[2] = {(const char*)(vh_g + (size_t)bh * SEQ * D_HEAD),
                         (const char*)(vl_g + (size_t)bh * SEQ * D_HEAD)};

    // Q: 2048 16B chunks (2 arrays x 128 rows x 8 segs)
    {
#pragma unroll
        for (int j = 0; j < 8; j++) {
            int id = tid + j * 256;
            int arr = id >> 10, row = (id >> 3) & 127, seg = id & 7;
            uint32_t dst = sb + (uint32_t)arr * 16384 + (uint32_t)row * 128 +
                           ((uint32_t)(seg ^ (row & 7)) << 4);
            cp_async16(dst, qb[arr] + (size_t)row * 128 + seg * 16);
        }
    }
    auto issue_kv = [&](int kt) {
        const uint32_t stg = sb + 32768 + (uint32_t)(kt & 1) * 32768;
        const size_t gof = (size_t)kt * 64 * 128;  // 64 rows * 128B
#pragma unroll
        for (int j = 0; j < 8; j++) {
            int id = tid + j * 256;
            int arr = id >> 9, row = (id >> 3) & 63, seg = id & 7;
            const char* src = ((arr < 2) ? kb[arr] : vb[arr - 2]) + gof + (size_t)row * 128 + seg * 16;
            uint32_t dst = stg + (uint32_t)arr * 8192 + (uint32_t)row * 128 +
                           ((uint32_t)(seg ^ (row & 7)) << 4);
            cp_async16(dst, src);
        }
    };

    issue_kv(0);
    cp_commit();  // group0: Q + stage0
    issue_kv(1);
    cp_commit();  // group1: stage1

    float accO[8][4];
#pragma unroll
    for (int t = 0; t < 8; t++)
#pragma unroll
        for (int q = 0; q < 4; q++) accO[t][q] = 0.f;
    float m0 = -1e30f, m1 = -1e30f, l0 = 0.f, l1 = 0.f;

    uint32_t qfh[4][4], qfl[4][4];
    const int qRow = warp * 16 + (lane & 15);
    const uint32_t qSw = (uint32_t)(qRow & 7);
    const uint32_t qRowB = (uint32_t)qRow * 128;

    const int NT = SEQ / 64;
    for (int kt = 0; kt < NT; kt++) {
        cp_wait<1>();
        __syncthreads();
        if (kt == 0) {
#pragma unroll
            for (int ks = 0; ks < 4; ks++) {
                uint32_t seg = ((uint32_t)(ks * 2 + (lane >> 4)) ^ qSw) << 4;
                ldm_x4(qfh[ks][0], qfh[ks][1], qfh[ks][2], qfh[ks][3], sb + qRowB + seg);
                ldm_x4(qfl[ks][0], qfl[ks][1], qfl[ks][2], qfl[ks][3], sb + 16384 + qRowB + seg);
            }
        }
        const uint32_t stg = sb + 32768 + (uint32_t)(kt & 1) * 32768;

        // ---- S = Q K^T (3 passes) ----
        float S[8][4];
#pragma unroll
        for (int t = 0; t < 8; t++)
#pragma unroll
            for (int q = 0; q < 4; q++) S[t][q] = 0.f;

        const int nRow = lane & 15;
        const int kh4 = lane >> 4;
#pragma unroll
        for (int ks = 0; ks < 4; ks++) {
            uint32_t kh[4][4], kl[4][4];
#pragma unroll
            for (int g = 0; g < 4; g++) {
                int row = g * 16 + nRow;
                uint32_t seg = ((uint32_t)(ks * 2 + kh4) ^ (uint32_t)(row & 7)) << 4;
                uint32_t base = stg + (uint32_t)row * 128 + seg;
                ldm_x4(kh[g][0], kh[g][1], kh[g][2], kh[g][3], base);
                ldm_x4(kl[g][0], kl[g][1], kl[g][2], kl[g][3], base + 8192);
            }
#pragma unroll
            for (int g = 0; g < 4; g++) {
                float* c0 = S[2 * g];
                float* c1 = S[2 * g + 1];
                mma_bf16(c0[0], c0[1], c0[2], c0[3],
                         qfh[ks][0], qfh[ks][1], qfh[ks][2], qfh[ks][3], kh[g][0], kh[g][2]);
                mma_bf16(c1[0], c1[1], c1[2], c1[3],
                         qfh[ks][0], qfh[ks][1], qfh[ks][2], qfh[ks][3], kh[g][1], kh[g][3]);
                mma_bf16(c0[0], c0[1], c0[2], c0[3],
                         qfl[ks][0], qfl[ks][1], qfl[ks][2], qfl[ks][3], kh[g][0], kh[g][2]);
                mma_bf16(c1[0], c1[1], c1[2], c1[3],
                         qfl[ks][0], qfl[ks][1], qfl[ks][2], qfl[ks][3], kh[g][1], kh[g][3]);
                mma_bf16(c0[0], c0[1], c0[2], c0[3],
                         qfh[ks][0], qfh[ks][1], qfh[ks][2], qfh[ks][3], kl[g][0], kl[g][2]);
                mma_bf16(c1[0], c1[1], c1[2], c1[3],
                         qfh[ks][0], qfh[ks][1], qfh[ks][2], qfh[ks][3], kl[g][1], kl[g][3]);
            }
        }

        // ---- online softmax (all FMA pipe, base-2 domain) ----
        float mx0 = S[0][0], mx1 = S[0][2];
#pragma unroll
        for (int t = 0; t < 8; t++) {
            mx0 = fmaxf(mx0, fmaxf(S[t][0], S[t][1]));
            mx1 = fmaxf(mx1, fmaxf(S[t][2], S[t][3]));
        }
        mx0 = fmaxf(mx0, __shfl_xor_sync(0xffffffffu, mx0, 1));
        mx0 = fmaxf(mx0, __shfl_xor_sync(0xffffffffu, mx0, 2));
        mx1 = fmaxf(mx1, __shfl_xor_sync(0xffffffffu, mx1, 1));
        mx1 = fmaxf(mx1, __shfl_xor_sync(0xffffffffu, mx1, 2));
        float mn0 = fmaxf(m0, mx0), mn1 = fmaxf(m1, mx1);
        float cr0 = exp2_poly(m0 - mn0), cr1 = exp2_poly(m1 - mn1);
        m0 = mn0; m1 = mn1;
        float sum0 = 0.f, sum1 = 0.f;
#pragma unroll
        for (int t = 0; t < 8; t++) {
            S[t][0] = exp2_poly(S[t][0] - mn0);
            S[t][1] = exp2_poly(S[t][1] - mn0);
            S[t][2] = exp2_poly(S[t][2] - mn1);
            S[t][3] = exp2_poly(S[t][3] - mn1);
            sum0 += S[t][0] + S[t][1];
            sum1 += S[t][2] + S[t][3];
        }
        sum0 += __shfl_xor_sync(0xffffffffu, sum0, 1);
        sum0 += __shfl_xor_sync(0xffffffffu, sum0, 2);
        sum1 += __shfl_xor_sync(0xffffffffu, sum1, 1);
        sum1 += __shfl_xor_sync(0xffffffffu, sum1, 2);
        l0 = l0 * cr0 + sum0;
        l1 = l1 * cr1 + sum1;
#pragma unroll
        for (int t = 0; t < 8; t++) {
            accO[t][0] *= cr0; accO[t][1] *= cr0;
            accO[t][2] *= cr1; accO[t][3] *= cr1;
        }

        // ---- O += P V (3 passes) ----
        const int vRow16 = lane & 15;
        const int vEh = lane >> 4;
#pragma unroll
        for (int ks = 0; ks < 4; ks++) {
            // P A-fragments for this k16 (keys 16ks..16ks+15)
            float ph0 = __bfloat162float(__float2bfloat16(S[2 * ks][0]));
            float ph1 = __bfloat162float(__float2bfloat16(S[2 * ks][1]));
            float ph2 = __bfloat162float(__float2bfloat16(S[2 * ks][2]));
            float ph3 = __bfloat162float(__float2bfloat16(S[2 * ks][3]));
            float qh0 = __bfloat162float(__float2bfloat16(S[2 * ks + 1][0]));
            float qh1 = __bfloat162float(__float2bfloat16(S[2 * ks + 1][1]));
            float qh2 = __bfloat162float(__float2bfloat16(S[2 * ks + 1][2]));
            float qh3 = __bfloat162float(__float2bfloat16(S[2 * ks + 1][3]));
            uint32_t pa_h[4], pa_l[4];
            pa_h[0] = pack_bf16(ph0, ph1);
            pa_h[1] = pack_bf16(ph2, ph3);
            pa_h[2] = pack_bf16(qh0, qh1);
            pa_h[3] = pack_bf16(qh2, qh3);
            pa_l[0] = pack_bf16(S[2 * ks][0] - ph0, S[2 * ks][1] - ph1);
            pa_l[1] = pack_bf16(S[2 * ks][2] - ph2, S[2 * ks][3] - ph3);
            pa_l[2] = pack_bf16(S[2 * ks + 1][0] - qh0, S[2 * ks + 1][1] - qh1);
            pa_l[3] = pack_bf16(S[2 * ks + 1][2] - qh2, S[2 * ks + 1][3] - qh3);

            uint32_t vh[4][4], vl[4][4];
#pragma unroll
            for (int g = 0; g < 4; g++) {
                int row = ks * 16 + vRow16;
                uint32_t seg = ((uint32_t)(g * 2 + vEh) ^ (uint32_t)(row & 7)) << 4;
                uint32_t base = stg + 16384 + (uint32_t)row * 128 + seg;
                ldm_x4_t(vh[g][0], vh[g][1], vh[g][2], vh[g][3], base);
                ldm_x4_t(vl[g][0], vl[g][1], vl[g][2], vl[g][3], base + 8192);
            }
#pragma unroll
            for (int g = 0; g < 4; g++) {
                float* c0 = accO[2 * g];
                float* c1 = accO[2 * g + 1];
                mma_bf16(c0[0], c0[1], c0[2], c0[3],
                         pa_h[0], pa_h[1], pa_h[2], pa_h[3], vh[g][0], vh[g][1]);
                mma_bf16(c1[0], c1[1], c1[2], c1[3],
                         pa_h[0], pa_h[1], pa_h[2], pa_h[3], vh[g][2], vh[g][3]);
                mma_bf16(c0[0], c0[1], c0[2], c0[3],
                         pa_l[0], pa_l[1], pa_l[2], pa_l[3], vh[g][0], vh[g][1]);
                mma_bf16(c1[0], c1[1], c1[2], c1[3],
                         pa_l[0], pa_l[1], pa_l[2], pa_l[3], vh[g][2], vh[g][3]);
                mma_bf16(c0[0], c0[1], c0[2], c0[3],
                         pa_h[0], pa_h[1], pa_h[2], pa_h[3], vl[g][0], vl[g][1]);
                mma_bf16(c1[0], c1[1], c1[2], c1[3],
                         pa_h[0], pa_h[1], pa_h[2], pa_h[3], vl[g][2], vl[g][3]);
            }
        }
        __syncthreads();
        if (kt + 2 < NT) issue_kv(kt + 2);
        cp_commit();
    }

    // ---- epilogue ----
    float inv0 = 1.0f / l0, inv1 = 1.0f / l1;
    const int b = bh >> 4, h = bh & 15;
    const int r1 = q0 + warp * 16 + (lane >> 2);
    const int r2 = r1 + 8;
    size_t t1 = ((size_t)(b * SEQ) + r1) * D_MODEL + h * D_HEAD;
    size_t t2 = ((size_t)(b * SEQ) + r2) * D_MODEL + h * D_HEAD;
#pragma unroll
    for (int t = 0; t < 8; t++) {
        int e = t * 8 + (lane & 3) * 2;
        float a0 = accO[t][0] * inv0, a1 = accO[t][1] * inv0;
        float b0 = accO[t][2] * inv1, b1 = accO[t][3] * inv1;
        bf16 h0, lo0, h1, lo1;
        split_bf16(a0, h0, lo0); split_bf16(a1, h1, lo1);
        *(uint32_t*)(ohi + t1 + e) = ((uint32_t)*(uint16_t*)&h1 << 16) | *(uint16_t*)&h0;
        *(uint32_t*)(olo + t1 + e) = ((uint32_t)*(uint16_t*)&lo1 << 16) | *(uint16_t*)&lo0;
        split_bf16(b0, h0, lo0); split_bf16(b1, h1, lo1);
        *(uint32_t*)(ohi + t2 + e) = ((uint32_t)*(uint16_t*)&h1 << 16) | *(uint16_t*)&h0;
        *(uint32_t*)(olo + t2 + e) = ((uint32_t)*(uint16_t*)&lo1 << 16) | *(uint16_t*)&lo0;
    }
}

// ---------------- launch ----------------
extern "C" void kernel_launch(void* const* d_in, const int* in_sizes, int n_in,
                              void* d_out, int out_size) {
    const float* x    = (const float*)d_in[0];
    const float* Wq   = (const float*)d_in[1];
    const float* Wk   = (const float*)d_in[2];
    const float* Wv   = (const float*)d_in[3];
    const float* Wo   = (const float*)d_in[4];
    const float* bo   = (const float*)d_in[5];
    const float* ln1g = (const float*)d_in[6];
    const float* ln1b = (const float*)d_in[7];
    const float* ln2g = (const float*)d_in[8];
    const float* ln2b = (const float*)d_in[9];
    const float* W1   = (const float*)d_in[10];
    const float* b1   = (const float*)d_in[11];
    const float* W2   = (const float*)d_in[12];
    const float* b2   = (const float*)d_in[13];
    float* out = (float*)d_out;

    bf16 *pWqkvH, *pWqkvL, *pWoH, *pWoL, *pW1H, *pW1L, *pW2H, *pW2L;
    bf16 *pXnH, *pXnL, *pAtH, *pAtL, *pHnH, *pHnL, *pFfH, *pFfL;
    bf16 *pQh, *pQl, *pKh, *pKl, *pVh, *pVl;
    float *pHid;
    cudaGetSymbolAddress((void**)&pWqkvH, g_WqkvT_hi);
    cudaGetSymbolAddress((void**)&pWqkvL, g_WqkvT_lo);
    cudaGetSymbolAddress((void**)&pWoH, g_WoT_hi);
    cudaGetSymbolAddress((void**)&pWoL, g_WoT_lo);
    cudaGetSymbolAddress((void**)&pW1H, g_W1T_hi);
    cudaGetSymbolAddress((void**)&pW1L, g_W1T_lo);
    cudaGetSymbolAddress((void**)&pW2H, g_W2T_hi);
    cudaGetSymbolAddress((void**)&pW2L, g_W2T_lo);
    cudaGetSymbolAddress((void**)&pXnH, g_xn_hi);
    cudaGetSymbolAddress((void**)&pXnL, g_xn_lo);
    cudaGetSymbolAddress((void**)&pAtH, g_at_hi);
    cudaGetSymbolAddress((void**)&pAtL, g_at_lo);
    cudaGetSymbolAddress((void**)&pHnH, g_hn_hi);
    cudaGetSymbolAddress((void**)&pHnL, g_hn_lo);
    cudaGetSymbolAddress((void**)&pFfH, g_ff_hi);
    cudaGetSymbolAddress((void**)&pFfL, g_ff_lo);
    cudaGetSymbolAddress((void**)&pQh, g_q_hi);
    cudaGetSymbolAddress((void**)&pQl, g_q_lo);
    cudaGetSymbolAddress((void**)&pKh, g_k_hi);
    cudaGetSymbolAddress((void**)&pKl, g_k_lo);
    cudaGetSymbolAddress((void**)&pVh, g_v_hi);
    cudaGetSymbolAddress((void**)&pVl, g_v_lo);
    cudaGetSymbolAddress((void**)&pHid, g_hidden);

    const int GEMM_SMEM = GSTAGES * STAGE_BYTES;
    cudaFuncSetAttribute(gemm_mma<1>, cudaFuncAttributeMaxDynamicSharedMemorySize, GEMM_SMEM);
    cudaFuncSetAttribute(gemm_mma<2>, cudaFuncAttributeMaxDynamicSharedMemorySize, GEMM_SMEM);
    cudaFuncSetAttribute(gemm_mma<3>, cudaFuncAttributeMaxDynamicSharedMemorySize, GEMM_SMEM);
    cudaFuncSetAttribute(attn_mma, cudaFuncAttributeMaxDynamicSharedMemorySize, ATT_SMEM);

    dim3 t328(32, 8);
    transconv_qkv_k<<<dim3(D_MODEL / 32, QKV_N / 32), t328>>>(Wq, Wk, Wv, pWqkvH, pWqkvL);
    transconv_k<<<dim3(D_MODEL / 32, D_MODEL / 32), t328>>>(Wo, pWoH, pWoL, D_MODEL, D_MODEL);
    transconv_k<<<dim3(D_MODEL / 32, D_FF / 32), t328>>>(W1, pW1H, pW1L, D_MODEL, D_FF);
    transconv_k<<<dim3(D_FF / 32, D_MODEL / 32), t328>>>(W2, pW2H, pW2L, D_FF, D_MODEL);

    layernorm_split_k<<<TOKENS, 256>>>(x, ln1g, ln1b, pXnH, pXnL);
    // QKV projection -> head-major split q/k/v (Q pre-scaled by 0.125*log2e)
    gemm_mma<3><<<dim3(QKV_N / 128, TOKENS / 128), 256, GEMM_SMEM>>>(
        pXnH, pXnL, pWqkvH, pWqkvL, D_MODEL, QKV_N,
        nullptr, nullptr, nullptr, nullptr, nullptr,
        pQh, pQl, pKh, pKl, pVh, pVl);
    // flash attention (HMMA + poly exp2)
    attn_mma<<<dim3(SEQ / 128, BH), 256, ATT_SMEM>>>(pQh, pQl, pKh, pKl, pVh, pVl, pAtH, pAtL);
    // O projection + bias + residual
    gemm_mma<1><<<dim3(D_MODEL / 128, TOKENS / 128), 256, GEMM_SMEM>>>(
        pAtH, pAtL, pWoH, pWoL, D_MODEL, D_MODEL, pHid, nullptr, nullptr, bo, x,
        nullptr, nullptr, nullptr, nullptr, nullptr, nullptr);
    layernorm_split_k<<<TOKENS, 256>>>(pHid, ln2g, ln2b, pHnH, pHnL);
    // FF1 + bias + GELU
    gemm_mma<2><<<dim3(D_FF / 128, TOKENS / 128), 256, GEMM_SMEM>>>(
        pHnH, pHnL, pW1H, pW1L, D_MODEL, D_FF, nullptr, pFfH, pFfL, b1, nullptr,
        nullptr, nullptr, nullptr, nullptr, nullptr, nullptr);
    // FF2 + bias + residual -> out
    gemm_mma<1><<<dim3(D_MODEL / 128, TOKENS / 128), 256, GEMM_SMEM>>>(
        pFfH, pFfL, pW2H, pW2L, D_FF, D_MODEL, out, nullptr, nullptr, b2, pHid,
        nullptr, nullptr, nullptr, nullptr, nullptr, nullptr);
}

// round 5
// speedup vs baseline: 2.9948x; 1.3358x over previous
#include <cuda_runtime.h>
#include <cuda_bf16.h>
#include <cuda_fp16.h>
#include <math.h>
#include <stdint.h>

#define D_MODEL 1024
#define N_HEADS 16
#define D_HEAD 64
#define D_FF 4096
#define SEQ 2048
#define BATCH 2
#define TOKENS (BATCH * SEQ)
#define QKV_N (3 * D_MODEL)
#define BH (BATCH * N_HEADS)

typedef __nv_bfloat16 bf16;
typedef __half hf;

// ---------------- scratch ----------------
__device__ hf g_WqkvT_hi[QKV_N * D_MODEL];
__device__ hf g_WqkvT_lo[QKV_N * D_MODEL];
__device__ hf g_WoT_hi[D_MODEL * D_MODEL];
__device__ hf g_W1T_hi[D_FF * D_MODEL];
__device__ hf g_W2T_hi[D_MODEL * D_FF];
__device__ hf g_xn_hi[TOKENS * D_MODEL];
__device__ hf g_xn_lo[TOKENS * D_MODEL];
// head-major QKV splits (bf16 for attention): [bh][s][64]
__device__ bf16 g_q_hi[BH * SEQ * D_HEAD];
__device__ bf16 g_q_lo[BH * SEQ * D_HEAD];
__device__ bf16 g_k_hi[BH * SEQ * D_HEAD];
__device__ bf16 g_k_lo[BH * SEQ * D_HEAD];
__device__ bf16 g_v_hi[BH * SEQ * D_HEAD];
__device__ bf16 g_v_lo[BH * SEQ * D_HEAD];
__device__ hf g_at_hi[TOKENS * D_MODEL];
__device__ hf g_at_lo[TOKENS * D_MODEL];
__device__ float g_hidden[TOKENS * D_MODEL];
__device__ hf g_hn_hi[TOKENS * D_MODEL];
__device__ hf g_hn_lo[TOKENS * D_MODEL];
__device__ hf g_ff_hi[(size_t)TOKENS * D_FF];
__device__ hf g_ff_lo[(size_t)TOKENS * D_FF];

__device__ __forceinline__ uint32_t smem_to_u32(const void* p) {
    uint32_t a;
    asm("{ .reg .u64 t; cvta.to.shared.u64 t, %1; cvt.u32.u64 %0, t; }"
        : "=r"(a) : "l"(p));
    return a;
}
__device__ __forceinline__ void cp_async16(uint32_t smem, const void* gmem) {
    asm volatile("cp.async.cg.shared.global [%0], [%1], 16;" :: "r"(smem), "l"(gmem));
}
__device__ __forceinline__ void cp_commit() { asm volatile("cp.async.commit_group;"); }
template <int N>
__device__ __forceinline__ void cp_wait() { asm volatile("cp.async.wait_group %0;" :: "n"(N)); }

__device__ __forceinline__ void ldm_x4(uint32_t& r0, uint32_t& r1, uint32_t& r2, uint32_t& r3,
                                       uint32_t addr) {
    asm volatile("ldmatrix.sync.aligned.m8n8.x4.shared.b16 {%0,%1,%2,%3}, [%4];"
                 : "=r"(r0), "=r"(r1), "=r"(r2), "=r"(r3) : "r"(addr));
}
__device__ __forceinline__ void ldm_x4_t(uint32_t& r0, uint32_t& r1, uint32_t& r2, uint32_t& r3,
                                         uint32_t addr) {
    asm volatile("ldmatrix.sync.aligned.m8n8.x4.trans.shared.b16 {%0,%1,%2,%3}, [%4];"
                 : "=r"(r0), "=r"(r1), "=r"(r2), "=r"(r3) : "r"(addr));
}
__device__ __forceinline__ void mma_bf16(float& c0, float& c1, float& c2, float& c3,
                                         uint32_t a0, uint32_t a1, uint32_t a2, uint32_t a3,
                                         uint32_t b0, uint32_t b1) {
    asm volatile(
        "mma.sync.aligned.m16n8k16.row.col.f32.bf16.bf16.f32 "
        "{%0,%1,%2,%3}, {%4,%5,%6,%7}, {%8,%9}, {%0,%1,%2,%3};"
        : "+f"(c0), "+f"(c1), "+f"(c2), "+f"(c3)
        : "r"(a0), "r"(a1), "r"(a2), "r"(a3), "r"(b0), "r"(b1));
}
__device__ __forceinline__ void mma_f16(float& c0, float& c1, float& c2, float& c3,
                                        uint32_t a0, uint32_t a1, uint32_t a2, uint32_t a3,
                                        uint32_t b0, uint32_t b1) {
    asm volatile(
        "mma.sync.aligned.m16n8k16.row.col.f32.f16.f16.f32 "
        "{%0,%1,%2,%3}, {%4,%5,%6,%7}, {%8,%9}, {%0,%1,%2,%3};"
        : "+f"(c0), "+f"(c1), "+f"(c2), "+f"(c3)
        : "r"(a0), "r"(a1), "r"(a2), "r"(a3), "r"(b0), "r"(b1));
}

__device__ __forceinline__ void split_bf16(float x, bf16& hi, bf16& lo) {
    hi = __float2bfloat16(x);
    lo = __float2bfloat16(x - __bfloat162float(hi));
}
__device__ __forceinline__ void split_h(float x, hf& hi, hf& lo) {
    hi = __float2half_rn(x);
    lo = __float2half_rn(x - __half2float(hi));
}
__device__ __forceinline__ float gelu_exact(float v) {
    return 0.5f * v * (1.0f + erff(v * 0.70710678118654752440f));
}
// FMA-pipe exp2 (no MUFU). y expected <= 0.
__device__ __forceinline__ float exp2_poly(float y) {
    float t = fmaxf(y, -126.0f);
    float fn = t + 12582912.0f;
    int n = __float_as_int(fn) - 0x4B400000;
    float f = t - (fn - 12582912.0f);
    float p = fmaf(0.0013333558f, f, 0.0096181291f);
    p = fmaf(p, f, 0.0555041087f);
    p = fmaf(p, f, 0.2402265070f);
    p = fmaf(p, f, 0.6931471806f);
    p = fmaf(p, f, 1.0f);
    return __int_as_float(__float_as_int(p) + (n << 23));
}
__device__ __forceinline__ uint32_t pack_bf16(float a, float b) {
    __nv_bfloat162 p = __floats2bfloat162_rn(a, b);
    return *(uint32_t*)&p;
}
__device__ __forceinline__ uint32_t pack_h(hf a, hf b) {
    __half2 p = __halves2half2(a, b);
    return *(uint32_t*)&p;
}

#define QSCALE 0.18033688011f  // 0.125 * log2(e)

// ---------------- weight transpose + fp16 split (hi/lo or hi only) ----------------
__global__ void transconv_k(const float* __restrict__ src, hf* __restrict__ dhi,
                            int K, int N) {
    __shared__ float t[32][33];
    int tx = threadIdx.x, ty = threadIdx.y;
    int k0 = blockIdx.x * 32, n0 = blockIdx.y * 32;
#pragma unroll
    for (int i = 0; i < 4; i++)
        t[ty + i * 8][tx] = src[(size_t)(k0 + ty + i * 8) * N + n0 + tx];
    __syncthreads();
#pragma unroll
    for (int i = 0; i < 4; i++) {
        float v = t[tx][ty + i * 8];
        size_t o = (size_t)(n0 + ty + i * 8) * K + k0 + tx;
        dhi[o] = __float2half_rn(v);
    }
}

__global__ void transconv_qkv_k(const float* __restrict__ Wq, const float* __restrict__ Wk,
                                const float* __restrict__ Wv,
                                hf* __restrict__ dhi, hf* __restrict__ dlo) {
    __shared__ float t[32][33];
    int tx = threadIdx.x, ty = threadIdx.y;
    int k0 = blockIdx.x * 32, n0 = blockIdx.y * 32;
    int w = n0 >> 10, h = (n0 >> 6) & 15, e0 = n0 & 63;
    const float* W = (w == 0) ? Wq : (w == 1) ? Wk : Wv;
    const float* src = W + (size_t)h * D_MODEL * D_HEAD;
#pragma unroll
    for (int i = 0; i < 4; i++)
        t[ty + i * 8][tx] = src[(size_t)(k0 + ty + i * 8) * 64 + e0 + tx];
    __syncthreads();
#pragma unroll
    for (int i = 0; i < 4; i++) {
        float v = t[tx][ty + i * 8];
        hf h2, l2; split_h(v, h2, l2);
        size_t o = (size_t)(n0 + ty + i * 8) * D_MODEL + k0 + tx;
        dhi[o] = h2; dlo[o] = l2;
    }
}

// ---------------- LayerNorm -> fp16 hi/lo ----------------
__global__ __launch_bounds__(256) void layernorm_split_k(const float* __restrict__ x,
                                                         const float* __restrict__ g,
                                                         const float* __restrict__ b,
                                                         hf* __restrict__ ohi,
                                                         hf* __restrict__ olo) {
    __shared__ float red[2][8];
    int row = blockIdx.x;
    int tid = threadIdx.x;
    const float4* xr = (const float4*)(x + (size_t)row * D_MODEL);
    float4 v = xr[tid];
    float s = v.x + v.y + v.z + v.w;
    float ss = v.x * v.x + v.y * v.y + v.z * v.z + v.w * v.w;
#pragma unroll
    for (int o = 16; o > 0; o >>= 1) {
        s += __shfl_xor_sync(0xffffffffu, s, o);
        ss += __shfl_xor_sync(0xffffffffu, ss, o);
    }
    int w = tid >> 5, l = tid & 31;
    if (l == 0) { red[0][w] = s; red[1][w] = ss; }
    __syncthreads();
    if (tid < 32) {
        s = (l < 8) ? red[0][l] : 0.f;
        ss = (l < 8) ? red[1][l] : 0.f;
#pragma unroll
        for (int o = 4; o > 0; o >>= 1) {
            s += __shfl_xor_sync(0xffffffffu, s, o);
            ss += __shfl_xor_sync(0xffffffffu, ss, o);
        }
        if (l == 0) { red[0][0] = s; red[1][0] = ss; }
    }
    __syncthreads();
    float mu = red[0][0] * (1.0f / D_MODEL);
    float var = red[1][0] * (1.0f / D_MODEL) - mu * mu;
    float r = rsqrtf(var + 1e-5f);
    float4 gv = ((const float4*)g)[tid];
    float4 bv = ((const float4*)b)[tid];
    float o0 = (v.x - mu) * r * gv.x + bv.x;
    float o1 = (v.y - mu) * r * gv.y + bv.y;
    float o2 = (v.z - mu) * r * gv.z + bv.z;
    float o3 = (v.w - mu) * r * gv.w + bv.w;
    size_t base = (size_t)row * D_MODEL + tid * 4;
    hf h0, l0, h1, l1, h2, l2, h3, l3;
    split_h(o0, h0, l0); split_h(o1, h1, l1);
    split_h(o2, h2, l2); split_h(o3, h3, l3);
    ohi[base + 0] = h0; ohi[base + 1] = h1; ohi[base + 2] = h2; ohi[base + 3] = h3;
    olo[base + 0] = l0; olo[base + 1] = l1; olo[base + 2] = l2; olo[base + 3] = l3;
}

// ---------------- fp16 HMMA GEMM, 2 or 3 passes ----------------
// C = (Ahi + Alo) @ B^T [+ Ahi @ Blo^T when NPASS==3]
// EPI: 0 fp32 C; 1 bias+residual fp32 C; 2 bias+GELU fp16 hi/lo; 3 QKV head-major bf16 split
#define GSTAGES 3

template <int EPI, int NPASS>
__global__ __launch_bounds__(256, 1) void gemm_mma(
    const hf* __restrict__ Ahi, const hf* __restrict__ Alo,
    const hf* __restrict__ Bhi, const hf* __restrict__ Blo,
    int K, int N,
    float* __restrict__ C, hf* __restrict__ Chi, hf* __restrict__ Clo,
    const float* __restrict__ bias, const float* __restrict__ res,
    bf16* __restrict__ Qh, bf16* __restrict__ Ql,
    bf16* __restrict__ Kh2, bf16* __restrict__ Kl2,
    bf16* __restrict__ Vh, bf16* __restrict__ Vl) {
    constexpr int NARR = (NPASS == 3) ? 4 : 3;
    constexpr int STAGE_BYTES = NARR * 8192;
    extern __shared__ char smem[];
    const uint32_t sb = smem_to_u32(smem);
    const int tid = threadIdx.x;
    const int lane = tid & 31;
    const int warp = tid >> 5;
    const int warpM = warp & 3, warpN = warp >> 2;
    const int bn = blockIdx.x * 128, bm = blockIdx.y * 128;

    const size_t rstrideB = (size_t)K * 2;
    const char* gArr[4];
    gArr[0] = (const char*)Ahi + (size_t)bm * K * 2;
    gArr[1] = (const char*)Alo + (size_t)bm * K * 2;
    gArr[2] = (const char*)Bhi + (size_t)bn * K * 2;
    gArr[3] = (NPASS == 3) ? ((const char*)Blo + (size_t)bn * K * 2) : gArr[2];

    const int NK = K >> 5;

    auto issue_chunk = [&](int c) {
        const uint32_t stg = sb + (uint32_t)(c % GSTAGES) * STAGE_BYTES;
        const size_t goff = (size_t)c * 64;
#pragma unroll
        for (int j = 0; j < NARR * 2; j++) {
            int id = tid + j * 256;
            int arr = id >> 9;
            int row = (id >> 2) & 127;
            int seg = id & 3;
            const char* src = gArr[arr] + goff + (size_t)row * rstrideB + seg * 16;
            uint32_t dst = stg + (uint32_t)arr * 8192 + (uint32_t)row * 64 +
                           ((uint32_t)(seg ^ ((row >> 1) & 3)) << 4);
            cp_async16(dst, src);
        }
    };

    const int aRow = warpM * 32 + (lane & 15);
    const int aKh = lane >> 4;
    const uint32_t aSw = (aRow >> 1) & 3;
    const uint32_t aRowB = (uint32_t)aRow * 64;
    const int bRowBase = warpN * 64 + (lane & 15);
    const int bKh = lane >> 4;
    const uint32_t bSw = (bRowBase >> 1) & 3;
    const uint32_t bRowB = (uint32_t)bRowBase * 64;

    float acc[2][8][4];
#pragma unroll
    for (int i = 0; i < 2; i++)
#pragma unroll
        for (int j = 0; j < 8; j++)
#pragma unroll
            for (int q = 0; q < 4; q++) acc[i][j][q] = 0.f;

#pragma unroll
    for (int s = 0; s < GSTAGES - 1; s++) { issue_chunk(s); cp_commit(); }

    for (int c = 0; c < NK; c++) {
        cp_wait<GSTAGES - 2>();
        __syncthreads();
        const uint32_t stg = sb + (uint32_t)(c % GSTAGES) * STAGE_BYTES;
#pragma unroll
        for (int k16 = 0; k16 < 2; k16++) {
            const uint32_t aSeg = ((uint32_t)(k16 * 2 + aKh) ^ aSw) << 4;
            const uint32_t bSeg = ((uint32_t)(k16 * 2 + bKh) ^ bSw) << 4;
            uint32_t ah[2][4], al[2][4], bh[4][4], bl[4][4];
#pragma unroll
            for (int i = 0; i < 2; i++) {
                uint32_t base = stg + aRowB + (uint32_t)i * 16 * 64 + aSeg;
                ldm_x4(ah[i][0], ah[i][1], ah[i][2], ah[i][3], base);
                ldm_x4(al[i][0], al[i][1], al[i][2], al[i][3], base + 8192);
            }
#pragma unroll
            for (int t = 0; t < 4; t++) {
                uint32_t base = stg + 16384 + bRowB + (uint32_t)t * 16 * 64 + bSeg;
                ldm_x4(bh[t][0], bh[t][1], bh[t][2], bh[t][3], base);
                if (NPASS == 3)
                    ldm_x4(bl[t][0], bl[t][1], bl[t][2], bl[t][3], base + 8192);
            }
#pragma unroll
            for (int i = 0; i < 2; i++)
#pragma unroll
                for (int t = 0; t < 4; t++) {
                    float* c0 = acc[i][2 * t];
                    float* c1 = acc[i][2 * t + 1];
                    mma_f16(c0[0], c0[1], c0[2], c0[3],
                            ah[i][0], ah[i][1], ah[i][2], ah[i][3], bh[t][0], bh[t][2]);
                    mma_f16(c1[0], c1[1], c1[2], c1[3],
                            ah[i][0], ah[i][1], ah[i][2], ah[i][3], bh[t][1], bh[t][3]);
                    mma_f16(c0[0], c0[1], c0[2], c0[3],
                            al[i][0], al[i][1], al[i][2], al[i][3], bh[t][0], bh[t][2]);
                    mma_f16(c1[0], c1[1], c1[2], c1[3],
                            al[i][0], al[i][1], al[i][2], al[i][3], bh[t][1], bh[t][3]);
                    if (NPASS == 3) {
                        mma_f16(c0[0], c0[1], c0[2], c0[3],
                                ah[i][0], ah[i][1], ah[i][2], ah[i][3], bl[t][0], bl[t][2]);
                        mma_f16(c1[0], c1[1], c1[2], c1[3],
                                ah[i][0], ah[i][1], ah[i][2], ah[i][3], bl[t][1], bl[t][3]);
                    }
                }
        }
        __syncthreads();
        if (c + GSTAGES - 1 < NK) issue_chunk(c + GSTAGES - 1);
        cp_commit();
    }

    const int gRow = lane >> 2;
    const int gCol = (lane & 3) * 2;
#pragma unroll
    for (int i = 0; i < 2; i++) {
#pragma unroll
        for (int j = 0; j < 8; j++) {
            int row = bm + warpM * 32 + i * 16 + gRow;
            int col = bn + warpN * 64 + j * 8 + gCol;
#pragma unroll
            for (int half = 0; half < 2; half++) {
                int r = row + half * 8;
                float v0 = acc[i][j][half * 2 + 0];
                float v1 = acc[i][j][half * 2 + 1];
                if (EPI == 1 || EPI == 2) {
                    float2 bb = *(const float2*)(bias + col);
                    v0 += bb.x; v1 += bb.y;
                }
                if (EPI == 1) {
                    float2 rv = *(const float2*)(res + (size_t)r * N + col);
                    v0 += rv.x; v1 += rv.y;
                    *(float2*)(C + (size_t)r * N + col) = make_float2(v0, v1);
                } else if (EPI == 2) {
                    v0 = gelu_exact(v0); v1 = gelu_exact(v1);
                    size_t o = (size_t)r * N + col;
                    hf h0, l0, h1, l1;
                    split_h(v0, h0, l0); split_h(v1, h1, l1);
                    *(uint32_t*)(Chi + o) = pack_h(h0, h1);
                    *(uint32_t*)(Clo + o) = pack_h(l0, l1);
                } else if (EPI == 3) {
                    int which = col >> 10;
                    int h = (col >> 6) & 15;
                    int e = col & 63;
                    int bb = r >> 11, s = r & 2047;
                    size_t o = (((size_t)(bb * 16 + h)) * SEQ + s) * D_HEAD + e;
                    if (which == 0) { v0 *= QSCALE; v1 *= QSCALE; }
                    bf16 h0, l0, h1, l1;
                    split_bf16(v0, h0, l0); split_bf16(v1, h1, l1);
                    uint32_t ph = ((uint32_t)*(uint16_t*)&h1 << 16) | *(uint16_t*)&h0;
                    uint32_t pl = ((uint32_t)*(uint16_t*)&l1 << 16) | *(uint16_t*)&l0;
                    bf16* dh = (which == 0) ? Qh : (which == 1) ? Kh2 : Vh;
                    bf16* dl = (which == 0) ? Ql : (which == 1) ? Kl2 : Vl;
                    *(uint32_t*)(dh + o) = ph;
                    *(uint32_t*)(dl + o) = pl;
                } else {
                    *(float2*)(C + (size_t)r * N + col) = make_float2(v0, v1);
                }
            }
        }
    }
}

// ---------------- HMMA flash attention (bf16 3-pass, proven) ----------------
#define ATT_SMEM (32768 + 2 * 32768)

__global__ __launch_bounds__(256, 1) void attn_mma(
    const bf16* __restrict__ qh_g, const bf16* __restrict__ ql_g,
    const bf16* __restrict__ kh_g, const bf16* __restrict__ kl_g,
    const bf16* __restrict__ vh_g, const bf16* __restrict__ vl_g,
    hf* __restrict__ ohi, hf* __restrict__ olo) {
    extern __shared__ char smem[];
    const uint32_t sb = smem_to_u32(smem);
    const int tid = threadIdx.x;
    const int lane = tid & 31;
    const int warp = tid >> 5;
    const int bh = blockIdx.y;
    const int q0 = blockIdx.x * 128;

    const char* qb[2] = {(const char*)(qh_g + ((size_t)bh * SEQ + q0) * D_HEAD),
                         (const char*)(ql_g + ((size_t)bh * SEQ + q0) * D_HEAD)};
    const char* kb[2] = {(const char*)(kh_g + (size_t)bh * SEQ * D_HEAD),
                         (const char*)(kl_g + (size_t)bh * SEQ * D_HEAD)};
    const char* vb[2] = {(const char*)(vh_g + (size_t)bh * SEQ * D_HEAD),
                         (const char*)(vl_g + (size_t)bh * SEQ * D_HEAD)};

    {
#pragma unroll
        for (int j = 0; j < 8; j++) {
            int id = tid + j * 256;
            int arr = id >> 10, row = (id >> 3) & 127, seg = id & 7;
            uint32_t dst = sb + (uint32_t)arr * 16384 + (uint32_t)row * 128 +
                           ((uint32_t)(seg ^ (row & 7)) << 4);
            cp_async16(dst, qb[arr] + (size_t)row * 128 + seg * 16);
        }
    }
    auto issue_kv = [&](int kt) {
        const uint32_t stg = sb + 32768 + (uint32_t)(kt & 1) * 32768;
        const size_t gof = (size_t)kt * 64 * 128;
#pragma unroll
        for (int j = 0; j < 8; j++) {
            int id = tid + j * 256;
            int arr = id >> 9, row = (id >> 3) & 63, seg = id & 7;
            const char* src = ((arr < 2) ? kb[arr] : vb[arr - 2]) + gof + (size_t)row * 128 + seg * 16;
            uint32_t dst = stg + (uint32_t)arr * 8192 + (uint32_t)row * 128 +
                           ((uint32_t)(seg ^ (row & 7)) << 4);
            cp_async16(dst, src);
        }
    };

    issue_kv(0);
    cp_commit();
    issue_kv(1);
    cp_commit();

    float accO[8][4];
#pragma unroll
    for (int t = 0; t < 8; t++)
#pragma unroll
        for (int q = 0; q < 4; q++) accO[t][q] = 0.f;
    float m0 = -1e30f, m1 = -1e30f, l0 = 0.f, l1 = 0.f;

    uint32_t qfh[4][4], qfl[4][4];
    const int qRow = warp * 16 + (lane & 15);
    const uint32_t qSw = (uint32_t)(qRow & 7);
    const uint32_t qRowB = (uint32_t)qRow * 128;

    const int NT = SEQ / 64;
    for (int kt = 0; kt < NT; kt++) {
        cp_wait<1>();
        __syncthreads();
        if (kt == 0) {
#pragma unroll
            for (int ks = 0; ks < 4; ks++) {
                uint32_t seg = ((uint32_t)(ks * 2 + (lane >> 4)) ^ qSw) << 4;
                ldm_x4(qfh[ks][0], qfh[ks][1], qfh[ks][2], qfh[ks][3], sb + qRowB + seg);
                ldm_x4(qfl[ks][0], qfl[ks][1], qfl[ks][2], qfl[ks][3], sb + 16384 + qRowB + seg);
            }
        }
        const uint32_t stg = sb + 32768 + (uint32_t)(kt & 1) * 32768;

        float S[8][4];
#pragma unroll
        for (int t = 0; t < 8; t++)
#pragma unroll
            for (int q = 0; q < 4; q++) S[t][q] = 0.f;

        const int nRow = lane & 15;
        const int kh4 = lane >> 4;
#pragma unroll
        for (int ks = 0; ks < 4; ks++) {
            uint32_t kh[4][4], kl[4][4];
#pragma unroll
            for (int g = 0; g < 4; g++) {
                int row = g * 16 + nRow;
                uint32_t seg = ((uint32_t)(ks * 2 + kh4) ^ (uint32_t)(row & 7)) << 4;
                uint32_t base = stg + (uint32_t)row * 128 + seg;
                ldm_x4(kh[g][0], kh[g][1], kh[g][2], kh[g][3], base);
                ldm_x4(kl[g][0], kl[g][1], kl[g][2], kl[g][3], base + 8192);
            }
#pragma unroll
            for (int g = 0; g < 4; g++) {
                float* c0 = S[2 * g];
                float* c1 = S[2 * g + 1];
                mma_bf16(c0[0], c0[1], c0[2], c0[3],
                         qfh[ks][0], qfh[ks][1], qfh[ks][2], qfh[ks][3], kh[g][0], kh[g][2]);
                mma_bf16(c1[0], c1[1], c1[2], c1[3],
                         qfh[ks][0], qfh[ks][1], qfh[ks][2], qfh[ks][3], kh[g][1], kh[g][3]);
                mma_bf16(c0[0], c0[1], c0[2], c0[3],
                         qfl[ks][0], qfl[ks][1], qfl[ks][2], qfl[ks][3], kh[g][0], kh[g][2]);
                mma_bf16(c1[0], c1[1], c1[2], c1[3],
                         qfl[ks][0], qfl[ks][1], qfl[ks][2], qfl[ks][3], kh[g][1], kh[g][3]);
                mma_bf16(c0[0], c0[1], c0[2], c0[3],
                         qfh[ks][0], qfh[ks][1], qfh[ks][2], qfh[ks][3], kl[g][0], kl[g][2]);
                mma_bf16(c1[0], c1[1], c1[2], c1[3],
                         qfh[ks][0], qfh[ks][1], qfh[ks][2], qfh[ks][3], kl[g][1], kl[g][3]);
            }
        }

        float mx0 = S[0][0], mx1 = S[0][2];
#pragma unroll
        for (int t = 0; t < 8; t++) {
            mx0 = fmaxf(mx0, fmaxf(S[t][0], S[t][1]));
            mx1 = fmaxf(mx1, fmaxf(S[t][2], S[t][3]));
        }
        mx0 = fmaxf(mx0, __shfl_xor_sync(0xffffffffu, mx0, 1));
        mx0 = fmaxf(mx0, __shfl_xor_sync(0xffffffffu, mx0, 2));
        mx1 = fmaxf(mx1, __shfl_xor_sync(0xffffffffu, mx1, 1));
        mx1 = fmaxf(mx1, __shfl_xor_sync(0xffffffffu, mx1, 2));
        float mn0 = fmaxf(m0, mx0), mn1 = fmaxf(m1, mx1);
        float cr0 = exp2_poly(m0 - mn0), cr1 = exp2_poly(m1 - mn1);
        m0 = mn0; m1 = mn1;
        float sum0 = 0.f, sum1 = 0.f;
#pragma unroll
        for (int t = 0; t < 8; t++) {
            S[t][0] = exp2_poly(S[t][0] - mn0);
            S[t][1] = exp2_poly(S[t][1] - mn0);
            S[t][2] = exp2_poly(S[t][2] - mn1);
            S[t][3] = exp2_poly(S[t][3] - mn1);
            sum0 += S[t][0] + S[t][1];
            sum1 += S[t][2] + S[t][3];
        }
        sum0 += __shfl_xor_sync(0xffffffffu, sum0, 1);
        sum0 += __shfl_xor_sync(0xffffffffu, sum0, 2);
        sum1 += __shfl_xor_sync(0xffffffffu, sum1, 1);
        sum1 += __shfl_xor_sync(0xffffffffu, sum1, 2);
        l0 = l0 * cr0 + sum0;
        l1 = l1 * cr1 + sum1;
#pragma unroll
        for (int t = 0; t < 8; t++) {
            accO[t][0] *= cr0; accO[t][1] *= cr0;
            accO[t][2] *= cr1; accO[t][3] *= cr1;
        }

        const int vRow16 = lane & 15;
        const int vEh = lane >> 4;
#pragma unroll
        for (int ks = 0; ks < 4; ks++) {
            float ph0 = __bfloat162float(__float2bfloat16(S[2 * ks][0]));
            float ph1 = __bfloat162float(__float2bfloat16(S[2 * ks][1]));
            float ph2 = __bfloat162float(__float2bfloat16(S[2 * ks][2]));
            float ph3 = __bfloat162float(__float2bfloat16(S[2 * ks][3]));
            float qh0 = __bfloat162float(__float2bfloat16(S[2 * ks + 1][0]));
            float qh1 = __bfloat162float(__float2bfloat16(S[2 * ks + 1][1]));
            float qh2 = __bfloat162float(__float2bfloat16(S[2 * ks + 1][2]));
            float qh3 = __bfloat162float(__float2bfloat16(S[2 * ks + 1][3]));
            uint32_t pa_h[4], pa_l[4];
            pa_h[0] = pack_bf16(ph0, ph1);
            pa_h[1] = pack_bf16(ph2, ph3);
            pa_h[2] = pack_bf16(qh0, qh1);
            pa_h[3] = pack_bf16(qh2, qh3);
            pa_l[0] = pack_bf16(S[2 * ks][0] - ph0, S[2 * ks][1] - ph1);
            pa_l[1] = pack_bf16(S[2 * ks][2] - ph2, S[2 * ks][3] - ph3);
            pa_l[2] = pack_bf16(S[2 * ks + 1][0] - qh0, S[2 * ks + 1][1] - qh1);
            pa_l[3] = pack_bf16(S[2 * ks + 1][2] - qh2, S[2 * ks + 1][3] - qh3);

            uint32_t vh[4][4], vl[4][4];
#pragma unroll
            for (int g = 0; g < 4; g++) {
                int row = ks * 16 + vRow16;
                uint32_t seg = ((uint32_t)(g * 2 + vEh) ^ (uint32_t)(row & 7)) << 4;
                uint32_t base = stg + 16384 + (uint32_t)row * 128 + seg;
                ldm_x4_t(vh[g][0], vh[g][1], vh[g][2], vh[g][3], base);
                ldm_x4_t(vl[g][0], vl[g][1], vl[g][2], vl[g][3], base + 8192);
            }
#pragma unroll
            for (int g = 0; g < 4; g++) {
                float* c0 = accO[2 * g];
                float* c1 = accO[2 * g + 1];
                mma_bf16(c0[0], c0[1], c0[2], c0[3],
                         pa_h[0], pa_h[1], pa_h[2], pa_h[3], vh[g][0], vh[g][1]);
                mma_bf16(c1[0], c1[1], c1[2], c1[3],
                         pa_h[0], pa_h[1], pa_h[2], pa_h[3], vh[g][2], vh[g][3]);
                mma_bf16(c0[0], c0[1], c0[2], c0[3],
                         pa_l[0], pa_l[1], pa_l[2], pa_l[3], vh[g][0], vh[g][1]);
                mma_bf16(c1[0], c1[1], c1[2], c1[3],
                         pa_l[0], pa_l[1], pa_l[2], pa_l[3], vh[g][2], vh[g][3]);
                mma_bf16(c0[0], c0[1], c0[2], c0[3],
                         pa_h[0], pa_h[1], pa_h[2], pa_h[3], vl[g][0], vl[g][1]);
                mma_bf16(c1[0], c1[1], c1[2], c1[3],
                         pa_h[0], pa_h[1], pa_h[2], pa_h[3], vl[g][2], vl[g][3]);
            }
        }
        __syncthreads();
        if (kt + 2 < NT) issue_kv(kt + 2);
        cp_commit();
    }

    float inv0 = 1.0f / l0, inv1 = 1.0f / l1;
    const int b = bh >> 4, h = bh & 15;
    const int r1 = q0 + warp * 16 + (lane >> 2);
    const int r2 = r1 + 8;
    size_t t1 = ((size_t)(b * SEQ) + r1) * D_MODEL + h * D_HEAD;
    size_t t2 = ((size_t)(b * SEQ) + r2) * D_MODEL + h * D_HEAD;
#pragma unroll
    for (int t = 0; t < 8; t++) {
        int e = t * 8 + (lane & 3) * 2;
        float a0 = accO[t][0] * inv0, a1 = accO[t][1] * inv0;
        float b0 = accO[t][2] * inv1, b1 = accO[t][3] * inv1;
        hf h0, lo0, h1, lo1;
        split_h(a0, h0, lo0); split_h(a1, h1, lo1);
        *(uint32_t*)(ohi + t1 + e) = pack_h(h0, h1);
        *(uint32_t*)(olo + t1 + e) = pack_h(lo0, lo1);
        split_h(b0, h0, lo0); split_h(b1, h1, lo1);
        *(uint32_t*)(ohi + t2 + e) = pack_h(h0, h1);
        *(uint32_t*)(olo + t2 + e) = pack_h(lo0, lo1);
    }
}

// ---------------- launch ----------------
extern "C" void kernel_launch(void* const* d_in, const int* in_sizes, int n_in,
                              void* d_out, int out_size) {
    const float* x    = (const float*)d_in[0];
    const float* Wq   = (const float*)d_in[1];
    const float* Wk   = (const float*)d_in[2];
    const float* Wv   = (const float*)d_in[3];
    const float* Wo   = (const float*)d_in[4];
    const float* bo   = (const float*)d_in[5];
    const float* ln1g = (const float*)d_in[6];
    const float* ln1b = (const float*)d_in[7];
    const float* ln2g = (const float*)d_in[8];
    const float* ln2b = (const float*)d_in[9];
    const float* W1   = (const float*)d_in[10];
    const float* b1   = (const float*)d_in[11];
    const float* W2   = (const float*)d_in[12];
    const float* b2   = (const float*)d_in[13];
    float* out = (float*)d_out;

    hf *pWqkvH, *pWqkvL, *pWoH, *pW1H, *pW2H;
    hf *pXnH, *pXnL, *pAtH, *pAtL, *pHnH, *pHnL, *pFfH, *pFfL;
    bf16 *pQh, *pQl, *pKh, *pKl, *pVh, *pVl;
    float *pHid;
    cudaGetSymbolAddress((void**)&pWqkvH, g_WqkvT_hi);
    cudaGetSymbolAddress((void**)&pWqkvL, g_WqkvT_lo);
    cudaGetSymbolAddress((void**)&pWoH, g_WoT_hi);
    cudaGetSymbolAddress((void**)&pW1H, g_W1T_hi);
    cudaGetSymbolAddress((void**)&pW2H, g_W2T_hi);
    cudaGetSymbolAddress((void**)&pXnH, g_xn_hi);
    cudaGetSymbolAddress((void**)&pXnL, g_xn_lo);
    cudaGetSymbolAddress((void**)&pAtH, g_at_hi);
    cudaGetSymbolAddress((void**)&pAtL, g_at_lo);
    cudaGetSymbolAddress((void**)&pHnH, g_hn_hi);
    cudaGetSymbolAddress((void**)&pHnL, g_hn_lo);
    cudaGetSymbolAddress((void**)&pFfH, g_ff_hi);
    cudaGetSymbolAddress((void**)&pFfL, g_ff_lo);
    cudaGetSymbolAddress((void**)&pQh, g_q_hi);
    cudaGetSymbolAddress((void**)&pQl, g_q_lo);
    cudaGetSymbolAddress((void**)&pKh, g_k_hi);
    cudaGetSymbolAddress((void**)&pKl, g_k_lo);
    cudaGetSymbolAddress((void**)&pVh, g_v_hi);
    cudaGetSymbolAddress((void**)&pVl, g_v_lo);
    cudaGetSymbolAddress((void**)&pHid, g_hidden);

    const int SMEM2 = GSTAGES * 3 * 8192;  // 73728
    const int SMEM3 = GSTAGES * 4 * 8192;  // 98304
    cudaFuncSetAttribute((gemm_mma<1, 2>), cudaFuncAttributeMaxDynamicSharedMemorySize, SMEM2);
    cudaFuncSetAttribute((gemm_mma<2, 2>), cudaFuncAttributeMaxDynamicSharedMemorySize, SMEM2);
    cudaFuncSetAttribute((gemm_mma<3, 3>), cudaFuncAttributeMaxDynamicSharedMemorySize, SMEM3);
    cudaFuncSetAttribute(attn_mma, cudaFuncAttributeMaxDynamicSharedMemorySize, ATT_SMEM);

    dim3 t328(32, 8);
    transconv_qkv_k<<<dim3(D_MODEL / 32, QKV_N / 32), t328>>>(Wq, Wk, Wv, pWqkvH, pWqkvL);
    transconv_k<<<dim3(D_MODEL / 32, D_MODEL / 32), t328>>>(Wo, pWoH, D_MODEL, D_MODEL);
    transconv_k<<<dim3(D_MODEL / 32, D_FF / 32), t328>>>(W1, pW1H, D_MODEL, D_FF);
    transconv_k<<<dim3(D_FF / 32, D_MODEL / 32), t328>>>(W2, pW2H, D_FF, D_MODEL);

    layernorm_split_k<<<TOKENS, 256>>>(x, ln1g, ln1b, pXnH, pXnL);
    // QKV projection (3-pass fp16 for score accuracy) -> head-major bf16 q/k/v
    gemm_mma<3, 3><<<dim3(QKV_N / 128, TOKENS / 128), 256, SMEM3>>>(
        pXnH, pXnL, pWqkvH, pWqkvL, D_MODEL, QKV_N,
        nullptr, nullptr, nullptr, nullptr, nullptr,
        pQh, pQl, pKh, pKl, pVh, pVl);
    // flash attention (bf16 3-pass + poly exp2) -> fp16 hi/lo
    attn_mma<<<dim3(SEQ / 128, BH), 256, ATT_SMEM>>>(pQh, pQl, pKh, pKl, pVh, pVl, pAtH, pAtL);
    // O projection (2-pass) + bias + residual
    gemm_mma<1, 2><<<dim3(D_MODEL / 128, TOKENS / 128), 256, SMEM2>>>(
        pAtH, pAtL, pWoH, nullptr, D_MODEL, D_MODEL, pHid, nullptr, nullptr, bo, x,
        nullptr, nullptr, nullptr, nullptr, nullptr, nullptr);
    layernorm_split_k<<<TOKENS, 256>>>(pHid, ln2g, ln2b, pHnH, pHnL);
    // FF1 (2-pass) + bias + GELU -> fp16 hi/lo
    gemm_mma<2, 2><<<dim3(D_FF / 128, TOKENS / 128), 256, SMEM2>>>(
        pHnH, pHnL, pW1H, nullptr, D_MODEL, D_FF, nullptr, pFfH, pFfL, b1, nullptr,
        nullptr, nullptr, nullptr, nullptr, nullptr, nullptr);
    // FF2 (2-pass) + bias + residual -> out
    gemm_mma<1, 2><<<dim3(D_MODEL / 128, TOKENS / 128), 256, SMEM2>>>(
        pFfH, pFfL, pW2H, nullptr, D_FF, D_MODEL, out, nullptr, nullptr, b2, pHid,
        nullptr, nullptr, nullptr, nullptr, nullptr, nullptr);
}

// round 6
// speedup vs baseline: 4.3259x; 1.4445x over previous
#include <cuda_runtime.h>
#include <cuda_bf16.h>
#include <cuda_fp16.h>
#include <math.h>
#include <stdint.h>

#define D_MODEL 1024
#define N_HEADS 16
#define D_HEAD 64
#define D_FF 4096
#define SEQ 2048
#define BATCH 2
#define TOKENS (BATCH * SEQ)
#define QKV_N (3 * D_MODEL)
#define BH (BATCH * N_HEADS)

typedef __half hf;

// ---------------- scratch ----------------
__device__ hf g_WqkvT_hi[QKV_N * D_MODEL];
__device__ hf g_WqkvT_lo[QKV_N * D_MODEL];
__device__ hf g_WoT_hi[D_MODEL * D_MODEL];
__device__ hf g_W1T_hi[D_FF * D_MODEL];
__device__ hf g_W2T_hi[D_MODEL * D_FF];
__device__ hf g_xn_hi[TOKENS * D_MODEL];
__device__ hf g_xn_lo[TOKENS * D_MODEL];
// head-major QKV: [bh][s][64]; Q split hi/lo, K/V hi only
__device__ hf g_q_hi[BH * SEQ * D_HEAD];
__device__ hf g_q_lo[BH * SEQ * D_HEAD];
__device__ hf g_k_hi[BH * SEQ * D_HEAD];
__device__ hf g_v_hi[BH * SEQ * D_HEAD];
__device__ hf g_at_hi[TOKENS * D_MODEL];
__device__ float g_hidden[TOKENS * D_MODEL];
__device__ hf g_hn_hi[TOKENS * D_MODEL];
__device__ hf g_hn_lo[TOKENS * D_MODEL];
__device__ hf g_ff_hi[(size_t)TOKENS * D_FF];

__device__ __forceinline__ uint32_t smem_to_u32(const void* p) {
    uint32_t a;
    asm("{ .reg .u64 t; cvta.to.shared.u64 t, %1; cvt.u32.u64 %0, t; }"
        : "=r"(a) : "l"(p));
    return a;
}
__device__ __forceinline__ void cp_async16(uint32_t smem, const void* gmem) {
    asm volatile("cp.async.cg.shared.global [%0], [%1], 16;" :: "r"(smem), "l"(gmem));
}
__device__ __forceinline__ void cp_commit() { asm volatile("cp.async.commit_group;"); }
template <int N>
__device__ __forceinline__ void cp_wait() { asm volatile("cp.async.wait_group %0;" :: "n"(N)); }

__device__ __forceinline__ void ldm_x4(uint32_t& r0, uint32_t& r1, uint32_t& r2, uint32_t& r3,
                                       uint32_t addr) {
    asm volatile("ldmatrix.sync.aligned.m8n8.x4.shared.b16 {%0,%1,%2,%3}, [%4];"
                 : "=r"(r0), "=r"(r1), "=r"(r2), "=r"(r3) : "r"(addr));
}
__device__ __forceinline__ void ldm_x4_t(uint32_t& r0, uint32_t& r1, uint32_t& r2, uint32_t& r3,
                                         uint32_t addr) {
    asm volatile("ldmatrix.sync.aligned.m8n8.x4.trans.shared.b16 {%0,%1,%2,%3}, [%4];"
                 : "=r"(r0), "=r"(r1), "=r"(r2), "=r"(r3) : "r"(addr));
}
__device__ __forceinline__ void mma_f16(float& c0, float& c1, float& c2, float& c3,
                                        uint32_t a0, uint32_t a1, uint32_t a2, uint32_t a3,
                                        uint32_t b0, uint32_t b1) {
    asm volatile(
        "mma.sync.aligned.m16n8k16.row.col.f32.f16.f16.f32 "
        "{%0,%1,%2,%3}, {%4,%5,%6,%7}, {%8,%9}, {%0,%1,%2,%3};"
        : "+f"(c0), "+f"(c1), "+f"(c2), "+f"(c3)
        : "r"(a0), "r"(a1), "r"(a2), "r"(a3), "r"(b0), "r"(b1));
}

__device__ __forceinline__ void split_h(float x, hf& hi, hf& lo) {
    hi = __float2half_rn(x);
    lo = __float2half_rn(x - __half2float(hi));
}
__device__ __forceinline__ float gelu_exact(float v) {
    return 0.5f * v * (1.0f + erff(v * 0.70710678118654752440f));
}
// FMA-pipe exp2 (no MUFU). y expected <= 0.
__device__ __forceinline__ float exp2_poly(float y) {
    float t = fmaxf(y, -126.0f);
    float fn = t + 12582912.0f;
    int n = __float_as_int(fn) - 0x4B400000;
    float f = t - (fn - 12582912.0f);
    float p = fmaf(0.0013333558f, f, 0.0096181291f);
    p = fmaf(p, f, 0.0555041087f);
    p = fmaf(p, f, 0.2402265070f);
    p = fmaf(p, f, 0.6931471806f);
    p = fmaf(p, f, 1.0f);
    return __int_as_float(__float_as_int(p) + (n << 23));
}
__device__ __forceinline__ uint32_t pack_h(hf a, hf b) {
    __half2 p = __halves2half2(a, b);
    return *(uint32_t*)&p;
}

#define QSCALE 0.18033688011f  // 0.125 * log2(e)

// ---------------- weight transpose, fp16 (hi only) ----------------
__global__ void transconv_k(const float* __restrict__ src, hf* __restrict__ dhi,
                            int K, int N) {
    __shared__ float t[32][33];
    int tx = threadIdx.x, ty = threadIdx.y;
    int k0 = blockIdx.x * 32, n0 = blockIdx.y * 32;
#pragma unroll
    for (int i = 0; i < 4; i++)
        t[ty + i * 8][tx] = src[(size_t)(k0 + ty + i * 8) * N + n0 + tx];
    __syncthreads();
#pragma unroll
    for (int i = 0; i < 4; i++) {
        float v = t[tx][ty + i * 8];
        size_t o = (size_t)(n0 + ty + i * 8) * K + k0 + tx;
        dhi[o] = __float2half_rn(v);
    }
}

__global__ void transconv_qkv_k(const float* __restrict__ Wq, const float* __restrict__ Wk,
                                const float* __restrict__ Wv,
                                hf* __restrict__ dhi, hf* __restrict__ dlo) {
    __shared__ float t[32][33];
    int tx = threadIdx.x, ty = threadIdx.y;
    int k0 = blockIdx.x * 32, n0 = blockIdx.y * 32;
    int w = n0 >> 10, h = (n0 >> 6) & 15, e0 = n0 & 63;
    const float* W = (w == 0) ? Wq : (w == 1) ? Wk : Wv;
    const float* src = W + (size_t)h * D_MODEL * D_HEAD;
#pragma unroll
    for (int i = 0; i < 4; i++)
        t[ty + i * 8][tx] = src[(size_t)(k0 + ty + i * 8) * 64 + e0 + tx];
    __syncthreads();
#pragma unroll
    for (int i = 0; i < 4; i++) {
        float v = t[tx][ty + i * 8];
        hf h2, l2; split_h(v, h2, l2);
        size_t o = (size_t)(n0 + ty + i * 8) * D_MODEL + k0 + tx;
        dhi[o] = h2; dlo[o] = l2;
    }
}

// ---------------- LayerNorm -> fp16 hi/lo ----------------
__global__ __launch_bounds__(256) void layernorm_split_k(const float* __restrict__ x,
                                                         const float* __restrict__ g,
                                                         const float* __restrict__ b,
                                                         hf* __restrict__ ohi,
                                                         hf* __restrict__ olo) {
    __shared__ float red[2][8];
    int row = blockIdx.x;
    int tid = threadIdx.x;
    const float4* xr = (const float4*)(x + (size_t)row * D_MODEL);
    float4 v = xr[tid];
    float s = v.x + v.y + v.z + v.w;
    float ss = v.x * v.x + v.y * v.y + v.z * v.z + v.w * v.w;
#pragma unroll
    for (int o = 16; o > 0; o >>= 1) {
        s += __shfl_xor_sync(0xffffffffu, s, o);
        ss += __shfl_xor_sync(0xffffffffu, ss, o);
    }
    int w = tid >> 5, l = tid & 31;
    if (l == 0) { red[0][w] = s; red[1][w] = ss; }
    __syncthreads();
    if (tid < 32) {
        s = (l < 8) ? red[0][l] : 0.f;
        ss = (l < 8) ? red[1][l] : 0.f;
#pragma unroll
        for (int o = 4; o > 0; o >>= 1) {
            s += __shfl_xor_sync(0xffffffffu, s, o);
            ss += __shfl_xor_sync(0xffffffffu, ss, o);
        }
        if (l == 0) { red[0][0] = s; red[1][0] = ss; }
    }
    __syncthreads();
    float mu = red[0][0] * (1.0f / D_MODEL);
    float var = red[1][0] * (1.0f / D_MODEL) - mu * mu;
    float r = rsqrtf(var + 1e-5f);
    float4 gv = ((const float4*)g)[tid];
    float4 bv = ((const float4*)b)[tid];
    float o0 = (v.x - mu) * r * gv.x + bv.x;
    float o1 = (v.y - mu) * r * gv.y + bv.y;
    float o2 = (v.z - mu) * r * gv.z + bv.z;
    float o3 = (v.w - mu) * r * gv.w + bv.w;
    size_t base = (size_t)row * D_MODEL + tid * 4;
    hf h0, l0, h1, l1, h2, l2, h3, l3;
    split_h(o0, h0, l0); split_h(o1, h1, l1);
    split_h(o2, h2, l2); split_h(o3, h3, l3);
    ohi[base + 0] = h0; ohi[base + 1] = h1; ohi[base + 2] = h2; ohi[base + 3] = h3;
    olo[base + 0] = l0; olo[base + 1] = l1; olo[base + 2] = l2; olo[base + 3] = l3;
}

// ---------------- fp16 HMMA GEMM, 1 or 3 passes ----------------
// NPASS==1: C = fl16(A) @ fl16(B)^T; NPASS==3: (Ahi+Alo)@Bhi + Ahi@Blo
// EPI: 1 bias+residual fp32 C; 2 bias+GELU fp16 hi; 3 QKV head-major (Q hi/lo scaled, K/V hi)
#define GSTAGES 3

template <int EPI, int NPASS>
__global__ __launch_bounds__(256, 1) void gemm_mma(
    const hf* __restrict__ Ahi, const hf* __restrict__ Alo,
    const hf* __restrict__ Bhi, const hf* __restrict__ Blo,
    int K, int N,
    float* __restrict__ C, hf* __restrict__ Chi,
    const float* __restrict__ bias, const float* __restrict__ res,
    hf* __restrict__ Qh, hf* __restrict__ Ql,
    hf* __restrict__ Kh2, hf* __restrict__ Vh) {
    constexpr int NARR = (NPASS == 3) ? 4 : 2;
    constexpr int STAGE_BYTES = NARR * 8192;
    constexpr uint32_t B_OFF = (NPASS == 3) ? 16384 : 8192;
    extern __shared__ char smem[];
    const uint32_t sb = smem_to_u32(smem);
    const int tid = threadIdx.x;
    const int lane = tid & 31;
    const int warp = tid >> 5;
    const int warpM = warp & 3, warpN = warp >> 2;
    const int bn = blockIdx.x * 128, bm = blockIdx.y * 128;

    const size_t rstrideB = (size_t)K * 2;
    const char* gArr[NARR];
    if (NPASS == 3) {
        gArr[0] = (const char*)Ahi + (size_t)bm * K * 2;
        gArr[1] = (const char*)Alo + (size_t)bm * K * 2;
        gArr[2] = (const char*)Bhi + (size_t)bn * K * 2;
        gArr[3] = (const char*)Blo + (size_t)bn * K * 2;
    } else {
        gArr[0] = (const char*)Ahi + (size_t)bm * K * 2;
        gArr[1] = (const char*)Bhi + (size_t)bn * K * 2;
    }

    const int NK = K >> 5;

    auto issue_chunk = [&](int c) {
        const uint32_t stg = sb + (uint32_t)(c % GSTAGES) * STAGE_BYTES;
        const size_t goff = (size_t)c * 64;
#pragma unroll
        for (int j = 0; j < NARR * 2; j++) {
            int id = tid + j * 256;
            int arr = id >> 9;
            int row = (id >> 2) & 127;
            int seg = id & 3;
            const char* src = gArr[arr] + goff + (size_t)row * rstrideB + seg * 16;
            uint32_t dst = stg + (uint32_t)arr * 8192 + (uint32_t)row * 64 +
                           ((uint32_t)(seg ^ ((row >> 1) & 3)) << 4);
            cp_async16(dst, src);
        }
    };

    const int aRow = warpM * 32 + (lane & 15);
    const int aKh = lane >> 4;
    const uint32_t aSw = (aRow >> 1) & 3;
    const uint32_t aRowB = (uint32_t)aRow * 64;
    const int bRowBase = warpN * 64 + (lane & 15);
    const int bKh = lane >> 4;
    const uint32_t bSw = (bRowBase >> 1) & 3;
    const uint32_t bRowB = (uint32_t)bRowBase * 64;

    float acc[2][8][4];
#pragma unroll
    for (int i = 0; i < 2; i++)
#pragma unroll
        for (int j = 0; j < 8; j++)
#pragma unroll
            for (int q = 0; q < 4; q++) acc[i][j][q] = 0.f;

#pragma unroll
    for (int s = 0; s < GSTAGES - 1; s++) { issue_chunk(s); cp_commit(); }

    for (int c = 0; c < NK; c++) {
        cp_wait<GSTAGES - 2>();
        __syncthreads();
        const uint32_t stg = sb + (uint32_t)(c % GSTAGES) * STAGE_BYTES;
#pragma unroll
        for (int k16 = 0; k16 < 2; k16++) {
            const uint32_t aSeg = ((uint32_t)(k16 * 2 + aKh) ^ aSw) << 4;
            const uint32_t bSeg = ((uint32_t)(k16 * 2 + bKh) ^ bSw) << 4;
            uint32_t ah[2][4], al[2][4], bh[4][4], bl[4][4];
#pragma unroll
            for (int i = 0; i < 2; i++) {
                uint32_t base = stg + aRowB + (uint32_t)i * 16 * 64 + aSeg;
                ldm_x4(ah[i][0], ah[i][1], ah[i][2], ah[i][3], base);
                if (NPASS == 3)
                    ldm_x4(al[i][0], al[i][1], al[i][2], al[i][3], base + 8192);
            }
#pragma unroll
            for (int t = 0; t < 4; t++) {
                uint32_t base = stg + B_OFF + bRowB + (uint32_t)t * 16 * 64 + bSeg;
                ldm_x4(bh[t][0], bh[t][1], bh[t][2], bh[t][3], base);
                if (NPASS == 3)
                    ldm_x4(bl[t][0], bl[t][1], bl[t][2], bl[t][3], base + 8192);
            }
#pragma unroll
            for (int i = 0; i < 2; i++)
#pragma unroll
                for (int t = 0; t < 4; t++) {
                    float* c0 = acc[i][2 * t];
                    float* c1 = acc[i][2 * t + 1];
                    mma_f16(c0[0], c0[1], c0[2], c0[3],
                            ah[i][0], ah[i][1], ah[i][2], ah[i][3], bh[t][0], bh[t][2]);
                    mma_f16(c1[0], c1[1], c1[2], c1[3],
                            ah[i][0], ah[i][1], ah[i][2], ah[i][3], bh[t][1], bh[t][3]);
                    if (NPASS == 3) {
                        mma_f16(c0[0], c0[1], c0[2], c0[3],
                                al[i][0], al[i][1], al[i][2], al[i][3], bh[t][0], bh[t][2]);
                        mma_f16(c1[0], c1[1], c1[2], c1[3],
                                al[i][0], al[i][1], al[i][2], al[i][3], bh[t][1], bh[t][3]);
                        mma_f16(c0[0], c0[1], c0[2], c0[3],
                                ah[i][0], ah[i][1], ah[i][2], ah[i][3], bl[t][0], bl[t][2]);
                        mma_f16(c1[0], c1[1], c1[2], c1[3],
                                ah[i][0], ah[i][1], ah[i][2], ah[i][3], bl[t][1], bl[t][3]);
                    }
                }
        }
        __syncthreads();
        if (c + GSTAGES - 1 < NK) issue_chunk(c + GSTAGES - 1);
        cp_commit();
    }

    const int gRow = lane >> 2;
    const int gCol = (lane & 3) * 2;
#pragma unroll
    for (int i = 0; i < 2; i++) {
#pragma unroll
        for (int j = 0; j < 8; j++) {
            int row = bm + warpM * 32 + i * 16 + gRow;
            int col = bn + warpN * 64 + j * 8 + gCol;
#pragma unroll
            for (int half = 0; half < 2; half++) {
                int r = row + half * 8;
                float v0 = acc[i][j][half * 2 + 0];
                float v1 = acc[i][j][half * 2 + 1];
                if (EPI == 1 || EPI == 2) {
                    float2 bb = *(const float2*)(bias + col);
                    v0 += bb.x; v1 += bb.y;
                }
                if (EPI == 1) {
                    float2 rv = *(const float2*)(res + (size_t)r * N + col);
                    v0 += rv.x; v1 += rv.y;
                    *(float2*)(C + (size_t)r * N + col) = make_float2(v0, v1);
                } else if (EPI == 2) {
                    v0 = gelu_exact(v0); v1 = gelu_exact(v1);
                    size_t o = (size_t)r * N + col;
                    *(uint32_t*)(Chi + o) = pack_h(__float2half_rn(v0), __float2half_rn(v1));
                } else if (EPI == 3) {
                    int which = col >> 10;
                    int h = (col >> 6) & 15;
                    int e = col & 63;
                    int bb = r >> 11, s = r & 2047;
                    size_t o = (((size_t)(bb * 16 + h)) * SEQ + s) * D_HEAD + e;
                    if (which == 0) {
                        v0 *= QSCALE; v1 *= QSCALE;
                        hf h0, l0, h1, l1;
                        split_h(v0, h0, l0); split_h(v1, h1, l1);
                        *(uint32_t*)(Qh + o) = pack_h(h0, h1);
                        *(uint32_t*)(Ql + o) = pack_h(l0, l1);
                    } else {
                        hf* dst = (which == 1) ? Kh2 : Vh;
                        *(uint32_t*)(dst + o) = pack_h(__float2half_rn(v0), __float2half_rn(v1));
                    }
                }
            }
        }
    }
}

// ---------------- fp16 HMMA flash attention, 2-pass S and PV ----------------
// smem: Qhi 0, Qlo 16384; stage s at 32768 + s*16384: Khi 0, Vhi 8192
#define ATT_SMEM (32768 + 2 * 16384)

__global__ __launch_bounds__(256, 1) void attn_mma(
    const hf* __restrict__ qh_g, const hf* __restrict__ ql_g,
    const hf* __restrict__ kh_g, const hf* __restrict__ vh_g,
    hf* __restrict__ ohi) {
    extern __shared__ char smem[];
    const uint32_t sb = smem_to_u32(smem);
    const int tid = threadIdx.x;
    const int lane = tid & 31;
    const int warp = tid >> 5;
    const int bh = blockIdx.y;
    const int q0 = blockIdx.x * 128;

    const char* qb[2] = {(const char*)(qh_g + ((size_t)bh * SEQ + q0) * D_HEAD),
                         (const char*)(ql_g + ((size_t)bh * SEQ + q0) * D_HEAD)};
    const char* kb = (const char*)(kh_g + (size_t)bh * SEQ * D_HEAD);
    const char* vb = (const char*)(vh_g + (size_t)bh * SEQ * D_HEAD);

    {
#pragma unroll
        for (int j = 0; j < 8; j++) {
            int id = tid + j * 256;
            int arr = id >> 10, row = (id >> 3) & 127, seg = id & 7;
            uint32_t dst = sb + (uint32_t)arr * 16384 + (uint32_t)row * 128 +
                           ((uint32_t)(seg ^ (row & 7)) << 4);
            cp_async16(dst, qb[arr] + (size_t)row * 128 + seg * 16);
        }
    }
    auto issue_kv = [&](int kt) {
        const uint32_t stg = sb + 32768 + (uint32_t)(kt & 1) * 16384;
        const size_t gof = (size_t)kt * 64 * 128;
#pragma unroll
        for (int j = 0; j < 4; j++) {
            int id = tid + j * 256;
            int arr = id >> 9, row = (id >> 3) & 63, seg = id & 7;
            const char* src = ((arr == 0) ? kb : vb) + gof + (size_t)row * 128 + seg * 16;
            uint32_t dst = stg + (uint32_t)arr * 8192 + (uint32_t)row * 128 +
                           ((uint32_t)(seg ^ (row & 7)) << 4);
            cp_async16(dst, src);
        }
    };

    issue_kv(0);
    cp_commit();
    issue_kv(1);
    cp_commit();

    float accO[8][4];
#pragma unroll
    for (int t = 0; t < 8; t++)
#pragma unroll
        for (int q = 0; q < 4; q++) accO[t][q] = 0.f;
    float m0 = -1e30f, m1 = -1e30f, l0 = 0.f, l1 = 0.f;

    uint32_t qfh[4][4], qfl[4][4];
    const int qRow = warp * 16 + (lane & 15);
    const uint32_t qSw = (uint32_t)(qRow & 7);
    const uint32_t qRowB = (uint32_t)qRow * 128;

    const int NT = SEQ / 64;
    for (int kt = 0; kt < NT; kt++) {
        cp_wait<1>();
        __syncthreads();
        if (kt == 0) {
#pragma unroll
            for (int ks = 0; ks < 4; ks++) {
                uint32_t seg = ((uint32_t)(ks * 2 + (lane >> 4)) ^ qSw) << 4;
                ldm_x4(qfh[ks][0], qfh[ks][1], qfh[ks][2], qfh[ks][3], sb + qRowB + seg);
                ldm_x4(qfl[ks][0], qfl[ks][1], qfl[ks][2], qfl[ks][3], sb + 16384 + qRowB + seg);
            }
        }
        const uint32_t stg = sb + 32768 + (uint32_t)(kt & 1) * 16384;

        // ---- S = (Qhi+Qlo) Khi^T ----
        float S[8][4];
#pragma unroll
        for (int t = 0; t < 8; t++)
#pragma unroll
            for (int q = 0; q < 4; q++) S[t][q] = 0.f;

        const int nRow = lane & 15;
        const int kh4 = lane >> 4;
#pragma unroll
        for (int ks = 0; ks < 4; ks++) {
            uint32_t kh[4][4];
#pragma unroll
            for (int g = 0; g < 4; g++) {
                int row = g * 16 + nRow;
                uint32_t seg = ((uint32_t)(ks * 2 + kh4) ^ (uint32_t)(row & 7)) << 4;
                ldm_x4(kh[g][0], kh[g][1], kh[g][2], kh[g][3],
                       stg + (uint32_t)row * 128 + seg);
            }
#pragma unroll
            for (int g = 0; g < 4; g++) {
                float* c0 = S[2 * g];
                float* c1 = S[2 * g + 1];
                mma_f16(c0[0], c0[1], c0[2], c0[3],
                        qfh[ks][0], qfh[ks][1], qfh[ks][2], qfh[ks][3], kh[g][0], kh[g][2]);
                mma_f16(c1[0], c1[1], c1[2], c1[3],
                        qfh[ks][0], qfh[ks][1], qfh[ks][2], qfh[ks][3], kh[g][1], kh[g][3]);
                mma_f16(c0[0], c0[1], c0[2], c0[3],
                        qfl[ks][0], qfl[ks][1], qfl[ks][2], qfl[ks][3], kh[g][0], kh[g][2]);
                mma_f16(c1[0], c1[1], c1[2], c1[3],
                        qfl[ks][0], qfl[ks][1], qfl[ks][2], qfl[ks][3], kh[g][1], kh[g][3]);
            }
        }

        // ---- online softmax (FMA pipe, base-2 domain) ----
        float mx0 = S[0][0], mx1 = S[0][2];
#pragma unroll
        for (int t = 0; t < 8; t++) {
            mx0 = fmaxf(mx0, fmaxf(S[t][0], S[t][1]));
            mx1 = fmaxf(mx1, fmaxf(S[t][2], S[t][3]));
        }
        mx0 = fmaxf(mx0, __shfl_xor_sync(0xffffffffu, mx0, 1));
        mx0 = fmaxf(mx0, __shfl_xor_sync(0xffffffffu, mx0, 2));
        mx1 = fmaxf(mx1, __shfl_xor_sync(0xffffffffu, mx1, 1));
        mx1 = fmaxf(mx1, __shfl_xor_sync(0xffffffffu, mx1, 2));
        float mn0 = fmaxf(m0, mx0), mn1 = fmaxf(m1, mx1);
        float cr0 = exp2_poly(m0 - mn0), cr1 = exp2_poly(m1 - mn1);
        m0 = mn0; m1 = mn1;
        float sum0 = 0.f, sum1 = 0.f;
#pragma unroll
        for (int t = 0; t < 8; t++) {
            S[t][0] = exp2_poly(S[t][0] - mn0);
            S[t][1] = exp2_poly(S[t][1] - mn0);
            S[t][2] = exp2_poly(S[t][2] - mn1);
            S[t][3] = exp2_poly(S[t][3] - mn1);
            sum0 += S[t][0] + S[t][1];
            sum1 += S[t][2] + S[t][3];
        }
        sum0 += __shfl_xor_sync(0xffffffffu, sum0, 1);
        sum0 += __shfl_xor_sync(0xffffffffu, sum0, 2);
        sum1 += __shfl_xor_sync(0xffffffffu, sum1, 1);
        sum1 += __shfl_xor_sync(0xffffffffu, sum1, 2);
        l0 = l0 * cr0 + sum0;
        l1 = l1 * cr1 + sum1;
#pragma unroll
        for (int t = 0; t < 8; t++) {
            accO[t][0] *= cr0; accO[t][1] *= cr0;
            accO[t][2] *= cr1; accO[t][3] *= cr1;
        }

        // ---- O += (Phi+Plo) Vhi ----
        const int vRow16 = lane & 15;
        const int vEh = lane >> 4;
#pragma unroll
        for (int ks = 0; ks < 4; ks++) {
            hf h00, l00, h01, l01, h02, l02, h03, l03;
            hf h10, l10, h11, l11, h12, l12, h13, l13;
            split_h(S[2 * ks][0], h00, l00); split_h(S[2 * ks][1], h01, l01);
            split_h(S[2 * ks][2], h02, l02); split_h(S[2 * ks][3], h03, l03);
            split_h(S[2 * ks + 1][0], h10, l10); split_h(S[2 * ks + 1][1], h11, l11);
            split_h(S[2 * ks + 1][2], h12, l12); split_h(S[2 * ks + 1][3], h13, l13);
            uint32_t pa_h[4], pa_l[4];
            pa_h[0] = pack_h(h00, h01); pa_h[1] = pack_h(h02, h03);
            pa_h[2] = pack_h(h10, h11); pa_h[3] = pack_h(h12, h13);
            pa_l[0] = pack_h(l00, l01); pa_l[1] = pack_h(l02, l03);
            pa_l[2] = pack_h(l10, l11); pa_l[3] = pack_h(l12, l13);

            uint32_t vh[4][4];
#pragma unroll
            for (int g = 0; g < 4; g++) {
                int row = ks * 16 + vRow16;
                uint32_t seg = ((uint32_t)(g * 2 + vEh) ^ (uint32_t)(row & 7)) << 4;
                ldm_x4_t(vh[g][0], vh[g][1], vh[g][2], vh[g][3],
                         stg + 8192 + (uint32_t)row * 128 + seg);
            }
#pragma unroll
            for (int g = 0; g < 4; g++) {
                float* c0 = accO[2 * g];
                float* c1 = accO[2 * g + 1];
                mma_f16(c0[0], c0[1], c0[2], c0[3],
                        pa_h[0], pa_h[1], pa_h[2], pa_h[3], vh[g][0], vh[g][1]);
                mma_f16(c1[0], c1[1], c1[2], c1[3],
                        pa_h[0], pa_h[1], pa_h[2], pa_h[3], vh[g][2], vh[g][3]);
                mma_f16(c0[0], c0[1], c0[2], c0[3],
                        pa_l[0], pa_l[1], pa_l[2], pa_l[3], vh[g][0], vh[g][1]);
                mma_f16(c1[0], c1[1], c1[2], c1[3],
                        pa_l[0], pa_l[1], pa_l[2], pa_l[3], vh[g][2], vh[g][3]);
            }
        }
        __syncthreads();
        if (kt + 2 < NT) issue_kv(kt + 2);
        cp_commit();
    }

    // ---- epilogue (fp16 hi only; O-proj is single-pass) ----
    float inv0 = 1.0f / l0, inv1 = 1.0f / l1;
    const int b = bh >> 4, h = bh & 15;
    const int r1 = q0 + warp * 16 + (lane >> 2);
    const int r2 = r1 + 8;
    size_t t1 = ((size_t)(b * SEQ) + r1) * D_MODEL + h * D_HEAD;
    size_t t2 = ((size_t)(b * SEQ) + r2) * D_MODEL + h * D_HEAD;
#pragma unroll
    for (int t = 0; t < 8; t++) {
        int e = t * 8 + (lane & 3) * 2;
        *(uint32_t*)(ohi + t1 + e) =
            pack_h(__float2half_rn(accO[t][0] * inv0), __float2half_rn(accO[t][1] * inv0));
        *(uint32_t*)(ohi + t2 + e) =
            pack_h(__float2half_rn(accO[t][2] * inv1), __float2half_rn(accO[t][3] * inv1));
    }
}

// ---------------- launch ----------------
extern "C" void kernel_launch(void* const* d_in, const int* in_sizes, int n_in,
                              void* d_out, int out_size) {
    const float* x    = (const float*)d_in[0];
    const float* Wq   = (const float*)d_in[1];
    const float* Wk   = (const float*)d_in[2];
    const float* Wv   = (const float*)d_in[3];
    const float* Wo   = (const float*)d_in[4];
    const float* bo   = (const float*)d_in[5];
    const float* ln1g = (const float*)d_in[6];
    const float* ln1b = (const float*)d_in[7];
    const float* ln2g = (const float*)d_in[8];
    const float* ln2b = (const float*)d_in[9];
    const float* W1   = (const float*)d_in[10];
    const float* b1   = (const float*)d_in[11];
    const float* W2   = (const float*)d_in[12];
    const float* b2   = (const float*)d_in[13];
    float* out = (float*)d_out;

    hf *pWqkvH, *pWqkvL, *pWoH, *pW1H, *pW2H;
    hf *pXnH, *pXnL, *pAtH, *pHnH, *pHnL, *pFfH;
    hf *pQh, *pQl, *pKh, *pVh;
    float *pHid;
    cudaGetSymbolAddress((void**)&pWqkvH, g_WqkvT_hi);
    cudaGetSymbolAddress((void**)&pWqkvL, g_WqkvT_lo);
    cudaGetSymbolAddress((void**)&pWoH, g_WoT_hi);
    cudaGetSymbolAddress((void**)&pW1H, g_W1T_hi);
    cudaGetSymbolAddress((void**)&pW2H, g_W2T_hi);
    cudaGetSymbolAddress((void**)&pXnH, g_xn_hi);
    cudaGetSymbolAddress((void**)&pXnL, g_xn_lo);
    cudaGetSymbolAddress((void**)&pAtH, g_at_hi);
    cudaGetSymbolAddress((void**)&pHnH, g_hn_hi);
    cudaGetSymbolAddress((void**)&pHnL, g_hn_lo);
    cudaGetSymbolAddress((void**)&pFfH, g_ff_hi);
    cudaGetSymbolAddress((void**)&pQh, g_q_hi);
    cudaGetSymbolAddress((void**)&pQl, g_q_lo);
    cudaGetSymbolAddress((void**)&pKh, g_k_hi);
    cudaGetSymbolAddress((void**)&pVh, g_v_hi);
    cudaGetSymbolAddress((void**)&pHid, g_hidden);

    const int SMEM1 = GSTAGES * 2 * 8192;  // 49152 (1-pass)
    const int SMEM3 = GSTAGES * 4 * 8192;  // 98304 (3-pass)
    cudaFuncSetAttribute((gemm_mma<1, 1>), cudaFuncAttributeMaxDynamicSharedMemorySize, SMEM1);
    cudaFuncSetAttribute((gemm_mma<2, 1>), cudaFuncAttributeMaxDynamicSharedMemorySize, SMEM1);
    cudaFuncSetAttribute((gemm_mma<3, 3>), cudaFuncAttributeMaxDynamicSharedMemorySize, SMEM3);
    cudaFuncSetAttribute(attn_mma, cudaFuncAttributeMaxDynamicSharedMemorySize, ATT_SMEM);

    dim3 t328(32, 8);
    transconv_qkv_k<<<dim3(D_MODEL / 32, QKV_N / 32), t328>>>(Wq, Wk, Wv, pWqkvH, pWqkvL);
    transconv_k<<<dim3(D_MODEL / 32, D_MODEL / 32), t328>>>(Wo, pWoH, D_MODEL, D_MODEL);
    transconv_k<<<dim3(D_MODEL / 32, D_FF / 32), t328>>>(W1, pW1H, D_MODEL, D_FF);
    transconv_k<<<dim3(D_FF / 32, D_MODEL / 32), t328>>>(W2, pW2H, D_FF, D_MODEL);

    layernorm_split_k<<<TOKENS, 256>>>(x, ln1g, ln1b, pXnH, pXnL);
    // QKV projection (3-pass, protects scores) -> head-major fp16 q(hi/lo,scaled)/k/v
    gemm_mma<3, 3><<<dim3(QKV_N / 128, TOKENS / 128), 256, SMEM3>>>(
        pXnH, pXnL, pWqkvH, pWqkvL, D_MODEL, QKV_N,
        nullptr, nullptr, nullptr, nullptr,
        pQh, pQl, pKh, pVh);
    // flash attention (fp16 2-pass S and PV + poly exp2) -> fp16
    attn_mma<<<dim3(SEQ / 128, BH), 256, ATT_SMEM>>>(pQh, pQl, pKh, pVh, pAtH);
    // O projection (1-pass) + bias + residual
    gemm_mma<1, 1><<<dim3(D_MODEL / 128, TOKENS / 128), 256, SMEM1>>>(
        pAtH, nullptr, pWoH, nullptr, D_MODEL, D_MODEL, pHid, nullptr, bo, x,
        nullptr, nullptr, nullptr, nullptr);
    layernorm_split_k<<<TOKENS, 256>>>(pHid, ln2g, ln2b, pHnH, pHnL);
    // FF1 (1-pass) + bias + GELU -> fp16
    gemm_mma<2, 1><<<dim3(D_FF / 128, TOKENS / 128), 256, SMEM1>>>(
        pHnH, nullptr, pW1H, nullptr, D_MODEL, D_FF, nullptr, pFfH, b1, nullptr,
        nullptr, nullptr, nullptr, nullptr);
    // FF2 (1-pass) + bias + residual -> out
    gemm_mma<1, 1><<<dim3(D_MODEL / 128, TOKENS / 128), 256, SMEM1>>>(
        pFfH, nullptr, pW2H, nullptr, D_FF, D_MODEL, out, nullptr, b2, pHid,
        nullptr, nullptr, nullptr, nullptr);
}

// round 7
// speedup vs baseline: 5.7961x; 1.3399x over previous
#include <cuda_runtime.h>
#include <cuda_fp16.h>
#include <math.h>
#include <stdint.h>

#define D_MODEL 1024
#define N_HEADS 16
#define D_HEAD 64
#define D_FF 4096
#define SEQ 2048
#define BATCH 2
#define TOKENS (BATCH * SEQ)
#define QKV_N (3 * D_MODEL)
#define BH (BATCH * N_HEADS)

typedef __half hf;

// ---------------- scratch ----------------
__device__ hf g_WqkvT[QKV_N * D_MODEL];
__device__ hf g_WoT[D_MODEL * D_MODEL];
__device__ hf g_W1T[D_FF * D_MODEL];
__device__ hf g_W2T[D_MODEL * D_FF];
__device__ hf g_xn[TOKENS * D_MODEL];
// head-major QKV: [bh][s][64]
__device__ hf g_q[BH * SEQ * D_HEAD];
__device__ hf g_k[BH * SEQ * D_HEAD];
__device__ hf g_v[BH * SEQ * D_HEAD];
__device__ hf g_at[TOKENS * D_MODEL];
__device__ float g_hidden[TOKENS * D_MODEL];
__device__ hf g_hn[TOKENS * D_MODEL];
__device__ hf g_ff[(size_t)TOKENS * D_FF];

__device__ __forceinline__ uint32_t smem_to_u32(const void* p) {
    uint32_t a;
    asm("{ .reg .u64 t; cvta.to.shared.u64 t, %1; cvt.u32.u64 %0, t; }"
        : "=r"(a) : "l"(p));
    return a;
}
__device__ __forceinline__ void cp_async16(uint32_t smem, const void* gmem) {
    asm volatile("cp.async.cg.shared.global [%0], [%1], 16;" :: "r"(smem), "l"(gmem));
}
__device__ __forceinline__ void cp_commit() { asm volatile("cp.async.commit_group;"); }
template <int N>
__device__ __forceinline__ void cp_wait() { asm volatile("cp.async.wait_group %0;" :: "n"(N)); }

__device__ __forceinline__ void ldm_x4(uint32_t& r0, uint32_t& r1, uint32_t& r2, uint32_t& r3,
                                       uint32_t addr) {
    asm volatile("ldmatrix.sync.aligned.m8n8.x4.shared.b16 {%0,%1,%2,%3}, [%4];"
                 : "=r"(r0), "=r"(r1), "=r"(r2), "=r"(r3) : "r"(addr));
}
__device__ __forceinline__ void ldm_x4_t(uint32_t& r0, uint32_t& r1, uint32_t& r2, uint32_t& r3,
                                         uint32_t addr) {
    asm volatile("ldmatrix.sync.aligned.m8n8.x4.trans.shared.b16 {%0,%1,%2,%3}, [%4];"
                 : "=r"(r0), "=r"(r1), "=r"(r2), "=r"(r3) : "r"(addr));
}
__device__ __forceinline__ void mma_f16(float& c0, float& c1, float& c2, float& c3,
                                        uint32_t a0, uint32_t a1, uint32_t a2, uint32_t a3,
                                        uint32_t b0, uint32_t b1) {
    asm volatile(
        "mma.sync.aligned.m16n8k16.row.col.f32.f16.f16.f32 "
        "{%0,%1,%2,%3}, {%4,%5,%6,%7}, {%8,%9}, {%0,%1,%2,%3};"
        : "+f"(c0), "+f"(c1), "+f"(c2), "+f"(c3)
        : "r"(a0), "r"(a1), "r"(a2), "r"(a3), "r"(b0), "r"(b1));
}

__device__ __forceinline__ float gelu_exact(float v) {
    return 0.5f * v * (1.0f + erff(v * 0.70710678118654752440f));
}
// FMA-pipe exp2 (no MUFU). y expected <= 0.
__device__ __forceinline__ float exp2_poly(float y) {
    float t = fmaxf(y, -126.0f);
    float fn = t + 12582912.0f;
    int n = __float_as_int(fn) - 0x4B400000;
    float f = t - (fn - 12582912.0f);
    float p = fmaf(0.0013333558f, f, 0.0096181291f);
    p = fmaf(p, f, 0.0555041087f);
    p = fmaf(p, f, 0.2402265070f);
    p = fmaf(p, f, 0.6931471806f);
    p = fmaf(p, f, 1.0f);
    return __int_as_float(__float_as_int(p) + (n << 23));
}
__device__ __forceinline__ uint32_t pack_h(hf a, hf b) {
    __half2 p = __halves2half2(a, b);
    return *(uint32_t*)&p;
}
__device__ __forceinline__ uint32_t pack_hf(float a, float b) {
    return pack_h(__float2half_rn(a), __float2half_rn(b));
}

#define QSCALE 0.18033688011f  // 0.125 * log2(e)

// ---------------- weight transpose -> fp16 ----------------
__global__ void transconv_k(const float* __restrict__ src, hf* __restrict__ d,
                            int K, int N) {
    __shared__ float t[32][33];
    int tx = threadIdx.x, ty = threadIdx.y;
    int k0 = blockIdx.x * 32, n0 = blockIdx.y * 32;
#pragma unroll
    for (int i = 0; i < 4; i++)
        t[ty + i * 8][tx] = src[(size_t)(k0 + ty + i * 8) * N + n0 + tx];
    __syncthreads();
#pragma unroll
    for (int i = 0; i < 4; i++) {
        size_t o = (size_t)(n0 + ty + i * 8) * K + k0 + tx;
        d[o] = __float2half_rn(t[tx][ty + i * 8]);
    }
}

__global__ void transconv_qkv_k(const float* __restrict__ Wq, const float* __restrict__ Wk,
                                const float* __restrict__ Wv, hf* __restrict__ d) {
    __shared__ float t[32][33];
    int tx = threadIdx.x, ty = threadIdx.y;
    int k0 = blockIdx.x * 32, n0 = blockIdx.y * 32;
    int w = n0 >> 10, h = (n0 >> 6) & 15, e0 = n0 & 63;
    const float* W = (w == 0) ? Wq : (w == 1) ? Wk : Wv;
    const float* src = W + (size_t)h * D_MODEL * D_HEAD;
#pragma unroll
    for (int i = 0; i < 4; i++)
        t[ty + i * 8][tx] = src[(size_t)(k0 + ty + i * 8) * 64 + e0 + tx];
    __syncthreads();
#pragma unroll
    for (int i = 0; i < 4; i++) {
        size_t o = (size_t)(n0 + ty + i * 8) * D_MODEL + k0 + tx;
        d[o] = __float2half_rn(t[tx][ty + i * 8]);
    }
}

// ---------------- LayerNorm -> fp16 ----------------
__global__ __launch_bounds__(256) void layernorm_k(const float* __restrict__ x,
                                                   const float* __restrict__ g,
                                                   const float* __restrict__ b,
                                                   hf* __restrict__ o) {
    __shared__ float red[2][8];
    int row = blockIdx.x;
    int tid = threadIdx.x;
    const float4* xr = (const float4*)(x + (size_t)row * D_MODEL);
    float4 v = xr[tid];
    float s = v.x + v.y + v.z + v.w;
    float ss = v.x * v.x + v.y * v.y + v.z * v.z + v.w * v.w;
#pragma unroll
    for (int of = 16; of > 0; of >>= 1) {
        s += __shfl_xor_sync(0xffffffffu, s, of);
        ss += __shfl_xor_sync(0xffffffffu, ss, of);
    }
    int w = tid >> 5, l = tid & 31;
    if (l == 0) { red[0][w] = s; red[1][w] = ss; }
    __syncthreads();
    if (tid < 32) {
        s = (l < 8) ? red[0][l] : 0.f;
        ss = (l < 8) ? red[1][l] : 0.f;
#pragma unroll
        for (int of = 4; of > 0; of >>= 1) {
            s += __shfl_xor_sync(0xffffffffu, s, of);
            ss += __shfl_xor_sync(0xffffffffu, ss, of);
        }
        if (l == 0) { red[0][0] = s; red[1][0] = ss; }
    }
    __syncthreads();
    float mu = red[0][0] * (1.0f / D_MODEL);
    float var = red[1][0] * (1.0f / D_MODEL) - mu * mu;
    float r = rsqrtf(var + 1e-5f);
    float4 gv = ((const float4*)g)[tid];
    float4 bv = ((const float4*)b)[tid];
    float o0 = (v.x - mu) * r * gv.x + bv.x;
    float o1 = (v.y - mu) * r * gv.y + bv.y;
    float o2 = (v.z - mu) * r * gv.z + bv.z;
    float o3 = (v.w - mu) * r * gv.w + bv.w;
    size_t base = (size_t)row * D_MODEL + tid * 4;
    *(uint32_t*)(o + base) = pack_hf(o0, o1);
    *(uint32_t*)(o + base + 2) = pack_hf(o2, o3);
}

// ---------------- fp16 HMMA GEMM, 1 pass ----------------
// EPI: 1 bias+residual fp32 C; 2 bias+GELU fp16; 3 QKV head-major (Q scaled)
#define GSTAGES 3
#define STAGE_BYTES 16384

template <int EPI>
__global__ __launch_bounds__(256, 1) void gemm_mma(
    const hf* __restrict__ A, const hf* __restrict__ B,
    int K, int N,
    float* __restrict__ C, hf* __restrict__ Ch,
    const float* __restrict__ bias, const float* __restrict__ res,
    hf* __restrict__ Qd, hf* __restrict__ Kd, hf* __restrict__ Vd) {
    extern __shared__ char smem[];
    const uint32_t sb = smem_to_u32(smem);
    const int tid = threadIdx.x;
    const int lane = tid & 31;
    const int warp = tid >> 5;
    const int warpM = warp & 3, warpN = warp >> 2;
    const int bn = blockIdx.x * 128, bm = blockIdx.y * 128;

    const size_t rstrideB = (size_t)K * 2;
    const char* gA = (const char*)A + (size_t)bm * K * 2;
    const char* gB = (const char*)B + (size_t)bn * K * 2;

    const int NK = K >> 5;

    auto issue_chunk = [&](int c) {
        const uint32_t stg = sb + (uint32_t)(c % GSTAGES) * STAGE_BYTES;
        const size_t goff = (size_t)c * 64;
#pragma unroll
        for (int j = 0; j < 4; j++) {
            int id = tid + j * 256;
            int arr = id >> 9;
            int row = (id >> 2) & 127;
            int seg = id & 3;
            const char* src = (arr ? gB : gA) + goff + (size_t)row * rstrideB + seg * 16;
            uint32_t dst = stg + (uint32_t)arr * 8192 + (uint32_t)row * 64 +
                           ((uint32_t)(seg ^ ((row >> 1) & 3)) << 4);
            cp_async16(dst, src);
        }
    };

    const int aRow = warpM * 32 + (lane & 15);
    const int aKh = lane >> 4;
    const uint32_t aSw = (aRow >> 1) & 3;
    const uint32_t aRowB = (uint32_t)aRow * 64;
    const int bRowBase = warpN * 64 + (lane & 15);
    const int bKh = lane >> 4;
    const uint32_t bSw = (bRowBase >> 1) & 3;
    const uint32_t bRowB = (uint32_t)bRowBase * 64;

    float acc[2][8][4];
#pragma unroll
    for (int i = 0; i < 2; i++)
#pragma unroll
        for (int j = 0; j < 8; j++)
#pragma unroll
            for (int q = 0; q < 4; q++) acc[i][j][q] = 0.f;

#pragma unroll
    for (int s = 0; s < GSTAGES - 1; s++) { issue_chunk(s); cp_commit(); }

    for (int c = 0; c < NK; c++) {
        cp_wait<GSTAGES - 2>();
        __syncthreads();
        const uint32_t stg = sb + (uint32_t)(c % GSTAGES) * STAGE_BYTES;
#pragma unroll
        for (int k16 = 0; k16 < 2; k16++) {
            const uint32_t aSeg = ((uint32_t)(k16 * 2 + aKh) ^ aSw) << 4;
            const uint32_t bSeg = ((uint32_t)(k16 * 2 + bKh) ^ bSw) << 4;
            uint32_t ah[2][4], bh[4][4];
#pragma unroll
            for (int i = 0; i < 2; i++)
                ldm_x4(ah[i][0], ah[i][1], ah[i][2], ah[i][3],
                       stg + aRowB + (uint32_t)i * 16 * 64 + aSeg);
#pragma unroll
            for (int t = 0; t < 4; t++)
                ldm_x4(bh[t][0], bh[t][1], bh[t][2], bh[t][3],
                       stg + 8192 + bRowB + (uint32_t)t * 16 * 64 + bSeg);
#pragma unroll
            for (int i = 0; i < 2; i++)
#pragma unroll
                for (int t = 0; t < 4; t++) {
                    float* c0 = acc[i][2 * t];
                    float* c1 = acc[i][2 * t + 1];
                    mma_f16(c0[0], c0[1], c0[2], c0[3],
                            ah[i][0], ah[i][1], ah[i][2], ah[i][3], bh[t][0], bh[t][2]);
                    mma_f16(c1[0], c1[1], c1[2], c1[3],
                            ah[i][0], ah[i][1], ah[i][2], ah[i][3], bh[t][1], bh[t][3]);
                }
        }
        __syncthreads();
        if (c + GSTAGES - 1 < NK) issue_chunk(c + GSTAGES - 1);
        cp_commit();
    }

    const int gRow = lane >> 2;
    const int gCol = (lane & 3) * 2;
#pragma unroll
    for (int i = 0; i < 2; i++) {
#pragma unroll
        for (int j = 0; j < 8; j++) {
            int row = bm + warpM * 32 + i * 16 + gRow;
            int col = bn + warpN * 64 + j * 8 + gCol;
#pragma unroll
            for (int half = 0; half < 2; half++) {
                int r = row + half * 8;
                float v0 = acc[i][j][half * 2 + 0];
                float v1 = acc[i][j][half * 2 + 1];
                if (EPI == 1 || EPI == 2) {
                    float2 bb = *(const float2*)(bias + col);
                    v0 += bb.x; v1 += bb.y;
                }
                if (EPI == 1) {
                    float2 rv = *(const float2*)(res + (size_t)r * N + col);
                    v0 += rv.x; v1 += rv.y;
                    *(float2*)(C + (size_t)r * N + col) = make_float2(v0, v1);
                } else if (EPI == 2) {
                    v0 = gelu_exact(v0); v1 = gelu_exact(v1);
                    *(uint32_t*)(Ch + (size_t)r * N + col) = pack_hf(v0, v1);
                } else if (EPI == 3) {
                    int which = col >> 10;
                    int h = (col >> 6) & 15;
                    int e = col & 63;
                    int bb = r >> 11, s = r & 2047;
                    size_t o = (((size_t)(bb * 16 + h)) * SEQ + s) * D_HEAD + e;
                    if (which == 0) { v0 *= QSCALE; v1 *= QSCALE; }
                    hf* dst = (which == 0) ? Qd : (which == 1) ? Kd : Vd;
                    *(uint32_t*)(dst + o) = pack_hf(v0, v1);
                }
            }
        }
    }
}

// ---------------- fp16 HMMA flash attention, 1-pass S and PV ----------------
// smem: Q 0 (16KB); stage s at 16384 + s*16384: K 0, V 8192
#define ATT_SMEM (16384 + 2 * 16384)

__global__ __launch_bounds__(256, 1) void attn_mma(
    const hf* __restrict__ q_g, const hf* __restrict__ k_g, const hf* __restrict__ v_g,
    hf* __restrict__ oh) {
    extern __shared__ char smem[];
    const uint32_t sb = smem_to_u32(smem);
    const int tid = threadIdx.x;
    const int lane = tid & 31;
    const int warp = tid >> 5;
    const int bh = blockIdx.y;
    const int q0 = blockIdx.x * 128;

    const char* qb = (const char*)(q_g + ((size_t)bh * SEQ + q0) * D_HEAD);
    const char* kb = (const char*)(k_g + (size_t)bh * SEQ * D_HEAD);
    const char* vb = (const char*)(v_g + (size_t)bh * SEQ * D_HEAD);

    {
#pragma unroll
        for (int j = 0; j < 4; j++) {
            int id = tid + j * 256;
            int row = (id >> 3) & 127, seg = id & 7;
            uint32_t dst = sb + (uint32_t)row * 128 + ((uint32_t)(seg ^ (row & 7)) << 4);
            cp_async16(dst, qb + (size_t)row * 128 + seg * 16);
        }
    }
    auto issue_kv = [&](int kt) {
        const uint32_t stg = sb + 16384 + (uint32_t)(kt & 1) * 16384;
        const size_t gof = (size_t)kt * 64 * 128;
#pragma unroll
        for (int j = 0; j < 4; j++) {
            int id = tid + j * 256;
            int arr = id >> 9, row = (id >> 3) & 63, seg = id & 7;
            const char* src = ((arr == 0) ? kb : vb) + gof + (size_t)row * 128 + seg * 16;
            uint32_t dst = stg + (uint32_t)arr * 8192 + (uint32_t)row * 128 +
                           ((uint32_t)(seg ^ (row & 7)) << 4);
            cp_async16(dst, src);
        }
    };

    issue_kv(0);
    cp_commit();
    issue_kv(1);
    cp_commit();

    float accO[8][4];
#pragma unroll
    for (int t = 0; t < 8; t++)
#pragma unroll
        for (int q = 0; q < 4; q++) accO[t][q] = 0.f;
    float m0 = -1e30f, m1 = -1e30f, l0 = 0.f, l1 = 0.f;

    uint32_t qf[4][4];
    const int qRow = warp * 16 + (lane & 15);
    const uint32_t qSw = (uint32_t)(qRow & 7);
    const uint32_t qRowB = (uint32_t)qRow * 128;

    const int NT = SEQ / 64;
    for (int kt = 0; kt < NT; kt++) {
        cp_wait<1>();
        __syncthreads();
        if (kt == 0) {
#pragma unroll
            for (int ks = 0; ks < 4; ks++) {
                uint32_t seg = ((uint32_t)(ks * 2 + (lane >> 4)) ^ qSw) << 4;
                ldm_x4(qf[ks][0], qf[ks][1], qf[ks][2], qf[ks][3], sb + qRowB + seg);
            }
        }
        const uint32_t stg = sb + 16384 + (uint32_t)(kt & 1) * 16384;

        // ---- S = Q K^T (1 pass) ----
        float S[8][4];
#pragma unroll
        for (int t = 0; t < 8; t++)
#pragma unroll
            for (int q = 0; q < 4; q++) S[t][q] = 0.f;

        const int nRow = lane & 15;
        const int kh4 = lane >> 4;
#pragma unroll
        for (int ks = 0; ks < 4; ks++) {
            uint32_t kh[4][4];
#pragma unroll
            for (int g = 0; g < 4; g++) {
                int row = g * 16 + nRow;
                uint32_t seg = ((uint32_t)(ks * 2 + kh4) ^ (uint32_t)(row & 7)) << 4;
                ldm_x4(kh[g][0], kh[g][1], kh[g][2], kh[g][3],
                       stg + (uint32_t)row * 128 + seg);
            }
#pragma unroll
            for (int g = 0; g < 4; g++) {
                float* c0 = S[2 * g];
                float* c1 = S[2 * g + 1];
                mma_f16(c0[0], c0[1], c0[2], c0[3],
                        qf[ks][0], qf[ks][1], qf[ks][2], qf[ks][3], kh[g][0], kh[g][2]);
                mma_f16(c1[0], c1[1], c1[2], c1[3],
                        qf[ks][0], qf[ks][1], qf[ks][2], qf[ks][3], kh[g][1], kh[g][3]);
            }
        }

        // ---- online softmax (FMA pipe, base-2 domain) ----
        float mx0 = S[0][0], mx1 = S[0][2];
#pragma unroll
        for (int t = 0; t < 8; t++) {
            mx0 = fmaxf(mx0, fmaxf(S[t][0], S[t][1]));
            mx1 = fmaxf(mx1, fmaxf(S[t][2], S[t][3]));
        }
        mx0 = fmaxf(mx0, __shfl_xor_sync(0xffffffffu, mx0, 1));
        mx0 = fmaxf(mx0, __shfl_xor_sync(0xffffffffu, mx0, 2));
        mx1 = fmaxf(mx1, __shfl_xor_sync(0xffffffffu, mx1, 1));
        mx1 = fmaxf(mx1, __shfl_xor_sync(0xffffffffu, mx1, 2));
        float mn0 = fmaxf(m0, mx0), mn1 = fmaxf(m1, mx1);
        float cr0 = exp2_poly(m0 - mn0), cr1 = exp2_poly(m1 - mn1);
        m0 = mn0; m1 = mn1;
        float sum0 = 0.f, sum1 = 0.f;
#pragma unroll
        for (int t = 0; t < 8; t++) {
            S[t][0] = exp2_poly(S[t][0] - mn0);
            S[t][1] = exp2_poly(S[t][1] - mn0);
            S[t][2] = exp2_poly(S[t][2] - mn1);
            S[t][3] = exp2_poly(S[t][3] - mn1);
            sum0 += S[t][0] + S[t][1];
            sum1 += S[t][2] + S[t][3];
        }
        sum0 += __shfl_xor_sync(0xffffffffu, sum0, 1);
        sum0 += __shfl_xor_sync(0xffffffffu, sum0, 2);
        sum1 += __shfl_xor_sync(0xffffffffu, sum1, 1);
        sum1 += __shfl_xor_sync(0xffffffffu, sum1, 2);
        l0 = l0 * cr0 + sum0;
        l1 = l1 * cr1 + sum1;
#pragma unroll
        for (int t = 0; t < 8; t++) {
            accO[t][0] *= cr0; accO[t][1] *= cr0;
            accO[t][2] *= cr1; accO[t][3] *= cr1;
        }

        // ---- O += P V (1 pass) ----
        const int vRow16 = lane & 15;
        const int vEh = lane >> 4;
#pragma unroll
        for (int ks = 0; ks < 4; ks++) {
            uint32_t pa[4];
            pa[0] = pack_hf(S[2 * ks][0], S[2 * ks][1]);
            pa[1] = pack_hf(S[2 * ks][2], S[2 * ks][3]);
            pa[2] = pack_hf(S[2 * ks + 1][0], S[2 * ks + 1][1]);
            pa[3] = pack_hf(S[2 * ks + 1][2], S[2 * ks + 1][3]);

            uint32_t vh[4][4];
#pragma unroll
            for (int g = 0; g < 4; g++) {
                int row = ks * 16 + vRow16;
                uint32_t seg = ((uint32_t)(g * 2 + vEh) ^ (uint32_t)(row & 7)) << 4;
                ldm_x4_t(vh[g][0], vh[g][1], vh[g][2], vh[g][3],
                         stg + 8192 + (uint32_t)row * 128 + seg);
            }
#pragma unroll
            for (int g = 0; g < 4; g++) {
                float* c0 = accO[2 * g];
                float* c1 = accO[2 * g + 1];
                mma_f16(c0[0], c0[1], c0[2], c0[3],
                        pa[0], pa[1], pa[2], pa[3], vh[g][0], vh[g][1]);
                mma_f16(c1[0], c1[1], c1[2], c1[3],
                        pa[0], pa[1], pa[2], pa[3], vh[g][2], vh[g][3]);
            }
        }
        __syncthreads();
        if (kt + 2 < NT) issue_kv(kt + 2);
        cp_commit();
    }

    // ---- epilogue ----
    float inv0 = 1.0f / l0, inv1 = 1.0f / l1;
    const int b = bh >> 4, h = bh & 15;
    const int r1 = q0 + warp * 16 + (lane >> 2);
    const int r2 = r1 + 8;
    size_t t1 = ((size_t)(b * SEQ) + r1) * D_MODEL + h * D_HEAD;
    size_t t2 = ((size_t)(b * SEQ) + r2) * D_MODEL + h * D_HEAD;
#pragma unroll
    for (int t = 0; t < 8; t++) {
        int e = t * 8 + (lane & 3) * 2;
        *(uint32_t*)(oh + t1 + e) = pack_hf(accO[t][0] * inv0, accO[t][1] * inv0);
        *(uint32_t*)(oh + t2 + e) = pack_hf(accO[t][2] * inv1, accO[t][3] * inv1);
    }
}

// ---------------- launch ----------------
extern "C" void kernel_launch(void* const* d_in, const int* in_sizes, int n_in,
                              void* d_out, int out_size) {
    const float* x    = (const float*)d_in[0];
    const float* Wq   = (const float*)d_in[1];
    const float* Wk   = (const float*)d_in[2];
    const float* Wv   = (const float*)d_in[3];
    const float* Wo   = (const float*)d_in[4];
    const float* bo   = (const float*)d_in[5];
    const float* ln1g = (const float*)d_in[6];
    const float* ln1b = (const float*)d_in[7];
    const float* ln2g = (const float*)d_in[8];
    const float* ln2b = (const float*)d_in[9];
    const float* W1   = (const float*)d_in[10];
    const float* b1   = (const float*)d_in[11];
    const float* W2   = (const float*)d_in[12];
    const float* b2   = (const float*)d_in[13];
    float* out = (float*)d_out;

    hf *pWqkv, *pWo, *pW1, *pW2, *pXn, *pAt, *pHn, *pFf, *pQ, *pK, *pV;
    float* pHid;
    cudaGetSymbolAddress((void**)&pWqkv, g_WqkvT);
    cudaGetSymbolAddress((void**)&pWo, g_WoT);
    cudaGetSymbolAddress((void**)&pW1, g_W1T);
    cudaGetSymbolAddress((void**)&pW2, g_W2T);
    cudaGetSymbolAddress((void**)&pXn, g_xn);
    cudaGetSymbolAddress((void**)&pAt, g_at);
    cudaGetSymbolAddress((void**)&pHn, g_hn);
    cudaGetSymbolAddress((void**)&pFf, g_ff);
    cudaGetSymbolAddress((void**)&pQ, g_q);
    cudaGetSymbolAddress((void**)&pK, g_k);
    cudaGetSymbolAddress((void**)&pV, g_v);
    cudaGetSymbolAddress((void**)&pHid, g_hidden);

    const int GEMM_SMEM = GSTAGES * STAGE_BYTES;  // 49152
    cudaFuncSetAttribute(gemm_mma<1>, cudaFuncAttributeMaxDynamicSharedMemorySize, GEMM_SMEM);
    cudaFuncSetAttribute(gemm_mma<2>, cudaFuncAttributeMaxDynamicSharedMemorySize, GEMM_SMEM);
    cudaFuncSetAttribute(gemm_mma<3>, cudaFuncAttributeMaxDynamicSharedMemorySize, GEMM_SMEM);
    cudaFuncSetAttribute(attn_mma, cudaFuncAttributeMaxDynamicSharedMemorySize, ATT_SMEM);

    dim3 t328(32, 8);
    transconv_qkv_k<<<dim3(D_MODEL / 32, QKV_N / 32), t328>>>(Wq, Wk, Wv, pWqkv);
    transconv_k<<<dim3(D_MODEL / 32, D_MODEL / 32), t328>>>(Wo, pWo, D_MODEL, D_MODEL);
    transconv_k<<<dim3(D_MODEL / 32, D_FF / 32), t328>>>(W1, pW1, D_MODEL, D_FF);
    transconv_k<<<dim3(D_FF / 32, D_MODEL / 32), t328>>>(W2, pW2, D_FF, D_MODEL);

    layernorm_k<<<TOKENS, 256>>>(x, ln1g, ln1b, pXn);
    // QKV projection (1-pass) -> head-major fp16 q(scaled)/k/v
    gemm_mma<3><<<dim3(QKV_N / 128, TOKENS / 128), 256, GEMM_SMEM>>>(
        pXn, pWqkv, D_MODEL, QKV_N, nullptr, nullptr, nullptr, nullptr, pQ, pK, pV);
    // flash attention (1-pass S, 1-pass PV, poly exp2)
    attn_mma<<<dim3(SEQ / 128, BH), 256, ATT_SMEM>>>(pQ, pK, pV, pAt);
    // O projection (1-pass) + bias + residual
    gemm_mma<1><<<dim3(D_MODEL / 128, TOKENS / 128), 256, GEMM_SMEM>>>(
        pAt, pWo, D_MODEL, D_MODEL, pHid, nullptr, bo, x, nullptr, nullptr, nullptr);
    layernorm_k<<<TOKENS, 256>>>(pHid, ln2g, ln2b, pHn);
    // FF1 (1-pass) + bias + GELU
    gemm_mma<2><<<dim3(D_FF / 128, TOKENS / 128), 256, GEMM_SMEM>>>(
        pHn, pW1, D_MODEL, D_FF, nullptr, pFf, b1, nullptr, nullptr, nullptr, nullptr);
    // FF2 (1-pass) + bias + residual -> out
    gemm_mma<1><<<dim3(D_MODEL / 128, TOKENS / 128), 256, GEMM_SMEM>>>(
        pFf, pW2, D_FF, D_MODEL, out, nullptr, b2, pHid, nullptr, nullptr, nullptr);
}

// round 8
// speedup vs baseline: 6.4091x; 1.1058x over previous
#include <cuda_runtime.h>
#include <cuda_fp16.h>
#include <math.h>
#include <stdint.h>

#define D_MODEL 1024
#define N_HEADS 16
#define D_HEAD 64
#define D_FF 4096
#define SEQ 2048
#define BATCH 2
#define TOKENS (BATCH * SEQ)
#define QKV_N (3 * D_MODEL)
#define BH (BATCH * N_HEADS)

typedef __half hf;

// ---------------- scratch ----------------
__device__ hf g_WqkvT[QKV_N * D_MODEL];
__device__ hf g_WoT[D_MODEL * D_MODEL];
__device__ hf g_W1T[D_FF * D_MODEL];
__device__ hf g_W2T[D_MODEL * D_FF];
__device__ hf g_xn[TOKENS * D_MODEL];
// head-major QKV: [bh][s][64]
__device__ hf g_q[BH * SEQ * D_HEAD];
__device__ hf g_k[BH * SEQ * D_HEAD];
__device__ hf g_v[BH * SEQ * D_HEAD];
__device__ hf g_at[TOKENS * D_MODEL];
__device__ float g_hidden[TOKENS * D_MODEL];
__device__ hf g_hn[TOKENS * D_MODEL];
__device__ hf g_ff[(size_t)TOKENS * D_FF];

__device__ __forceinline__ uint32_t smem_to_u32(const void* p) {
    uint32_t a;
    asm("{ .reg .u64 t; cvta.to.shared.u64 t, %1; cvt.u32.u64 %0, t; }"
        : "=r"(a) : "l"(p));
    return a;
}
__device__ __forceinline__ void cp_async16(uint32_t smem, const void* gmem) {
    asm volatile("cp.async.cg.shared.global [%0], [%1], 16;" :: "r"(smem), "l"(gmem));
}
__device__ __forceinline__ void cp_commit() { asm volatile("cp.async.commit_group;"); }
template <int N>
__device__ __forceinline__ void cp_wait() { asm volatile("cp.async.wait_group %0;" :: "n"(N)); }

__device__ __forceinline__ void ldm_x4(uint32_t& r0, uint32_t& r1, uint32_t& r2, uint32_t& r3,
                                       uint32_t addr) {
    asm volatile("ldmatrix.sync.aligned.m8n8.x4.shared.b16 {%0,%1,%2,%3}, [%4];"
                 : "=r"(r0), "=r"(r1), "=r"(r2), "=r"(r3) : "r"(addr));
}
__device__ __forceinline__ void ldm_x4_t(uint32_t& r0, uint32_t& r1, uint32_t& r2, uint32_t& r3,
                                         uint32_t addr) {
    asm volatile("ldmatrix.sync.aligned.m8n8.x4.trans.shared.b16 {%0,%1,%2,%3}, [%4];"
                 : "=r"(r0), "=r"(r1), "=r"(r2), "=r"(r3) : "r"(addr));
}
__device__ __forceinline__ void mma_f16(float& c0, float& c1, float& c2, float& c3,
                                        uint32_t a0, uint32_t a1, uint32_t a2, uint32_t a3,
                                        uint32_t b0, uint32_t b1) {
    asm volatile(
        "mma.sync.aligned.m16n8k16.row.col.f32.f16.f16.f32 "
        "{%0,%1,%2,%3}, {%4,%5,%6,%7}, {%8,%9}, {%0,%1,%2,%3};"
        : "+f"(c0), "+f"(c1), "+f"(c2), "+f"(c3)
        : "r"(a0), "r"(a1), "r"(a2), "r"(a3), "r"(b0), "r"(b1));
}

__device__ __forceinline__ float gelu_exact(float v) {
    return 0.5f * v * (1.0f + erff(v * 0.70710678118654752440f));
}

// ---- packed f32x2 helpers (sm_100+ base PTX) ----
__device__ __forceinline__ uint64_t pk2(float a, float b) {
    uint64_t r; asm("mov.b64 %0, {%1, %2};" : "=l"(r) : "f"(a), "f"(b)); return r;
}
__device__ __forceinline__ void upk2(uint64_t v, float& a, float& b) {
    asm("mov.b64 {%0, %1}, %2;" : "=f"(a), "=f"(b) : "l"(v));
}
__device__ __forceinline__ uint64_t add2_(uint64_t a, uint64_t b) {
    uint64_t r; asm("add.rn.f32x2 %0, %1, %2;" : "=l"(r) : "l"(a), "l"(b)); return r;
}
__device__ __forceinline__ uint64_t fma2_(uint64_t a, uint64_t b, uint64_t c) {
    uint64_t r; asm("fma.rn.f32x2 %0, %1, %2, %3;" : "=l"(r) : "l"(a), "l"(b), "l"(c)); return r;
}
// exp2 of two values at once, pure FMA/ALU pipes (no MUFU). inputs expected <= 0.
__device__ __forceinline__ void exp2_pair(float& x0, float& x1) {
    float t0 = fmaxf(x0, -126.0f), t1 = fmaxf(x1, -126.0f);
    uint64_t t = pk2(t0, t1);
    uint64_t fn = add2_(t, pk2(12582912.0f, 12582912.0f));
    float fn0, fn1; upk2(fn, fn0, fn1);
    int n0 = __float_as_int(fn0) - 0x4B400000;
    int n1 = __float_as_int(fn1) - 0x4B400000;
    uint64_t fm = add2_(fn, pk2(-12582912.0f, -12582912.0f));
    uint64_t f = fma2_(fm, pk2(-1.0f, -1.0f), t);  // f = t - (fn - magic)
    uint64_t p = pk2(0.0013333558f, 0.0013333558f);
    p = fma2_(p, f, pk2(0.0096181291f, 0.0096181291f));
    p = fma2_(p, f, pk2(0.0555041087f, 0.0555041087f));
    p = fma2_(p, f, pk2(0.2402265070f, 0.2402265070f));
    p = fma2_(p, f, pk2(0.6931471806f, 0.6931471806f));
    p = fma2_(p, f, pk2(1.0f, 1.0f));
    float p0, p1; upk2(p, p0, p1);
    x0 = __int_as_float(__float_as_int(p0) + (n0 << 23));
    x1 = __int_as_float(__float_as_int(p1) + (n1 << 23));
}

__device__ __forceinline__ uint32_t pack_h(hf a, hf b) {
    __half2 p = __halves2half2(a, b);
    return *(uint32_t*)&p;
}
__device__ __forceinline__ uint32_t pack_hf(float a, float b) {
    return pack_h(__float2half_rn(a), __float2half_rn(b));
}

#define QSCALE 0.18033688011f  // 0.125 * log2(e)

// ---------------- weight transpose -> fp16 ----------------
__global__ void transconv_k(const float* __restrict__ src, hf* __restrict__ d,
                            int K, int N) {
    __shared__ float t[32][33];
    int tx = threadIdx.x, ty = threadIdx.y;
    int k0 = blockIdx.x * 32, n0 = blockIdx.y * 32;
#pragma unroll
    for (int i = 0; i < 4; i++)
        t[ty + i * 8][tx] = src[(size_t)(k0 + ty + i * 8) * N + n0 + tx];
    __syncthreads();
#pragma unroll
    for (int i = 0; i < 4; i++) {
        size_t o = (size_t)(n0 + ty + i * 8) * K + k0 + tx;
        d[o] = __float2half_rn(t[tx][ty + i * 8]);
    }
}

__global__ void transconv_qkv_k(const float* __restrict__ Wq, const float* __restrict__ Wk,
                                const float* __restrict__ Wv, hf* __restrict__ d) {
    __shared__ float t[32][33];
    int tx = threadIdx.x, ty = threadIdx.y;
    int k0 = blockIdx.x * 32, n0 = blockIdx.y * 32;
    int w = n0 >> 10, h = (n0 >> 6) & 15, e0 = n0 & 63;
    const float* W = (w == 0) ? Wq : (w == 1) ? Wk : Wv;
    const float* src = W + (size_t)h * D_MODEL * D_HEAD;
#pragma unroll
    for (int i = 0; i < 4; i++)
        t[ty + i * 8][tx] = src[(size_t)(k0 + ty + i * 8) * 64 + e0 + tx];
    __syncthreads();
#pragma unroll
    for (int i = 0; i < 4; i++) {
        size_t o = (size_t)(n0 + ty + i * 8) * D_MODEL + k0 + tx;
        d[o] = __float2half_rn(t[tx][ty + i * 8]);
    }
}

// ---------------- LayerNorm -> fp16 ----------------
__global__ __launch_bounds__(256) void layernorm_k(const float* __restrict__ x,
                                                   const float* __restrict__ g,
                                                   const float* __restrict__ b,
                                                   hf* __restrict__ o) {
    __shared__ float red[2][8];
    int row = blockIdx.x;
    int tid = threadIdx.x;
    const float4* xr = (const float4*)(x + (size_t)row * D_MODEL);
    float4 v = xr[tid];
    float s = v.x + v.y + v.z + v.w;
    float ss = v.x * v.x + v.y * v.y + v.z * v.z + v.w * v.w;
#pragma unroll
    for (int of = 16; of > 0; of >>= 1) {
        s += __shfl_xor_sync(0xffffffffu, s, of);
        ss += __shfl_xor_sync(0xffffffffu, ss, of);
    }
    int w = tid >> 5, l = tid & 31;
    if (l == 0) { red[0][w] = s; red[1][w] = ss; }
    __syncthreads();
    if (tid < 32) {
        s = (l < 8) ? red[0][l] : 0.f;
        ss = (l < 8) ? red[1][l] : 0.f;
#pragma unroll
        for (int of = 4; of > 0; of >>= 1) {
            s += __shfl_xor_sync(0xffffffffu, s, of);
            ss += __shfl_xor_sync(0xffffffffu, ss, of);
        }
        if (l == 0) { red[0][0] = s; red[1][0] = ss; }
    }
    __syncthreads();
    float mu = red[0][0] * (1.0f / D_MODEL);
    float var = red[1][0] * (1.0f / D_MODEL) - mu * mu;
    float r = rsqrtf(var + 1e-5f);
    float4 gv = ((const float4*)g)[tid];
    float4 bv = ((const float4*)b)[tid];
    float o0 = (v.x - mu) * r * gv.x + bv.x;
    float o1 = (v.y - mu) * r * gv.y + bv.y;
    float o2 = (v.z - mu) * r * gv.z + bv.z;
    float o3 = (v.w - mu) * r * gv.w + bv.w;
    size_t base = (size_t)row * D_MODEL + tid * 4;
    *(uint32_t*)(o + base) = pack_hf(o0, o1);
    *(uint32_t*)(o + base + 2) = pack_hf(o2, o3);
}

// ---------------- fp16 HMMA GEMM, 1 pass ----------------
// EPI: 1 bias+residual fp32 C; 2 bias+GELU fp16; 3 QKV head-major (Q scaled)
#define GSTAGES 3
#define STAGE_BYTES 16384

template <int EPI>
__global__ __launch_bounds__(256, 2) void gemm_mma(
    const hf* __restrict__ A, const hf* __restrict__ B,
    int K, int N,
    float* __restrict__ C, hf* __restrict__ Ch,
    const float* __restrict__ bias, const float* __restrict__ res,
    hf* __restrict__ Qd, hf* __restrict__ Kd, hf* __restrict__ Vd) {
    extern __shared__ char smem[];
    const uint32_t sb = smem_to_u32(smem);
    const int tid = threadIdx.x;
    const int lane = tid & 31;
    const int warp = tid >> 5;
    const int warpM = warp & 3, warpN = warp >> 2;
    const int bn = blockIdx.x * 128, bm = blockIdx.y * 128;

    const size_t rstrideB = (size_t)K * 2;
    const char* gA = (const char*)A + (size_t)bm * K * 2;
    const char* gB = (const char*)B + (size_t)bn * K * 2;

    const int NK = K >> 5;

    auto issue_chunk = [&](int c) {
        const uint32_t stg = sb + (uint32_t)(c % GSTAGES) * STAGE_BYTES;
        const size_t goff = (size_t)c * 64;
#pragma unroll
        for (int j = 0; j < 4; j++) {
            int id = tid + j * 256;
            int arr = id >> 9;
            int row = (id >> 2) & 127;
            int seg = id & 3;
            const char* src = (arr ? gB : gA) + goff + (size_t)row * rstrideB + seg * 16;
            uint32_t dst = stg + (uint32_t)arr * 8192 + (uint32_t)row * 64 +
                           ((uint32_t)(seg ^ ((row >> 1) & 3)) << 4);
            cp_async16(dst, src);
        }
    };

    const int aRow = warpM * 32 + (lane & 15);
    const int aKh = lane >> 4;
    const uint32_t aSw = (aRow >> 1) & 3;
    const uint32_t aRowB = (uint32_t)aRow * 64;
    const int bRowBase = warpN * 64 + (lane & 15);
    const int bKh = lane >> 4;
    const uint32_t bSw = (bRowBase >> 1) & 3;
    const uint32_t bRowB = (uint32_t)bRowBase * 64;

    float acc[2][8][4];
#pragma unroll
    for (int i = 0; i < 2; i++)
#pragma unroll
        for (int j = 0; j < 8; j++)
#pragma unroll
            for (int q = 0; q < 4; q++) acc[i][j][q] = 0.f;

#pragma unroll
    for (int s = 0; s < GSTAGES - 1; s++) { issue_chunk(s); cp_commit(); }

    for (int c = 0; c < NK; c++) {
        cp_wait<GSTAGES - 2>();
        __syncthreads();
        const uint32_t stg = sb + (uint32_t)(c % GSTAGES) * STAGE_BYTES;
#pragma unroll
        for (int k16 = 0; k16 < 2; k16++) {
            const uint32_t aSeg = ((uint32_t)(k16 * 2 + aKh) ^ aSw) << 4;
            const uint32_t bSeg = ((uint32_t)(k16 * 2 + bKh) ^ bSw) << 4;
            uint32_t ah[2][4], bh[4][4];
#pragma unroll
            for (int i = 0; i < 2; i++)
                ldm_x4(ah[i][0], ah[i][1], ah[i][2], ah[i][3],
                       stg + aRowB + (uint32_t)i * 16 * 64 + aSeg);
#pragma unroll
            for (int t = 0; t < 4; t++)
                ldm_x4(bh[t][0], bh[t][1], bh[t][2], bh[t][3],
                       stg + 8192 + bRowB + (uint32_t)t * 16 * 64 + bSeg);
#pragma unroll
            for (int i = 0; i < 2; i++)
#pragma unroll
                for (int t = 0; t < 4; t++) {
                    float* c0 = acc[i][2 * t];
                    float* c1 = acc[i][2 * t + 1];
                    mma_f16(c0[0], c0[1], c0[2], c0[3],
                            ah[i][0], ah[i][1], ah[i][2], ah[i][3], bh[t][0], bh[t][2]);
                    mma_f16(c1[0], c1[1], c1[2], c1[3],
                            ah[i][0], ah[i][1], ah[i][2], ah[i][3], bh[t][1], bh[t][3]);
                }
        }
        __syncthreads();
        if (c + GSTAGES - 1 < NK) issue_chunk(c + GSTAGES - 1);
        cp_commit();
    }

    const int gRow = lane >> 2;
    const int gCol = (lane & 3) * 2;
#pragma unroll
    for (int i = 0; i < 2; i++) {
#pragma unroll
        for (int j = 0; j < 8; j++) {
            int row = bm + warpM * 32 + i * 16 + gRow;
            int col = bn + warpN * 64 + j * 8 + gCol;
#pragma unroll
            for (int half = 0; half < 2; half++) {
                int r = row + half * 8;
                float v0 = acc[i][j][half * 2 + 0];
                float v1 = acc[i][j][half * 2 + 1];
                if (EPI == 1 || EPI == 2) {
                    float2 bb = *(const float2*)(bias + col);
                    v0 += bb.x; v1 += bb.y;
                }
                if (EPI == 1) {
                    float2 rv = *(const float2*)(res + (size_t)r * N + col);
                    v0 += rv.x; v1 += rv.y;
                    *(float2*)(C + (size_t)r * N + col) = make_float2(v0, v1);
                } else if (EPI == 2) {
                    v0 = gelu_exact(v0); v1 = gelu_exact(v1);
                    *(uint32_t*)(Ch + (size_t)r * N + col) = pack_hf(v0, v1);
                } else if (EPI == 3) {
                    int which = col >> 10;
                    int h = (col >> 6) & 15;
                    int e = col & 63;
                    int bb = r >> 11, s = r & 2047;
                    size_t o = (((size_t)(bb * 16 + h)) * SEQ + s) * D_HEAD + e;
                    if (which == 0) { v0 *= QSCALE; v1 *= QSCALE; }
                    hf* dst = (which == 0) ? Qd : (which == 1) ? Kd : Vd;
                    *(uint32_t*)(dst + o) = pack_hf(v0, v1);
                }
            }
        }
    }
}

// ---------------- fp16 HMMA flash attention, 1-pass S and PV ----------------
// smem: Q 0 (16KB); stage s at 16384 + s*16384: K 0, V 8192
#define ATT_SMEM (16384 + 2 * 16384)

__global__ __launch_bounds__(256, 1) void attn_mma(
    const hf* __restrict__ q_g, const hf* __restrict__ k_g, const hf* __restrict__ v_g,
    hf* __restrict__ oh) {
    extern __shared__ char smem[];
    const uint32_t sb = smem_to_u32(smem);
    const int tid = threadIdx.x;
    const int lane = tid & 31;
    const int warp = tid >> 5;
    const int bh = blockIdx.y;
    const int q0 = blockIdx.x * 128;

    const char* qb = (const char*)(q_g + ((size_t)bh * SEQ + q0) * D_HEAD);
    const char* kb = (const char*)(k_g + (size_t)bh * SEQ * D_HEAD);
    const char* vb = (const char*)(v_g + (size_t)bh * SEQ * D_HEAD);

    {
#pragma unroll
        for (int j = 0; j < 4; j++) {
            int id = tid + j * 256;
            int row = (id >> 3) & 127, seg = id & 7;
            uint32_t dst = sb + (uint32_t)row * 128 + ((uint32_t)(seg ^ (row & 7)) << 4);
            cp_async16(dst, qb + (size_t)row * 128 + seg * 16);
        }
    }
    auto issue_kv = [&](int kt) {
        const uint32_t stg = sb + 16384 + (uint32_t)(kt & 1) * 16384;
        const size_t gof = (size_t)kt * 64 * 128;
#pragma unroll
        for (int j = 0; j < 4; j++) {
            int id = tid + j * 256;
            int arr = id >> 9, row = (id >> 3) & 63, seg = id & 7;
            const char* src = ((arr == 0) ? kb : vb) + gof + (size_t)row * 128 + seg * 16;
            uint32_t dst = stg + (uint32_t)arr * 8192 + (uint32_t)row * 128 +
                           ((uint32_t)(seg ^ (row & 7)) << 4);
            cp_async16(dst, src);
        }
    };

    issue_kv(0);
    cp_commit();
    issue_kv(1);
    cp_commit();

    float accO[8][4];
#pragma unroll
    for (int t = 0; t < 8; t++)
#pragma unroll
        for (int q = 0; q < 4; q++) accO[t][q] = 0.f;
    float m0 = -1e30f, m1 = -1e30f, l0 = 0.f, l1 = 0.f;

    uint32_t qf[4][4];
    const int qRow = warp * 16 + (lane & 15);
    const uint32_t qSw = (uint32_t)(qRow & 7);
    const uint32_t qRowB = (uint32_t)qRow * 128;

    const int NT = SEQ / 64;
    for (int kt = 0; kt < NT; kt++) {
        cp_wait<1>();
        __syncthreads();
        if (kt == 0) {
#pragma unroll
            for (int ks = 0; ks < 4; ks++) {
                uint32_t seg = ((uint32_t)(ks * 2 + (lane >> 4)) ^ qSw) << 4;
                ldm_x4(qf[ks][0], qf[ks][1], qf[ks][2], qf[ks][3], sb + qRowB + seg);
            }
        }
        const uint32_t stg = sb + 16384 + (uint32_t)(kt & 1) * 16384;

        // ---- S = Q K^T (1 pass) ----
        float S[8][4];
#pragma unroll
        for (int t = 0; t < 8; t++)
#pragma unroll
            for (int q = 0; q < 4; q++) S[t][q] = 0.f;

        const int nRow = lane & 15;
        const int kh4 = lane >> 4;
#pragma unroll
        for (int ks = 0; ks < 4; ks++) {
            uint32_t kh[4][4];
#pragma unroll
            for (int g = 0; g < 4; g++) {
                int row = g * 16 + nRow;
                uint32_t seg = ((uint32_t)(ks * 2 + kh4) ^ (uint32_t)(row & 7)) << 4;
                ldm_x4(kh[g][0], kh[g][1], kh[g][2], kh[g][3],
                       stg + (uint32_t)row * 128 + seg);
            }
#pragma unroll
            for (int g = 0; g < 4; g++) {
                float* c0 = S[2 * g];
                float* c1 = S[2 * g + 1];
                mma_f16(c0[0], c0[1], c0[2], c0[3],
                        qf[ks][0], qf[ks][1], qf[ks][2], qf[ks][3], kh[g][0], kh[g][2]);
                mma_f16(c1[0], c1[1], c1[2], c1[3],
                        qf[ks][0], qf[ks][1], qf[ks][2], qf[ks][3], kh[g][1], kh[g][3]);
            }
        }

        // ---- online softmax (f32x2 packed exp2, base-2 domain) ----
        float mx0 = S[0][0], mx1 = S[0][2];
#pragma unroll
        for (int t = 0; t < 8; t++) {
            mx0 = fmaxf(mx0, fmaxf(S[t][0], S[t][1]));
            mx1 = fmaxf(mx1, fmaxf(S[t][2], S[t][3]));
        }
        mx0 = fmaxf(mx0, __shfl_xor_sync(0xffffffffu, mx0, 1));
        mx0 = fmaxf(mx0, __shfl_xor_sync(0xffffffffu, mx0, 2));
        mx1 = fmaxf(mx1, __shfl_xor_sync(0xffffffffu, mx1, 1));
        mx1 = fmaxf(mx1, __shfl_xor_sync(0xffffffffu, mx1, 2));
        float mn0 = fmaxf(m0, mx0), mn1 = fmaxf(m1, mx1);
        float cr0 = m0 - mn0, cr1 = m1 - mn1;
        exp2_pair(cr0, cr1);
        m0 = mn0; m1 = mn1;
        float sum0 = 0.f, sum1 = 0.f;
#pragma unroll
        for (int t = 0; t < 8; t++) {
            float a0 = S[t][0] - mn0, a1 = S[t][1] - mn0;
            float b0 = S[t][2] - mn1, b1 = S[t][3] - mn1;
            exp2_pair(a0, a1);
            exp2_pair(b0, b1);
            S[t][0] = a0; S[t][1] = a1; S[t][2] = b0; S[t][3] = b1;
            sum0 += a0 + a1;
            sum1 += b0 + b1;
        }
        sum0 += __shfl_xor_sync(0xffffffffu, sum0, 1);
        sum0 += __shfl_xor_sync(0xffffffffu, sum0, 2);
        sum1 += __shfl_xor_sync(0xffffffffu, sum1, 1);
        sum1 += __shfl_xor_sync(0xffffffffu, sum1, 2);
        l0 = l0 * cr0 + sum0;
        l1 = l1 * cr1 + sum1;
#pragma unroll
        for (int t = 0; t < 8; t++) {
            accO[t][0] *= cr0; accO[t][1] *= cr0;
            accO[t][2] *= cr1; accO[t][3] *= cr1;
        }

        // ---- O += P V (1 pass) ----
        const int vRow16 = lane & 15;
        const int vEh = lane >> 4;
#pragma unroll
        for (int ks = 0; ks < 4; ks++) {
            uint32_t pa[4];
            pa[0] = pack_hf(S[2 * ks][0], S[2 * ks][1]);
            pa[1] = pack_hf(S[2 * ks][2], S[2 * ks][3]);
            pa[2] = pack_hf(S[2 * ks + 1][0], S[2 * ks + 1][1]);
            pa[3] = pack_hf(S[2 * ks + 1][2], S[2 * ks + 1][3]);

            uint32_t vh[4][4];
#pragma unroll
            for (int g = 0; g < 4; g++) {
                int row = ks * 16 + vRow16;
                uint32_t seg = ((uint32_t)(g * 2 + vEh) ^ (uint32_t)(row & 7)) << 4;
                ldm_x4_t(vh[g][0], vh[g][1], vh[g][2], vh[g][3],
                         stg + 8192 + (uint32_t)row * 128 + seg);
            }
#pragma unroll
            for (int g = 0; g < 4; g++) {
                float* c0 = accO[2 * g];
                float* c1 = accO[2 * g + 1];
                mma_f16(c0[0], c0[1], c0[2], c0[3],
                        pa[0], pa[1], pa[2], pa[3], vh[g][0], vh[g][1]);
                mma_f16(c1[0], c1[1], c1[2], c1[3],
                        pa[0], pa[1], pa[2], pa[3], vh[g][2], vh[g][3]);
            }
        }
        __syncthreads();
        if (kt + 2 < NT) issue_kv(kt + 2);
        cp_commit();
    }

    // ---- epilogue ----
    float inv0 = 1.0f / l0, inv1 = 1.0f / l1;
    const int b = bh >> 4, h = bh & 15;
    const int r1 = q0 + warp * 16 + (lane >> 2);
    const int r2 = r1 + 8;
    size_t t1 = ((size_t)(b * SEQ) + r1) * D_MODEL + h * D_HEAD;
    size_t t2 = ((size_t)(b * SEQ) + r2) * D_MODEL + h * D_HEAD;
#pragma unroll
    for (int t = 0; t < 8; t++) {
        int e = t * 8 + (lane & 3) * 2;
        *(uint32_t*)(oh + t1 + e) = pack_hf(accO[t][0] * inv0, accO[t][1] * inv0);
        *(uint32_t*)(oh + t2 + e) = pack_hf(accO[t][2] * inv1, accO[t][3] * inv1);
    }
}

// ---------------- launch ----------------
extern "C" void kernel_launch(void* const* d_in, const int* in_sizes, int n_in,
                              void* d_out, int out_size) {
    const float* x    = (const float*)d_in[0];
    const float* Wq   = (const float*)d_in[1];
    const float* Wk   = (const float*)d_in[2];
    const float* Wv   = (const float*)d_in[3];
    const float* Wo   = (const float*)d_in[4];
    const float* bo   = (const float*)d_in[5];
    const float* ln1g = (const float*)d_in[6];
    const float* ln1b = (const float*)d_in[7];
    const float* ln2g = (const float*)d_in[8];
    const float* ln2b = (const float*)d_in[9];
    const float* W1   = (const float*)d_in[10];
    const float* b1   = (const float*)d_in[11];
    const float* W2   = (const float*)d_in[12];
    const float* b2   = (const float*)d_in[13];
    float* out = (float*)d_out;

    hf *pWqkv, *pWo, *pW1, *pW2, *pXn, *pAt, *pHn, *pFf, *pQ, *pK, *pV;
    float* pHid;
    cudaGetSymbolAddress((void**)&pWqkv, g_WqkvT);
    cudaGetSymbolAddress((void**)&pWo, g_WoT);
    cudaGetSymbolAddress((void**)&pW1, g_W1T);
    cudaGetSymbolAddress((void**)&pW2, g_W2T);
    cudaGetSymbolAddress((void**)&pXn, g_xn);
    cudaGetSymbolAddress((void**)&pAt, g_at);
    cudaGetSymbolAddress((void**)&pHn, g_hn);
    cudaGetSymbolAddress((void**)&pFf, g_ff);
    cudaGetSymbolAddress((void**)&pQ, g_q);
    cudaGetSymbolAddress((void**)&pK, g_k);
    cudaGetSymbolAddress((void**)&pV, g_v);
    cudaGetSymbolAddress((void**)&pHid, g_hidden);

    const int GEMM_SMEM = GSTAGES * STAGE_BYTES;  // 49152
    cudaFuncSetAttribute(gemm_mma<1>, cudaFuncAttributeMaxDynamicSharedMemorySize, GEMM_SMEM);
    cudaFuncSetAttribute(gemm_mma<2>, cudaFuncAttributeMaxDynamicSharedMemorySize, GEMM_SMEM);
    cudaFuncSetAttribute(gemm_mma<3>, cudaFuncAttributeMaxDynamicSharedMemorySize, GEMM_SMEM);
    cudaFuncSetAttribute(attn_mma, cudaFuncAttributeMaxDynamicSharedMemorySize, ATT_SMEM);

    dim3 t328(32, 8);
    transconv_qkv_k<<<dim3(D_MODEL / 32, QKV_N / 32), t328>>>(Wq, Wk, Wv, pWqkv);
    transconv_k<<<dim3(D_MODEL / 32, D_MODEL / 32), t328>>>(Wo, pWo, D_MODEL, D_MODEL);
    transconv_k<<<dim3(D_MODEL / 32, D_FF / 32), t328>>>(W1, pW1, D_MODEL, D_FF);
    transconv_k<<<dim3(D_FF / 32, D_MODEL / 32), t328>>>(W2, pW2, D_FF, D_MODEL);

    layernorm_k<<<TOKENS, 256>>>(x, ln1g, ln1b, pXn);
    // QKV projection (1-pass) -> head-major fp16 q(scaled)/k/v
    gemm_mma<3><<<dim3(QKV_N / 128, TOKENS / 128), 256, GEMM_SMEM>>>(
        pXn, pWqkv, D_MODEL, QKV_N, nullptr, nullptr, nullptr, nullptr, pQ, pK, pV);
    // flash attention (1-pass S, 1-pass PV, packed exp2)
    attn_mma<<<dim3(SEQ / 128, BH), 256, ATT_SMEM>>>(pQ, pK, pV, pAt);
    // O projection (1-pass) + bias + residual
    gemm_mma<1><<<dim3(D_MODEL / 128, TOKENS / 128), 256, GEMM_SMEM>>>(
        pAt, pWo, D_MODEL, D_MODEL, pHid, nullptr, bo, x, nullptr, nullptr, nullptr);
    layernorm_k<<<TOKENS, 256>>>(pHid, ln2g, ln2b, pHn);
    // FF1 (1-pass) + bias + GELU
    gemm_mma<2><<<dim3(D_FF / 128, TOKENS / 128), 256, GEMM_SMEM>>>(
        pHn, pW1, D_MODEL, D_FF, nullptr, pFf, b1, nullptr, nullptr, nullptr, nullptr);
    // FF2 (1-pass) + bias + residual -> out
    gemm_mma<1><<<dim3(D_MODEL / 128, TOKENS / 128), 256, GEMM_SMEM>>>(
        pFf, pW2, D_FF, D_MODEL, out, nullptr, b2, pHid, nullptr, nullptr, nullptr);
}

// round 9
// speedup vs baseline: 6.4716x; 1.0098x over previous
#include <cuda_runtime.h>
#include <cuda_fp16.h>
#include <math.h>
#include <stdint.h>

#define D_MODEL 1024
#define N_HEADS 16
#define D_HEAD 64
#define D_FF 4096
#define SEQ 2048
#define BATCH 2
#define TOKENS (BATCH * SEQ)
#define QKV_N (3 * D_MODEL)
#define BH (BATCH * N_HEADS)

typedef __half hf;

// ---------------- scratch ----------------
__device__ hf g_WqkvT[QKV_N * D_MODEL];
__device__ hf g_WoT[D_MODEL * D_MODEL];
__device__ hf g_W1T[D_FF * D_MODEL];
__device__ hf g_W2T[D_MODEL * D_FF];
__device__ hf g_xn[TOKENS * D_MODEL];
// head-major QKV: [bh][s][64]
__device__ hf g_q[BH * SEQ * D_HEAD];
__device__ hf g_k[BH * SEQ * D_HEAD];
__device__ hf g_v[BH * SEQ * D_HEAD];
__device__ hf g_at[TOKENS * D_MODEL];
__device__ float g_hidden[TOKENS * D_MODEL];
__device__ hf g_hn[TOKENS * D_MODEL];
__device__ hf g_ff[(size_t)TOKENS * D_FF];

__device__ __forceinline__ uint32_t smem_to_u32(const void* p) {
    uint32_t a;
    asm("{ .reg .u64 t; cvta.to.shared.u64 t, %1; cvt.u32.u64 %0, t; }"
        : "=r"(a) : "l"(p));
    return a;
}
__device__ __forceinline__ void cp_async16(uint32_t smem, const void* gmem) {
    asm volatile("cp.async.cg.shared.global [%0], [%1], 16;" :: "r"(smem), "l"(gmem));
}
__device__ __forceinline__ void cp_commit() { asm volatile("cp.async.commit_group;"); }
template <int N>
__device__ __forceinline__ void cp_wait() { asm volatile("cp.async.wait_group %0;" :: "n"(N)); }

__device__ __forceinline__ void ldm_x4(uint32_t& r0, uint32_t& r1, uint32_t& r2, uint32_t& r3,
                                       uint32_t addr) {
    asm volatile("ldmatrix.sync.aligned.m8n8.x4.shared.b16 {%0,%1,%2,%3}, [%4];"
                 : "=r"(r0), "=r"(r1), "=r"(r2), "=r"(r3) : "r"(addr));
}
__device__ __forceinline__ void ldm_x4_t(uint32_t& r0, uint32_t& r1, uint32_t& r2, uint32_t& r3,
                                         uint32_t addr) {
    asm volatile("ldmatrix.sync.aligned.m8n8.x4.trans.shared.b16 {%0,%1,%2,%3}, [%4];"
                 : "=r"(r0), "=r"(r1), "=r"(r2), "=r"(r3) : "r"(addr));
}
__device__ __forceinline__ void mma_f16(float& c0, float& c1, float& c2, float& c3,
                                        uint32_t a0, uint32_t a1, uint32_t a2, uint32_t a3,
                                        uint32_t b0, uint32_t b1) {
    asm volatile(
        "mma.sync.aligned.m16n8k16.row.col.f32.f16.f16.f32 "
        "{%0,%1,%2,%3}, {%4,%5,%6,%7}, {%8,%9}, {%0,%1,%2,%3};"
        : "+f"(c0), "+f"(c1), "+f"(c2), "+f"(c3)
        : "r"(a0), "r"(a1), "r"(a2), "r"(a3), "r"(b0), "r"(b1));
}

__device__ __forceinline__ float gelu_exact(float v) {
    return 0.5f * v * (1.0f + erff(v * 0.70710678118654752440f));
}

// ---- packed f32x2 helpers (sm_100+ base PTX) ----
__device__ __forceinline__ uint64_t pk2(float a, float b) {
    uint64_t r; asm("mov.b64 %0, {%1, %2};" : "=l"(r) : "f"(a), "f"(b)); return r;
}
__device__ __forceinline__ void upk2(uint64_t v, float& a, float& b) {
    asm("mov.b64 {%0, %1}, %2;" : "=f"(a), "=f"(b) : "l"(v));
}
__device__ __forceinline__ uint64_t add2_(uint64_t a, uint64_t b) {
    uint64_t r; asm("add.rn.f32x2 %0, %1, %2;" : "=l"(r) : "l"(a), "l"(b)); return r;
}
__device__ __forceinline__ uint64_t fma2_(uint64_t a, uint64_t b, uint64_t c) {
    uint64_t r; asm("fma.rn.f32x2 %0, %1, %2, %3;" : "=l"(r) : "l"(a), "l"(b), "l"(c)); return r;
}
// exp2 of two values at once, pure FMA/ALU pipes (no MUFU). inputs expected <= 0.
__device__ __forceinline__ void exp2_pair(float& x0, float& x1) {
    float t0 = fmaxf(x0, -126.0f), t1 = fmaxf(x1, -126.0f);
    uint64_t t = pk2(t0, t1);
    uint64_t fn = add2_(t, pk2(12582912.0f, 12582912.0f));
    float fn0, fn1; upk2(fn, fn0, fn1);
    int n0 = __float_as_int(fn0) - 0x4B400000;
    int n1 = __float_as_int(fn1) - 0x4B400000;
    uint64_t fm = add2_(fn, pk2(-12582912.0f, -12582912.0f));
    uint64_t f = fma2_(fm, pk2(-1.0f, -1.0f), t);  // f = t - (fn - magic)
    uint64_t p = pk2(0.0013333558f, 0.0013333558f);
    p = fma2_(p, f, pk2(0.0096181291f, 0.0096181291f));
    p = fma2_(p, f, pk2(0.0555041087f, 0.0555041087f));
    p = fma2_(p, f, pk2(0.2402265070f, 0.2402265070f));
    p = fma2_(p, f, pk2(0.6931471806f, 0.6931471806f));
    p = fma2_(p, f, pk2(1.0f, 1.0f));
    float p0, p1; upk2(p, p0, p1);
    x0 = __int_as_float(__float_as_int(p0) + (n0 << 23));
    x1 = __int_as_float(__float_as_int(p1) + (n1 << 23));
}

__device__ __forceinline__ uint32_t pack_h(hf a, hf b) {
    __half2 p = __halves2half2(a, b);
    return *(uint32_t*)&p;
}
__device__ __forceinline__ uint32_t pack_hf(float a, float b) {
    return pack_h(__float2half_rn(a), __float2half_rn(b));
}

#define QSCALE 0.18033688011f  // 0.125 * log2(e)

// ---------------- weight transpose -> fp16 (64x64 tiles, float4 loads) ----------------
__global__ __launch_bounds__(256) void transconv_k(const float* __restrict__ src,
                                                   hf* __restrict__ d, int K, int N) {
    __shared__ float t[64][65];
    const int tid = threadIdx.x;
    const int k0 = blockIdx.x * 64, n0 = blockIdx.y * 64;
    const int lr = tid >> 4, lc = (tid & 15) * 4;
#pragma unroll
    for (int i = 0; i < 4; i++) {
        float4 v = *(const float4*)(src + (size_t)(k0 + lr + i * 16) * N + n0 + lc);
        t[lr + i * 16][lc + 0] = v.x;
        t[lr + i * 16][lc + 1] = v.y;
        t[lr + i * 16][lc + 2] = v.z;
        t[lr + i * 16][lc + 3] = v.w;
    }
    __syncthreads();
    const int nr = tid >> 2, kc = (tid & 3) * 16;
    hf* dst = d + (size_t)(n0 + nr) * K + k0 + kc;
#pragma unroll
    for (int j = 0; j < 8; j++)
        *(uint32_t*)(dst + 2 * j) = pack_hf(t[kc + 2 * j][nr], t[kc + 2 * j + 1][nr]);
}

// Wq/Wk/Wv [h][d][64] -> dst row n = w*1024 + h*64 + e, col k = d. 64-wide n-tiles align to heads.
__global__ __launch_bounds__(256) void transconv_qkv_k(const float* __restrict__ Wq,
                                                       const float* __restrict__ Wk,
                                                       const float* __restrict__ Wv,
                                                       hf* __restrict__ d) {
    __shared__ float t[64][65];
    const int tid = threadIdx.x;
    const int k0 = blockIdx.x * 64, n0 = blockIdx.y * 64;
    const int w = n0 >> 10, h = (n0 >> 6) & 15;
    const float* W = (w == 0) ? Wq : (w == 1) ? Wk : Wv;
    const float* src = W + (size_t)h * D_MODEL * D_HEAD;
    const int lr = tid >> 4, lc = (tid & 15) * 4;
#pragma unroll
    for (int i = 0; i < 4; i++) {
        float4 v = *(const float4*)(src + (size_t)(k0 + lr + i * 16) * 64 + lc);
        t[lr + i * 16][lc + 0] = v.x;
        t[lr + i * 16][lc + 1] = v.y;
        t[lr + i * 16][lc + 2] = v.z;
        t[lr + i * 16][lc + 3] = v.w;
    }
    __syncthreads();
    const int nr = tid >> 2, kc = (tid & 3) * 16;
    hf* dst = d + (size_t)(n0 + nr) * D_MODEL + k0 + kc;
#pragma unroll
    for (int j = 0; j < 8; j++)
        *(uint32_t*)(dst + 2 * j) = pack_hf(t[kc + 2 * j][nr], t[kc + 2 * j + 1][nr]);
}

// ---------------- LayerNorm -> fp16 ----------------
__global__ __launch_bounds__(256) void layernorm_k(const float* __restrict__ x,
                                                   const float* __restrict__ g,
                                                   const float* __restrict__ b,
                                                   hf* __restrict__ o) {
    __shared__ float red[2][8];
    int row = blockIdx.x;
    int tid = threadIdx.x;
    const float4* xr = (const float4*)(x + (size_t)row * D_MODEL);
    float4 v = xr[tid];
    float s = v.x + v.y + v.z + v.w;
    float ss = v.x * v.x + v.y * v.y + v.z * v.z + v.w * v.w;
#pragma unroll
    for (int of = 16; of > 0; of >>= 1) {
        s += __shfl_xor_sync(0xffffffffu, s, of);
        ss += __shfl_xor_sync(0xffffffffu, ss, of);
    }
    int w = tid >> 5, l = tid & 31;
    if (l == 0) { red[0][w] = s; red[1][w] = ss; }
    __syncthreads();
    if (tid < 32) {
        s = (l < 8) ? red[0][l] : 0.f;
        ss = (l < 8) ? red[1][l] : 0.f;
#pragma unroll
        for (int of = 4; of > 0; of >>= 1) {
            s += __shfl_xor_sync(0xffffffffu, s, of);
            ss += __shfl_xor_sync(0xffffffffu, ss, of);
        }
        if (l == 0) { red[0][0] = s; red[1][0] = ss; }
    }
    __syncthreads();
    float mu = red[0][0] * (1.0f / D_MODEL);
    float var = red[1][0] * (1.0f / D_MODEL) - mu * mu;
    float r = rsqrtf(var + 1e-5f);
    float4 gv = ((const float4*)g)[tid];
    float4 bv = ((const float4*)b)[tid];
    float o0 = (v.x - mu) * r * gv.x + bv.x;
    float o1 = (v.y - mu) * r * gv.y + bv.y;
    float o2 = (v.z - mu) * r * gv.z + bv.z;
    float o3 = (v.w - mu) * r * gv.w + bv.w;
    size_t base = (size_t)row * D_MODEL + tid * 4;
    *(uint32_t*)(o + base) = pack_hf(o0, o1);
    *(uint32_t*)(o + base + 2) = pack_hf(o2, o3);
}

// ---------------- fp16 HMMA GEMM, 1 pass ----------------
// EPI: 1 bias+residual fp32 C; 2 bias+GELU fp16; 3 QKV head-major (Q scaled)
#define GSTAGES 3
#define STAGE_BYTES 16384

template <int EPI>
__global__ __launch_bounds__(256, 2) void gemm_mma(
    const hf* __restrict__ A, const hf* __restrict__ B,
    int K, int N,
    float* __restrict__ C, hf* __restrict__ Ch,
    const float* __restrict__ bias, const float* __restrict__ res,
    hf* __restrict__ Qd, hf* __restrict__ Kd, hf* __restrict__ Vd) {
    extern __shared__ char smem[];
    const uint32_t sb = smem_to_u32(smem);
    const int tid = threadIdx.x;
    const int lane = tid & 31;
    const int warp = tid >> 5;
    const int warpM = warp & 3, warpN = warp >> 2;
    const int bn = blockIdx.x * 128, bm = blockIdx.y * 128;

    const size_t rstrideB = (size_t)K * 2;
    const char* gA = (const char*)A + (size_t)bm * K * 2;
    const char* gB = (const char*)B + (size_t)bn * K * 2;

    const int NK = K >> 5;

    auto issue_chunk = [&](int c) {
        const uint32_t stg = sb + (uint32_t)(c % GSTAGES) * STAGE_BYTES;
        const size_t goff = (size_t)c * 64;
#pragma unroll
        for (int j = 0; j < 4; j++) {
            int id = tid + j * 256;
            int arr = id >> 9;
            int row = (id >> 2) & 127;
            int seg = id & 3;
            const char* src = (arr ? gB : gA) + goff + (size_t)row * rstrideB + seg * 16;
            uint32_t dst = stg + (uint32_t)arr * 8192 + (uint32_t)row * 64 +
                           ((uint32_t)(seg ^ ((row >> 1) & 3)) << 4);
            cp_async16(dst, src);
        }
    };

    const int aRow = warpM * 32 + (lane & 15);
    const int aKh = lane >> 4;
    const uint32_t aSw = (aRow >> 1) & 3;
    const uint32_t aRowB = (uint32_t)aRow * 64;
    const int bRowBase = warpN * 64 + (lane & 15);
    const int bKh = lane >> 4;
    const uint32_t bSw = (bRowBase >> 1) & 3;
    const uint32_t bRowB = (uint32_t)bRowBase * 64;

    float acc[2][8][4];
#pragma unroll
    for (int i = 0; i < 2; i++)
#pragma unroll
        for (int j = 0; j < 8; j++)
#pragma unroll
            for (int q = 0; q < 4; q++) acc[i][j][q] = 0.f;

#pragma unroll
    for (int s = 0; s < GSTAGES - 1; s++) { issue_chunk(s); cp_commit(); }

    for (int c = 0; c < NK; c++) {
        cp_wait<GSTAGES - 2>();
        __syncthreads();
        const uint32_t stg = sb + (uint32_t)(c % GSTAGES) * STAGE_BYTES;
#pragma unroll
        for (int k16 = 0; k16 < 2; k16++) {
            const uint32_t aSeg = ((uint32_t)(k16 * 2 + aKh) ^ aSw) << 4;
            const uint32_t bSeg = ((uint32_t)(k16 * 2 + bKh) ^ bSw) << 4;
            uint32_t ah[2][4], bh[4][4];
#pragma unroll
            for (int i = 0; i < 2; i++)
                ldm_x4(ah[i][0], ah[i][1], ah[i][2], ah[i][3],
                       stg + aRowB + (uint32_t)i * 16 * 64 + aSeg);
#pragma unroll
            for (int t = 0; t < 4; t++)
                ldm_x4(bh[t][0], bh[t][1], bh[t][2], bh[t][3],
                       stg + 8192 + bRowB + (uint32_t)t * 16 * 64 + bSeg);
#pragma unroll
            for (int i = 0; i < 2; i++)
#pragma unroll
                for (int t = 0; t < 4; t++) {
                    float* c0 = acc[i][2 * t];
                    float* c1 = acc[i][2 * t + 1];
                    mma_f16(c0[0], c0[1], c0[2], c0[3],
                            ah[i][0], ah[i][1], ah[i][2], ah[i][3], bh[t][0], bh[t][2]);
                    mma_f16(c1[0], c1[1], c1[2], c1[3],
                            ah[i][0], ah[i][1], ah[i][2], ah[i][3], bh[t][1], bh[t][3]);
                }
        }
        __syncthreads();
        if (c + GSTAGES - 1 < NK) issue_chunk(c + GSTAGES - 1);
        cp_commit();
    }

    const int gRow = lane >> 2;
    const int gCol = (lane & 3) * 2;
#pragma unroll
    for (int i = 0; i < 2; i++) {
#pragma unroll
        for (int j = 0; j < 8; j++) {
            int row = bm + warpM * 32 + i * 16 + gRow;
            int col = bn + warpN * 64 + j * 8 + gCol;
#pragma unroll
            for (int half = 0; half < 2; half++) {
                int r = row + half * 8;
                float v0 = acc[i][j][half * 2 + 0];
                float v1 = acc[i][j][half * 2 + 1];
                if (EPI == 1 || EPI == 2) {
                    float2 bb = *(const float2*)(bias + col);
                    v0 += bb.x; v1 += bb.y;
                }
                if (EPI == 1) {
                    float2 rv = *(const float2*)(res + (size_t)r * N + col);
                    v0 += rv.x; v1 += rv.y;
                    *(float2*)(C + (size_t)r * N + col) = make_float2(v0, v1);
                } else if (EPI == 2) {
                    v0 = gelu_exact(v0); v1 = gelu_exact(v1);
                    *(uint32_t*)(Ch + (size_t)r * N + col) = pack_hf(v0, v1);
                } else if (EPI == 3) {
                    int which = col >> 10;
                    int h = (col >> 6) & 15;
                    int e = col & 63;
                    int bb = r >> 11, s = r & 2047;
                    size_t o = (((size_t)(bb * 16 + h)) * SEQ + s) * D_HEAD + e;
                    if (which == 0) { v0 *= QSCALE; v1 *= QSCALE; }
                    hf* dst = (which == 0) ? Qd : (which == 1) ? Kd : Vd;
                    *(uint32_t*)(dst + o) = pack_hf(v0, v1);
                }
            }
        }
    }
}

// ---------------- fp16 HMMA flash attention, 1-pass S and PV, 2 CTAs/SM ----------------
// smem: Q 0 (16KB); stage s at 16384 + s*16384: K 0, V 8192
#define ATT_SMEM (16384 + 2 * 16384)

__global__ __launch_bounds__(256, 2) void attn_mma(
    const hf* __restrict__ q_g, const hf* __restrict__ k_g, const hf* __restrict__ v_g,
    hf* __restrict__ oh) {
    extern __shared__ char smem[];
    const uint32_t sb = smem_to_u32(smem);
    const int tid = threadIdx.x;
    const int lane = tid & 31;
    const int warp = tid >> 5;
    const int bh = blockIdx.y;
    const int q0 = blockIdx.x * 128;

    const char* qb = (const char*)(q_g + ((size_t)bh * SEQ + q0) * D_HEAD);
    const char* kb = (const char*)(k_g + (size_t)bh * SEQ * D_HEAD);
    const char* vb = (const char*)(v_g + (size_t)bh * SEQ * D_HEAD);

    {
#pragma unroll
        for (int j = 0; j < 4; j++) {
            int id = tid + j * 256;
            int row = (id >> 3) & 127, seg = id & 7;
            uint32_t dst = sb + (uint32_t)row * 128 + ((uint32_t)(seg ^ (row & 7)) << 4);
            cp_async16(dst, qb + (size_t)row * 128 + seg * 16);
        }
    }
    auto issue_kv = [&](int kt) {
        const uint32_t stg = sb + 16384 + (uint32_t)(kt & 1) * 16384;
        const size_t gof = (size_t)kt * 64 * 128;
#pragma unroll
        for (int j = 0; j < 4; j++) {
            int id = tid + j * 256;
            int arr = id >> 9, row = (id >> 3) & 63, seg = id & 7;
            const char* src = ((arr == 0) ? kb : vb) + gof + (size_t)row * 128 + seg * 16;
            uint32_t dst = stg + (uint32_t)arr * 8192 + (uint32_t)row * 128 +
                           ((uint32_t)(seg ^ (row & 7)) << 4);
            cp_async16(dst, src);
        }
    };

    issue_kv(0);
    cp_commit();
    issue_kv(1);
    cp_commit();

    float accO[8][4];
#pragma unroll
    for (int t = 0; t < 8; t++)
#pragma unroll
        for (int q = 0; q < 4; q++) accO[t][q] = 0.f;
    float m0 = -1e30f, m1 = -1e30f, l0 = 0.f, l1 = 0.f;

    uint32_t qf[4][4];
    const int qRow = warp * 16 + (lane & 15);
    const uint32_t qSw = (uint32_t)(qRow & 7);
    const uint32_t qRowB = (uint32_t)qRow * 128;

    const int NT = SEQ / 64;
    for (int kt = 0; kt < NT; kt++) {
        cp_wait<1>();
        __syncthreads();
        if (kt == 0) {
#pragma unroll
            for (int ks = 0; ks < 4; ks++) {
                uint32_t seg = ((uint32_t)(ks * 2 + (lane >> 4)) ^ qSw) << 4;
                ldm_x4(qf[ks][0], qf[ks][1], qf[ks][2], qf[ks][3], sb + qRowB + seg);
            }
        }
        const uint32_t stg = sb + 16384 + (uint32_t)(kt & 1) * 16384;

        // ---- S = Q K^T (1 pass) ----
        float S[8][4];
#pragma unroll
        for (int t = 0; t < 8; t++)
#pragma unroll
            for (int q = 0; q < 4; q++) S[t][q] = 0.f;

        const int nRow = lane & 15;
        const int kh4 = lane >> 4;
#pragma unroll
        for (int ks = 0; ks < 4; ks++) {
            uint32_t kh[4][4];
#pragma unroll
            for (int g = 0; g < 4; g++) {
                int row = g * 16 + nRow;
                uint32_t seg = ((uint32_t)(ks * 2 + kh4) ^ (uint32_t)(row & 7)) << 4;
                ldm_x4(kh[g][0], kh[g][1], kh[g][2], kh[g][3],
                       stg + (uint32_t)row * 128 + seg);
            }
#pragma unroll
            for (int g = 0; g < 4; g++) {
                float* c0 = S[2 * g];
                float* c1 = S[2 * g + 1];
                mma_f16(c0[0], c0[1], c0[2], c0[3],
                        qf[ks][0], qf[ks][1], qf[ks][2], qf[ks][3], kh[g][0], kh[g][2]);
                mma_f16(c1[0], c1[1], c1[2], c1[3],
                        qf[ks][0], qf[ks][1], qf[ks][2], qf[ks][3], kh[g][1], kh[g][3]);
            }
        }

        // ---- online softmax (f32x2 packed exp2, base-2 domain) ----
        float mx0 = S[0][0], mx1 = S[0][2];
#pragma unroll
        for (int t = 0; t < 8; t++) {
            mx0 = fmaxf(mx0, fmaxf(S[t][0], S[t][1]));
            mx1 = fmaxf(mx1, fmaxf(S[t][2], S[t][3]));
        }
        mx0 = fmaxf(mx0, __shfl_xor_sync(0xffffffffu, mx0, 1));
        mx0 = fmaxf(mx0, __shfl_xor_sync(0xffffffffu, mx0, 2));
        mx1 = fmaxf(mx1, __shfl_xor_sync(0xffffffffu, mx1, 1));
        mx1 = fmaxf(mx1, __shfl_xor_sync(0xffffffffu, mx1, 2));
        float mn0 = fmaxf(m0, mx0), mn1 = fmaxf(m1, mx1);
        float cr0 = m0 - mn0, cr1 = m1 - mn1;
        exp2_pair(cr0, cr1);
        m0 = mn0; m1 = mn1;
        float sum0 = 0.f, sum1 = 0.f;
#pragma unroll
        for (int t = 0; t < 8; t++) {
            float a0 = S[t][0] - mn0, a1 = S[t][1] - mn0;
            float b0 = S[t][2] - mn1, b1 = S[t][3] - mn1;
            exp2_pair(a0, a1);
            exp2_pair(b0, b1);
            S[t][0] = a0; S[t][1] = a1; S[t][2] = b0; S[t][3] = b1;
            sum0 += a0 + a1;
            sum1 += b0 + b1;
        }
        sum0 += __shfl_xor_sync(0xffffffffu, sum0, 1);
        sum0 += __shfl_xor_sync(0xffffffffu, sum0, 2);
        sum1 += __shfl_xor_sync(0xffffffffu, sum1, 1);
        sum1 += __shfl_xor_sync(0xffffffffu, sum1, 2);
        l0 = l0 * cr0 + sum0;
        l1 = l1 * cr1 + sum1;
#pragma unroll
        for (int t = 0; t < 8; t++) {
            accO[t][0] *= cr0; accO[t][1] *= cr0;
            accO[t][2] *= cr1; accO[t][3] *= cr1;
        }

        // ---- O += P V (1 pass) ----
        const int vRow16 = lane & 15;
        const int vEh = lane >> 4;
#pragma unroll
        for (int ks = 0; ks < 4; ks++) {
            uint32_t pa[4];
            pa[0] = pack_hf(S[2 * ks][0], S[2 * ks][1]);
            pa[1] = pack_hf(S[2 * ks][2], S[2 * ks][3]);
            pa[2] = pack_hf(S[2 * ks + 1][0], S[2 * ks + 1][1]);
            pa[3] = pack_hf(S[2 * ks + 1][2], S[2 * ks + 1][3]);

            uint32_t vh[4][4];
#pragma unroll
            for (int g = 0; g < 4; g++) {
                int row = ks * 16 + vRow16;
                uint32_t seg = ((uint32_t)(g * 2 + vEh) ^ (uint32_t)(row & 7)) << 4;
                ldm_x4_t(vh[g][0], vh[g][1], vh[g][2], vh[g][3],
                         stg + 8192 + (uint32_t)row * 128 + seg);
            }
#pragma unroll
            for (int g = 0; g < 4; g++) {
                float* c0 = accO[2 * g];
                float* c1 = accO[2 * g + 1];
                mma_f16(c0[0], c0[1], c0[2], c0[3],
                        pa[0], pa[1], pa[2], pa[3], vh[g][0], vh[g][1]);
                mma_f16(c1[0], c1[1], c1[2], c1[3],
                        pa[0], pa[1], pa[2], pa[3], vh[g][2], vh[g][3]);
            }
        }
        __syncthreads();
        if (kt + 2 < NT) issue_kv(kt + 2);
        cp_commit();
    }

    // ---- epilogue ----
    float inv0 = 1.0f / l0, inv1 = 1.0f / l1;
    const int b = bh >> 4, h = bh & 15;
    const int r1 = q0 + warp * 16 + (lane >> 2);
    const int r2 = r1 + 8;
    size_t t1 = ((size_t)(b * SEQ) + r1) * D_MODEL + h * D_HEAD;
    size_t t2 = ((size_t)(b * SEQ) + r2) * D_MODEL + h * D_HEAD;
#pragma unroll
    for (int t = 0; t < 8; t++) {
        int e = t * 8 + (lane & 3) * 2;
        *(uint32_t*)(oh + t1 + e) = pack_hf(accO[t][0] * inv0, accO[t][1] * inv0);
        *(uint32_t*)(oh + t2 + e) = pack_hf(accO[t][2] * inv1, accO[t][3] * inv1);
    }
}

// ---------------- launch ----------------
extern "C" void kernel_launch(void* const* d_in, const int* in_sizes, int n_in,
                              void* d_out, int out_size) {
    const float* x    = (const float*)d_in[0];
    const float* Wq   = (const float*)d_in[1];
    const float* Wk   = (const float*)d_in[2];
    const float* Wv   = (const float*)d_in[3];
    const float* Wo   = (const float*)d_in[4];
    const float* bo   = (const float*)d_in[5];
    const float* ln1g = (const float*)d_in[6];
    const float* ln1b = (const float*)d_in[7];
    const float* ln2g = (const float*)d_in[8];
    const float* ln2b = (const float*)d_in[9];
    const float* W1   = (const float*)d_in[10];
    const float* b1   = (const float*)d_in[11];
    const float* W2   = (const float*)d_in[12];
    const float* b2   = (const float*)d_in[13];
    float* out = (float*)d_out;

    hf *pWqkv, *pWo, *pW1, *pW2, *pXn, *pAt, *pHn, *pFf, *pQ, *pK, *pV;
    float* pHid;
    cudaGetSymbolAddress((void**)&pWqkv, g_WqkvT);
    cudaGetSymbolAddress((void**)&pWo, g_WoT);
    cudaGetSymbolAddress((void**)&pW1, g_W1T);
    cudaGetSymbolAddress((void**)&pW2, g_W2T);
    cudaGetSymbolAddress((void**)&pXn, g_xn);
    cudaGetSymbolAddress((void**)&pAt, g_at);
    cudaGetSymbolAddress((void**)&pHn, g_hn);
    cudaGetSymbolAddress((void**)&pFf, g_ff);
    cudaGetSymbolAddress((void**)&pQ, g_q);
    cudaGetSymbolAddress((void**)&pK, g_k);
    cudaGetSymbolAddress((void**)&pV, g_v);
    cudaGetSymbolAddress((void**)&pHid, g_hidden);

    const int GEMM_SMEM = GSTAGES * STAGE_BYTES;  // 49152
    cudaFuncSetAttribute(gemm_mma<1>, cudaFuncAttributeMaxDynamicSharedMemorySize, GEMM_SMEM);
    cudaFuncSetAttribute(gemm_mma<2>, cudaFuncAttributeMaxDynamicSharedMemorySize, GEMM_SMEM);
    cudaFuncSetAttribute(gemm_mma<3>, cudaFuncAttributeMaxDynamicSharedMemorySize, GEMM_SMEM);
    cudaFuncSetAttribute(attn_mma, cudaFuncAttributeMaxDynamicSharedMemorySize, ATT_SMEM);

    transconv_qkv_k<<<dim3(D_MODEL / 64, QKV_N / 64), 256>>>(Wq, Wk, Wv, pWqkv);
    transconv_k<<<dim3(D_MODEL / 64, D_MODEL / 64), 256>>>(Wo, pWo, D_MODEL, D_MODEL);
    transconv_k<<<dim3(D_MODEL / 64, D_FF / 64), 256>>>(W1, pW1, D_MODEL, D_FF);
    transconv_k<<<dim3(D_FF / 64, D_MODEL / 64), 256>>>(W2, pW2, D_FF, D_MODEL);

    layernorm_k<<<TOKENS, 256>>>(x, ln1g, ln1b, pXn);
    // QKV projection (1-pass) -> head-major fp16 q(scaled)/k/v
    gemm_mma<3><<<dim3(QKV_N / 128, TOKENS / 128), 256, GEMM_SMEM>>>(
        pXn, pWqkv, D_MODEL, QKV_N, nullptr, nullptr, nullptr, nullptr, pQ, pK, pV);
    // flash attention (1-pass S, 1-pass PV, packed exp2, 2 CTAs/SM)
    attn_mma<<<dim3(SEQ / 128, BH), 256, ATT_SMEM>>>(pQ, pK, pV, pAt);
    // O projection (1-pass) + bias + residual
    gemm_mma<1><<<dim3(D_MODEL / 128, TOKENS / 128), 256, GEMM_SMEM>>>(
        pAt, pWo, D_MODEL, D_MODEL, pHid, nullptr, bo, x, nullptr, nullptr, nullptr);
    layernorm_k<<<TOKENS, 256>>>(pHid, ln2g, ln2b, pHn);
    // FF1 (1-pass) + bias + GELU
    gemm_mma<2><<<dim3(D_FF / 128, TOKENS / 128), 256, GEMM_SMEM>>>(
        pHn, pW1, D_MODEL, D_FF, nullptr, pFf, b1, nullptr, nullptr, nullptr, nullptr);
    // FF2 (1-pass) + bias + residual -> out
    gemm_mma<1><<<dim3(D_MODEL / 128, TOKENS / 128), 256, GEMM_SMEM>>>(
        pFf, pW2, D_FF, D_MODEL, out, nullptr, b2, pHid, nullptr, nullptr, nullptr);
}